// round 1
// baseline (speedup 1.0000x reference)
#include <cuda_runtime.h>
#include <math.h>

// ---------------- problem constants ----------------
#define BATCH   16          // B = 2*NUM_FRAMES
#define NFRAMES 8
#define SEQ     256         // L
#define DMODEL  768
#define NHEADS  12
#define DHEAD   64
#define DFF     3072
#define ADC     128
#define ROWS    (BATCH*SEQ) // 4096

// ---------------- scratch (device globals; no allocations) ----------------
__device__ float g_h1  [ROWS*ADC];
__device__ float g_conv[ROWS*ADC];
__device__ float g_hs  [ROWS*DMODEL];
__device__ float g_hn  [ROWS*DMODEL];
__device__ float g_q   [ROWS*DMODEL];
__device__ float g_k   [ROWS*DMODEL];
__device__ float g_v   [ROWS*DMODEL];
__device__ float g_ctx [ROWS*DMODEL];
__device__ float g_hs2 [ROWS*DMODEL];
__device__ float g_attn[BATCH*NHEADS*SEQ*SEQ];
__device__ float g_ff  [ROWS*DFF];
__device__ int   g_bucket[SEQ*SEQ];

// ---------------- relative-position bucket ----------------
__global__ void bucket_kernel(int* __restrict__ bkt) {
    int i = blockIdx.x, j = threadIdx.x;
    int rel = j - i;
    int base = (rel > 0) ? 16 : 0;
    int arel = rel < 0 ? -rel : rel;
    int v;
    if (arel < 8) {
        v = arel;
    } else {
        float t = logf((float)arel / 8.0f) / 2.772588722239781f * 8.0f;
        v = 8 + (int)t;
        if (v > 15) v = 15;
    }
    bkt[i*SEQ + j] = base + v;
}

// ---------------- generic 128x128x8 SGEMM, 8x8 per thread ----------------
// EPI: 0=none, 1=+bias[col], 2=relu, 3=+residual[row*N+col]
template<int EPI>
__global__ __launch_bounds__(256) void sgemm_kernel(
    const float* __restrict__ A, const float* __restrict__ B,
    float* __restrict__ C, int M, int N, int K, const float* __restrict__ aux)
{
    __shared__ float As[8][128];
    __shared__ float Bs[8][128];
    const int tid   = threadIdx.x;
    const int tx    = tid & 15;
    const int ty    = tid >> 4;
    const int a_row = tid >> 1;
    const int a_col = (tid & 1) << 2;
    const int b_row = tid >> 5;
    const int b_col = (tid & 31) << 2;

    const float* Ab = A + (size_t)blockIdx.y * 128 * K;
    const float* Bb = B + (size_t)blockIdx.x * 128;

    float acc[8][8];
    #pragma unroll
    for (int i = 0; i < 8; i++)
        #pragma unroll
        for (int j = 0; j < 8; j++) acc[i][j] = 0.f;

    for (int k0 = 0; k0 < K; k0 += 8) {
        float4 av = *(const float4*)(Ab + (size_t)a_row * K + k0 + a_col);
        float4 bv = *(const float4*)(Bb + (size_t)(k0 + b_row) * N + b_col);
        __syncthreads();
        As[a_col+0][a_row] = av.x;
        As[a_col+1][a_row] = av.y;
        As[a_col+2][a_row] = av.z;
        As[a_col+3][a_row] = av.w;
        *(float4*)&Bs[b_row][b_col] = bv;
        __syncthreads();
        #pragma unroll
        for (int kk = 0; kk < 8; kk++) {
            float a[8], b[8];
            *(float4*)&a[0] = *(const float4*)&As[kk][ty << 2];
            *(float4*)&a[4] = *(const float4*)&As[kk][64 + (ty << 2)];
            *(float4*)&b[0] = *(const float4*)&Bs[kk][tx << 2];
            *(float4*)&b[4] = *(const float4*)&Bs[kk][64 + (tx << 2)];
            #pragma unroll
            for (int i = 0; i < 8; i++)
                #pragma unroll
                for (int j = 0; j < 8; j++)
                    acc[i][j] = fmaf(a[i], b[j], acc[i][j]);
        }
    }

    #pragma unroll
    for (int ih = 0; ih < 2; ih++)
    #pragma unroll
    for (int ii = 0; ii < 4; ii++) {
        int row = blockIdx.y * 128 + ih * 64 + (ty << 2) + ii;
        #pragma unroll
        for (int jh = 0; jh < 2; jh++) {
            int col = blockIdx.x * 128 + jh * 64 + (tx << 2);
            float vv[4];
            #pragma unroll
            for (int jj = 0; jj < 4; jj++) {
                float v = acc[ih*4+ii][jh*4+jj];
                if (EPI == 1) v += aux[col + jj];
                else if (EPI == 2) v = fmaxf(v, 0.f);
                else if (EPI == 3) v += aux[(size_t)row * N + col + jj];
                vv[jj] = v;
            }
            *(float4*)(C + (size_t)row * N + col) = make_float4(vv[0], vv[1], vv[2], vv[3]);
        }
    }
}

// ---------------- depthwise 3x3 conv over (frames, seq) ----------------
__global__ __launch_bounds__(128) void conv_kernel(
    const float* __restrict__ h1, const float* __restrict__ cw,
    const float* __restrict__ cb, float* __restrict__ out)
{
    int p  = blockIdx.x;            // 0..4095 == ((bi*8+ni)*256 + l)
    int l  = p & 255;
    int bn = p >> 8;
    int ni = bn & 7;
    int bi = bn >> 3;
    int c  = threadIdx.x;

    float acc = cb[c];
    #pragma unroll
    for (int dn = -1; dn <= 1; dn++) {
        int nn = ni + dn;
        if (nn < 0 || nn >= NFRAMES) continue;
        #pragma unroll
        for (int dl = -1; dl <= 1; dl++) {
            int ll = l + dl;
            if (ll < 0 || ll >= SEQ) continue;
            float x = h1[(size_t)(((bi*NFRAMES + nn)*SEQ) + ll) * ADC + c];
            acc = fmaf(x, cw[c*9 + (dn+1)*3 + (dl+1)], acc);
        }
    }
    out[(size_t)p * ADC + c] = acc;
}

// ---------------- block reductions / norms ----------------
__device__ __forceinline__ float blk_sum(float v, volatile float* red) {
    int tid = threadIdx.x;
    #pragma unroll
    for (int o = 16; o; o >>= 1) v += __shfl_xor_sync(0xffffffffu, v, o);
    if ((tid & 31) == 0) red[tid >> 5] = v;
    __syncthreads();
    if (tid == 0) {
        float s = 0.f;
        #pragma unroll
        for (int w = 0; w < 8; w++) s += red[w];
        red[8] = s;
    }
    __syncthreads();
    return red[8];
}

__global__ __launch_bounds__(256) void ln_res_kernel(
    const float* __restrict__ x, const float* __restrict__ w,
    const float* __restrict__ bvec, const float* __restrict__ res,
    float* __restrict__ out)
{
    __shared__ float red[9];
    size_t base = (size_t)blockIdx.x * DMODEL;
    int t = threadIdx.x;
    float v0 = x[base+t], v1 = x[base+t+256], v2 = x[base+t+512];
    float mu = blk_sum(v0+v1+v2, red) * (1.f/DMODEL);
    __syncthreads();
    float d0 = v0-mu, d1 = v1-mu, d2 = v2-mu;
    float var = blk_sum(d0*d0 + d1*d1 + d2*d2, red) * (1.f/DMODEL);
    float inv = rsqrtf(var + 1e-5f);
    out[base+t    ] = d0*inv*w[t]     + bvec[t]     + res[base+t];
    out[base+t+256] = d1*inv*w[t+256] + bvec[t+256] + res[base+t+256];
    out[base+t+512] = d2*inv*w[t+512] + bvec[t+512] + res[base+t+512];
}

__global__ __launch_bounds__(256) void rms_kernel(
    const float* __restrict__ x, const float* __restrict__ w, float* __restrict__ out)
{
    __shared__ float red[9];
    size_t base = (size_t)blockIdx.x * DMODEL;
    int t = threadIdx.x;
    float v0 = x[base+t], v1 = x[base+t+256], v2 = x[base+t+512];
    float ms = blk_sum(v0*v0 + v1*v1 + v2*v2, red) * (1.f/DMODEL);
    float inv = rsqrtf(ms + 1e-6f);
    out[base+t    ] = w[t]    *v0*inv;
    out[base+t+256] = w[t+256]*v1*inv;
    out[base+t+512] = w[t+512]*v2*inv;
}

// ---------------- fused scores (+bbox +relpos) + softmax ----------------
// one block per (b, i); thread j owns column j; bbox read exactly once.
__global__ __launch_bounds__(256) void scores_kernel(
    const float* __restrict__ q, const float* __restrict__ k,
    const float* __restrict__ bbox, const float* __restrict__ rel_bias,
    const int* __restrict__ bkt, float* __restrict__ attn)
{
    int b = blockIdx.x;
    int i = blockIdx.y;
    __shared__ float qrow[DMODEL];
    __shared__ float sc[NHEADS][SEQ];
    int tid = threadIdx.x;

    for (int t = tid; t < DMODEL; t += 256)
        qrow[t] = q[((size_t)(b*SEQ) + i) * DMODEL + t];
    __syncthreads();

    int j = tid;
    const float* krow = k + ((size_t)(b*SEQ) + j) * DMODEL;
    const float* bb   = bbox + (((size_t)i*SEQ + j) * BATCH + b) * DHEAD;
    int bu = bkt[i*SEQ + j];

    float bbv[DHEAD];
    #pragma unroll
    for (int d = 0; d < DHEAD; d += 4)
        *(float4*)&bbv[d] = *(const float4*)&bb[d];

    for (int h = 0; h < NHEADS; h++) {
        const float* qh = &qrow[h*DHEAD];
        const float* kh = &krow[h*DHEAD];
        float s1 = 0.f, s2 = 0.f;
        #pragma unroll
        for (int d = 0; d < DHEAD; d += 4) {
            float4 kv = *(const float4*)&kh[d];
            s1 = fmaf(qh[d+0], kv.x, s1);
            s1 = fmaf(qh[d+1], kv.y, s1);
            s1 = fmaf(qh[d+2], kv.z, s1);
            s1 = fmaf(qh[d+3], kv.w, s1);
            s2 = fmaf(qh[d+0], bbv[d+0], s2);
            s2 = fmaf(qh[d+1], bbv[d+1], s2);
            s2 = fmaf(qh[d+2], bbv[d+2], s2);
            s2 = fmaf(qh[d+3], bbv[d+3], s2);
        }
        sc[h][j] = (s1 + s2 + rel_bias[bu*NHEADS + h]) * 0.125f;
    }
    __syncthreads();

    // softmax over j per head; warp w handles heads w, w+8
    int warp = tid >> 5, lane = tid & 31;
    for (int h = warp; h < NHEADS; h += 8) {
        float m = -1e30f;
        for (int t = lane; t < SEQ; t += 32) m = fmaxf(m, sc[h][t]);
        #pragma unroll
        for (int o = 16; o; o >>= 1) m = fmaxf(m, __shfl_xor_sync(0xffffffffu, m, o));
        float sum = 0.f;
        for (int t = lane; t < SEQ; t += 32) {
            float e = expf(sc[h][t] - m);
            sc[h][t] = e;
            sum += e;
        }
        #pragma unroll
        for (int o = 16; o; o >>= 1) sum += __shfl_xor_sync(0xffffffffu, sum, o);
        float invs = 1.f / sum;
        float* out = attn + (((size_t)(b*NHEADS + h)*SEQ) + i) * SEQ;
        for (int t = lane; t < SEQ; t += 32) out[t] = sc[h][t] * invs;
    }
}

// ---------------- ctx = attn @ V, written as (b, l, h, d) ----------------
__global__ __launch_bounds__(256) void ctx_kernel(
    const float* __restrict__ attn, const float* __restrict__ v,
    float* __restrict__ ctx)
{
    int bh = blockIdx.x;            // b*12+h
    int b = bh / NHEADS, h = bh % NHEADS;
    int i0 = blockIdx.y * 64;
    __shared__ float At[64][65];    // [j][i]
    __shared__ float Vt[64][64];    // [j][d]
    int tid = threadIdx.x;
    int tx = tid & 15, ty = tid >> 4;

    float acc[4][4] = {};
    const float* arow = attn + ((size_t)bh * SEQ + i0) * SEQ;

    for (int j0 = 0; j0 < SEQ; j0 += 64) {
        __syncthreads();
        for (int e = tid; e < 4096; e += 256) {
            int r = e >> 6, c = e & 63;
            At[c][r] = arow[(size_t)r * SEQ + j0 + c];
            Vt[r][c] = v[(size_t)(b*SEQ + j0 + r) * DMODEL + h*DHEAD + c];
        }
        __syncthreads();
        #pragma unroll 8
        for (int kk = 0; kk < 64; kk++) {
            float a[4], bb[4];
            #pragma unroll
            for (int ii = 0; ii < 4; ii++) a[ii] = At[kk][(ty<<2) + ii];
            *(float4*)bb = *(const float4*)&Vt[kk][tx<<2];
            #pragma unroll
            for (int ii = 0; ii < 4; ii++)
                #pragma unroll
                for (int jj = 0; jj < 4; jj++)
                    acc[ii][jj] = fmaf(a[ii], bb[jj], acc[ii][jj]);
        }
    }
    #pragma unroll
    for (int ii = 0; ii < 4; ii++)
        #pragma unroll
        for (int jj = 0; jj < 4; jj++)
            ctx[(((size_t)(b*SEQ + i0 + (ty<<2) + ii))*NHEADS + h)*DHEAD + (tx<<2) + jj]
                = acc[ii][jj];
}

// ---------------- launch ----------------
extern "C" void kernel_launch(void* const* d_in, const int* in_sizes, int n_in,
                              void* d_out, int out_size)
{
    const float* hidden  = (const float*)d_in[0];
    const float* bbox    = (const float*)d_in[1];
    const float* fc1_w   = (const float*)d_in[2];
    const float* fc1_b   = (const float*)d_in[3];
    const float* conv_w  = (const float*)d_in[4];
    const float* conv_b  = (const float*)d_in[5];
    const float* fc2_w   = (const float*)d_in[6];
    const float* fc2_b   = (const float*)d_in[7];
    const float* ln_ad_w = (const float*)d_in[8];
    const float* ln_ad_b = (const float*)d_in[9];
    const float* ln1_w   = (const float*)d_in[10];
    const float* q_w     = (const float*)d_in[11];
    const float* k_w     = (const float*)d_in[12];
    const float* v_w     = (const float*)d_in[13];
    const float* o_w     = (const float*)d_in[14];
    const float* rel_b   = (const float*)d_in[15];
    const float* ln2_w   = (const float*)d_in[16];
    const float* wi_w    = (const float*)d_in[17];
    const float* wo_w    = (const float*)d_in[18];
    float* out = (float*)d_out;

    float *h1, *cv, *hs, *hn, *q, *k, *v, *ctx, *hs2, *attn, *ff;
    int* bkt;
    cudaGetSymbolAddress((void**)&h1,  g_h1);
    cudaGetSymbolAddress((void**)&cv,  g_conv);
    cudaGetSymbolAddress((void**)&hs,  g_hs);
    cudaGetSymbolAddress((void**)&hn,  g_hn);
    cudaGetSymbolAddress((void**)&q,   g_q);
    cudaGetSymbolAddress((void**)&k,   g_k);
    cudaGetSymbolAddress((void**)&v,   g_v);
    cudaGetSymbolAddress((void**)&ctx, g_ctx);
    cudaGetSymbolAddress((void**)&hs2, g_hs2);
    cudaGetSymbolAddress((void**)&attn,g_attn);
    cudaGetSymbolAddress((void**)&ff,  g_ff);
    cudaGetSymbolAddress((void**)&bkt, g_bucket);

    // rel-pos bucket table
    bucket_kernel<<<SEQ, SEQ>>>(bkt);

    // ---- adapter ----
    sgemm_kernel<1><<<dim3(1, 32), 256>>>(hidden, fc1_w, h1, ROWS, ADC, DMODEL, fc1_b);
    conv_kernel<<<ROWS, ADC>>>(h1, conv_w, conv_b, cv);
    sgemm_kernel<1><<<dim3(6, 32), 256>>>(cv, fc2_w, hn, ROWS, DMODEL, ADC, fc2_b);
    ln_res_kernel<<<ROWS, 256>>>(hn, ln_ad_w, ln_ad_b, hidden, hs);

    // ---- attention ----
    rms_kernel<<<ROWS, 256>>>(hs, ln1_w, hn);
    sgemm_kernel<0><<<dim3(6, 32), 256>>>(hn, q_w, q, ROWS, DMODEL, DMODEL, nullptr);
    sgemm_kernel<0><<<dim3(6, 32), 256>>>(hn, k_w, k, ROWS, DMODEL, DMODEL, nullptr);
    sgemm_kernel<0><<<dim3(6, 32), 256>>>(hn, v_w, v, ROWS, DMODEL, DMODEL, nullptr);
    scores_kernel<<<dim3(BATCH, SEQ), 256>>>(q, k, bbox, rel_b, bkt, attn);
    ctx_kernel<<<dim3(BATCH*NHEADS, SEQ/64), 256>>>(attn, v, ctx);
    sgemm_kernel<3><<<dim3(6, 32), 256>>>(ctx, o_w, hs2, ROWS, DMODEL, DMODEL, hs);

    // ---- FFN ----
    rms_kernel<<<ROWS, 256>>>(hs2, ln2_w, hn);
    sgemm_kernel<2><<<dim3(24, 32), 256>>>(hn, wi_w, ff, ROWS, DFF, DMODEL, nullptr);
    sgemm_kernel<3><<<dim3(6, 32), 256>>>(ff, wo_w, out, ROWS, DMODEL, DFF, hs2);
}

// round 2
// speedup vs baseline: 1.7623x; 1.7623x over previous
#include <cuda_runtime.h>
#include <math.h>

// ---------------- problem constants ----------------
#define BATCH   16          // B = 2*NUM_FRAMES
#define NFRAMES 8
#define SEQ     256         // L
#define DMODEL  768
#define NHEADS  12
#define DHEAD   64
#define DFF     3072
#define ADC     128
#define ROWS    (BATCH*SEQ) // 4096

// ---------------- scratch (device globals; no allocations) ----------------
__device__ float g_h1  [ROWS*ADC];
__device__ float g_conv[ROWS*ADC];
__device__ float g_hs  [ROWS*DMODEL];
__device__ float g_hn  [ROWS*DMODEL];
__device__ float g_q   [ROWS*DMODEL];
__device__ float g_k   [ROWS*DMODEL];
__device__ float g_v   [ROWS*DMODEL];
__device__ float g_ctx [ROWS*DMODEL];
__device__ float g_hs2 [ROWS*DMODEL];
__device__ float g_attn[BATCH*NHEADS*SEQ*SEQ];
__device__ float g_ff  [ROWS*DFF];
__device__ int   g_bucket[SEQ*SEQ];

// ---------------- relative-position bucket ----------------
__global__ void bucket_kernel(int* __restrict__ bkt) {
    int i = blockIdx.x, j = threadIdx.x;
    int rel = j - i;
    int base = (rel > 0) ? 16 : 0;
    int arel = rel < 0 ? -rel : rel;
    int v;
    if (arel < 8) {
        v = arel;
    } else {
        float t = logf((float)arel / 8.0f) / 2.772588722239781f * 8.0f;
        v = 8 + (int)t;
        if (v > 15) v = 15;
    }
    bkt[i*SEQ + j] = base + v;
}

// ================= TF32 tensor-core GEMM =================
// block tile 128x128, K-tile 32, 256 threads (8 warps, 2x4 -> 64x32 warp tiles)
// EPI: 0=none, 1=+bias[col], 2=relu, 3=+residual[row*N+col]

#define STAGEF  8736          // floats per stage: As 32*137 + Bs 32*136
#define SMEM_BYTES (2*STAGEF*4)

__device__ __forceinline__ float tf32r(float x) {
    unsigned y;
    asm("cvt.rna.tf32.f32 %0, %1;" : "=r"(y) : "f"(x));
    return __uint_as_float(y);
}

__device__ __forceinline__ void mma_tf32(float c[4], const unsigned a[4], const unsigned b[2]) {
    asm volatile(
        "mma.sync.aligned.m16n8k8.row.col.f32.tf32.tf32.f32 "
        "{%0,%1,%2,%3}, {%4,%5,%6,%7}, {%8,%9}, {%0,%1,%2,%3};\n"
        : "+f"(c[0]), "+f"(c[1]), "+f"(c[2]), "+f"(c[3])
        : "r"(a[0]), "r"(a[1]), "r"(a[2]), "r"(a[3]),
          "r"(b[0]), "r"(b[1]));
}

__device__ __forceinline__ void stage_store(
    float* __restrict__ as, float* __restrict__ bs,
    const float4* ar, const float4* br,
    int am, int ak, int bk, int bn4)
{
    #pragma unroll
    for (int i = 0; i < 4; i++) {
        int m = am + i*32;
        as[(ak+0)*137 + m] = tf32r(ar[i].x);
        as[(ak+1)*137 + m] = tf32r(ar[i].y);
        as[(ak+2)*137 + m] = tf32r(ar[i].z);
        as[(ak+3)*137 + m] = tf32r(ar[i].w);
    }
    #pragma unroll
    for (int i = 0; i < 4; i++) {
        float4 v;
        v.x = tf32r(br[i].x); v.y = tf32r(br[i].y);
        v.z = tf32r(br[i].z); v.w = tf32r(br[i].w);
        *(float4*)(bs + (bk + i*8)*136 + bn4) = v;
    }
}

template<int EPI>
__device__ __forceinline__ void tgemm_core(
    const float* __restrict__ A, const float* __restrict__ B, float* __restrict__ C,
    int M, int N, int K, const float* __restrict__ aux)
{
    extern __shared__ float sm[];
    const int tid  = threadIdx.x;
    const int lane = tid & 31;
    const int warp = tid >> 5;
    const int wm = (warp & 1) * 64;
    const int wn = (warp >> 1) * 32;
    const int g = lane >> 2;
    const int t = lane & 3;
    const size_t bm = (size_t)blockIdx.y * 128;
    const size_t bn = (size_t)blockIdx.x * 128;

    const float* Ab = A + bm * K;
    const float* Bb = B + bn;

    const int am  = tid >> 3;         // + i*32
    const int ak  = (tid & 7) * 4;
    const int bk  = tid >> 5;         // + i*8
    const int bn4 = (tid & 31) * 4;

    float acc[4][4][4];
    #pragma unroll
    for (int i = 0; i < 4; i++)
        #pragma unroll
        for (int j = 0; j < 4; j++)
            #pragma unroll
            for (int r = 0; r < 4; r++) acc[i][j][r] = 0.f;

    const int ktiles = K >> 5;
    float4 ar[4], br[4];

    // prefetch tile 0
    #pragma unroll
    for (int i = 0; i < 4; i++)
        ar[i] = *(const float4*)(Ab + (size_t)(am + i*32) * K + ak);
    #pragma unroll
    for (int i = 0; i < 4; i++)
        br[i] = *(const float4*)(Bb + (size_t)(bk + i*8) * N + bn4);

    stage_store(sm, sm + 4384, ar, br, am, ak, bk, bn4);
    __syncthreads();

    int cur = 0;
    for (int kt = 0; kt < ktiles; kt++) {
        if (kt + 1 < ktiles) {
            const float* Ag = Ab + (kt+1)*32;
            const float* Bg = Bb + (size_t)(kt+1)*32*N;
            #pragma unroll
            for (int i = 0; i < 4; i++)
                ar[i] = *(const float4*)(Ag + (size_t)(am + i*32) * K + ak);
            #pragma unroll
            for (int i = 0; i < 4; i++)
                br[i] = *(const float4*)(Bg + (size_t)(bk + i*8) * N + bn4);
        }
        const float* as = sm + cur * STAGEF;
        const float* bs = as + 4384;
        #pragma unroll
        for (int ks = 0; ks < 4; ks++) {
            unsigned af[4][4], bf[4][2];
            const int r0 = ks*8 + t, r1 = r0 + 4;
            #pragma unroll
            for (int im = 0; im < 4; im++) {
                int m0 = wm + im*16 + g;
                af[im][0] = __float_as_uint(as[r0*137 + m0]);
                af[im][1] = __float_as_uint(as[r0*137 + m0 + 8]);
                af[im][2] = __float_as_uint(as[r1*137 + m0]);
                af[im][3] = __float_as_uint(as[r1*137 + m0 + 8]);
            }
            #pragma unroll
            for (int in = 0; in < 4; in++) {
                int n0 = wn + in*8 + g;
                bf[in][0] = __float_as_uint(bs[r0*136 + n0]);
                bf[in][1] = __float_as_uint(bs[r1*136 + n0]);
            }
            #pragma unroll
            for (int im = 0; im < 4; im++)
                #pragma unroll
                for (int in = 0; in < 4; in++)
                    mma_tf32(acc[im][in], af[im], bf[in]);
        }
        if (kt + 1 < ktiles) {
            float* nas = sm + (cur ^ 1) * STAGEF;
            stage_store(nas, nas + 4384, ar, br, am, ak, bk, bn4);
            __syncthreads();
            cur ^= 1;
        }
    }

    // epilogue
    #pragma unroll
    for (int im = 0; im < 4; im++) {
        #pragma unroll
        for (int half = 0; half < 2; half++) {
            size_t row = bm + wm + im*16 + g + half*8;
            #pragma unroll
            for (int in = 0; in < 4; in++) {
                size_t col = bn + wn + in*8 + 2*t;
                float v0 = acc[im][in][half*2 + 0];
                float v1 = acc[im][in][half*2 + 1];
                if (EPI == 1) { v0 += aux[col]; v1 += aux[col+1]; }
                else if (EPI == 2) { v0 = fmaxf(v0, 0.f); v1 = fmaxf(v1, 0.f); }
                else if (EPI == 3) { v0 += aux[row*N+col]; v1 += aux[row*N+col+1]; }
                *(float2*)(C + row*N + col) = make_float2(v0, v1);
            }
        }
    }
}

template<int EPI>
__global__ __launch_bounds__(256, 2) void tgemm(
    const float* __restrict__ A, const float* __restrict__ B, float* __restrict__ C,
    int M, int N, int K, const float* __restrict__ aux)
{
    tgemm_core<EPI>(A, B, C, M, N, K, aux);
}

__global__ __launch_bounds__(256, 2) void qkv_tgemm(
    const float* __restrict__ A,
    const float* __restrict__ B0, const float* __restrict__ B1, const float* __restrict__ B2,
    float* __restrict__ C0, float* __restrict__ C1, float* __restrict__ C2,
    int M, int N, int K)
{
    const float* B = (blockIdx.z == 0) ? B0 : ((blockIdx.z == 1) ? B1 : B2);
    float*       C = (blockIdx.z == 0) ? C0 : ((blockIdx.z == 1) ? C1 : C2);
    tgemm_core<0>(A, B, C, M, N, K, nullptr);
}

// ---------------- depthwise 3x3 conv over (frames, seq) ----------------
__global__ __launch_bounds__(128) void conv_kernel(
    const float* __restrict__ h1, const float* __restrict__ cw,
    const float* __restrict__ cb, float* __restrict__ out)
{
    int p  = blockIdx.x;            // 0..4095 == ((bi*8+ni)*256 + l)
    int l  = p & 255;
    int bn = p >> 8;
    int ni = bn & 7;
    int bi = bn >> 3;
    int c  = threadIdx.x;

    float acc = cb[c];
    #pragma unroll
    for (int dn = -1; dn <= 1; dn++) {
        int nn = ni + dn;
        if (nn < 0 || nn >= NFRAMES) continue;
        #pragma unroll
        for (int dl = -1; dl <= 1; dl++) {
            int ll = l + dl;
            if (ll < 0 || ll >= SEQ) continue;
            float x = h1[(size_t)(((bi*NFRAMES + nn)*SEQ) + ll) * ADC + c];
            acc = fmaf(x, cw[c*9 + (dn+1)*3 + (dl+1)], acc);
        }
    }
    out[(size_t)p * ADC + c] = acc;
}

// ---------------- block reductions / norms ----------------
__device__ __forceinline__ float blk_sum(float v, volatile float* red) {
    int tid = threadIdx.x;
    #pragma unroll
    for (int o = 16; o; o >>= 1) v += __shfl_xor_sync(0xffffffffu, v, o);
    if ((tid & 31) == 0) red[tid >> 5] = v;
    __syncthreads();
    if (tid == 0) {
        float s = 0.f;
        #pragma unroll
        for (int w = 0; w < 8; w++) s += red[w];
        red[8] = s;
    }
    __syncthreads();
    return red[8];
}

__global__ __launch_bounds__(256) void ln_res_kernel(
    const float* __restrict__ x, const float* __restrict__ w,
    const float* __restrict__ bvec, const float* __restrict__ res,
    float* __restrict__ out)
{
    __shared__ float red[9];
    size_t base = (size_t)blockIdx.x * DMODEL;
    int t = threadIdx.x;
    float v0 = x[base+t], v1 = x[base+t+256], v2 = x[base+t+512];
    float mu = blk_sum(v0+v1+v2, red) * (1.f/DMODEL);
    __syncthreads();
    float d0 = v0-mu, d1 = v1-mu, d2 = v2-mu;
    float var = blk_sum(d0*d0 + d1*d1 + d2*d2, red) * (1.f/DMODEL);
    float inv = rsqrtf(var + 1e-5f);
    out[base+t    ] = d0*inv*w[t]     + bvec[t]     + res[base+t];
    out[base+t+256] = d1*inv*w[t+256] + bvec[t+256] + res[base+t+256];
    out[base+t+512] = d2*inv*w[t+512] + bvec[t+512] + res[base+t+512];
}

__global__ __launch_bounds__(256) void rms_kernel(
    const float* __restrict__ x, const float* __restrict__ w, float* __restrict__ out)
{
    __shared__ float red[9];
    size_t base = (size_t)blockIdx.x * DMODEL;
    int t = threadIdx.x;
    float v0 = x[base+t], v1 = x[base+t+256], v2 = x[base+t+512];
    float ms = blk_sum(v0*v0 + v1*v1 + v2*v2, red) * (1.f/DMODEL);
    float inv = rsqrtf(ms + 1e-6f);
    out[base+t    ] = w[t]    *v0*inv;
    out[base+t+256] = w[t+256]*v1*inv;
    out[base+t+512] = w[t+512]*v2*inv;
}

// ---------------- fused scores (+bbox +relpos) + softmax ----------------
__global__ __launch_bounds__(256) void scores_kernel(
    const float* __restrict__ q, const float* __restrict__ k,
    const float* __restrict__ bbox, const float* __restrict__ rel_bias,
    const int* __restrict__ bkt, float* __restrict__ attn)
{
    int b = blockIdx.x;
    int i = blockIdx.y;
    __shared__ float qrow[DMODEL];
    __shared__ float sc[NHEADS][SEQ];
    int tid = threadIdx.x;

    for (int t = tid; t < DMODEL; t += 256)
        qrow[t] = q[((size_t)(b*SEQ) + i) * DMODEL + t];
    __syncthreads();

    int j = tid;
    const float* krow = k + ((size_t)(b*SEQ) + j) * DMODEL;
    const float* bb   = bbox + (((size_t)i*SEQ + j) * BATCH + b) * DHEAD;
    int bu = bkt[i*SEQ + j];

    float bbv[DHEAD];
    #pragma unroll
    for (int d = 0; d < DHEAD; d += 4)
        *(float4*)&bbv[d] = *(const float4*)&bb[d];

    for (int h = 0; h < NHEADS; h++) {
        const float* qh = &qrow[h*DHEAD];
        const float* kh = &krow[h*DHEAD];
        float s1 = 0.f, s2 = 0.f;
        #pragma unroll
        for (int d = 0; d < DHEAD; d += 4) {
            float4 kv = *(const float4*)&kh[d];
            s1 = fmaf(qh[d+0], kv.x, s1);
            s1 = fmaf(qh[d+1], kv.y, s1);
            s1 = fmaf(qh[d+2], kv.z, s1);
            s1 = fmaf(qh[d+3], kv.w, s1);
            s2 = fmaf(qh[d+0], bbv[d+0], s2);
            s2 = fmaf(qh[d+1], bbv[d+1], s2);
            s2 = fmaf(qh[d+2], bbv[d+2], s2);
            s2 = fmaf(qh[d+3], bbv[d+3], s2);
        }
        sc[h][j] = (s1 + s2 + rel_bias[bu*NHEADS + h]) * 0.125f;
    }
    __syncthreads();

    int warp = tid >> 5, lane = tid & 31;
    for (int h = warp; h < NHEADS; h += 8) {
        float m = -1e30f;
        for (int t = lane; t < SEQ; t += 32) m = fmaxf(m, sc[h][t]);
        #pragma unroll
        for (int o = 16; o; o >>= 1) m = fmaxf(m, __shfl_xor_sync(0xffffffffu, m, o));
        float sum = 0.f;
        for (int t = lane; t < SEQ; t += 32) {
            float e = expf(sc[h][t] - m);
            sc[h][t] = e;
            sum += e;
        }
        #pragma unroll
        for (int o = 16; o; o >>= 1) sum += __shfl_xor_sync(0xffffffffu, sum, o);
        float invs = 1.f / sum;
        float* out = attn + (((size_t)(b*NHEADS + h)*SEQ) + i) * SEQ;
        for (int t = lane; t < SEQ; t += 32) out[t] = sc[h][t] * invs;
    }
}

// ---------------- ctx = attn @ V, written as (b, l, h, d) ----------------
__global__ __launch_bounds__(256) void ctx_kernel(
    const float* __restrict__ attn, const float* __restrict__ v,
    float* __restrict__ ctx)
{
    int bh = blockIdx.x;            // b*12+h
    int b = bh / NHEADS, h = bh % NHEADS;
    int i0 = blockIdx.y * 64;
    __shared__ float At[64][65];
    __shared__ float Vt[64][64];
    int tid = threadIdx.x;
    int tx = tid & 15, ty = tid >> 4;

    float acc[4][4] = {};
    const float* arow = attn + ((size_t)bh * SEQ + i0) * SEQ;

    for (int j0 = 0; j0 < SEQ; j0 += 64) {
        __syncthreads();
        for (int e = tid; e < 4096; e += 256) {
            int r = e >> 6, c = e & 63;
            At[c][r] = arow[(size_t)r * SEQ + j0 + c];
            Vt[r][c] = v[(size_t)(b*SEQ + j0 + r) * DMODEL + h*DHEAD + c];
        }
        __syncthreads();
        #pragma unroll 8
        for (int kk = 0; kk < 64; kk++) {
            float a[4], bb[4];
            #pragma unroll
            for (int ii = 0; ii < 4; ii++) a[ii] = At[kk][(ty<<2) + ii];
            *(float4*)bb = *(const float4*)&Vt[kk][tx<<2];
            #pragma unroll
            for (int ii = 0; ii < 4; ii++)
                #pragma unroll
                for (int jj = 0; jj < 4; jj++)
                    acc[ii][jj] = fmaf(a[ii], bb[jj], acc[ii][jj]);
        }
    }
    #pragma unroll
    for (int ii = 0; ii < 4; ii++)
        #pragma unroll
        for (int jj = 0; jj < 4; jj++)
            ctx[(((size_t)(b*SEQ + i0 + (ty<<2) + ii))*NHEADS + h)*DHEAD + (tx<<2) + jj]
                = acc[ii][jj];
}

// ---------------- launch ----------------
extern "C" void kernel_launch(void* const* d_in, const int* in_sizes, int n_in,
                              void* d_out, int out_size)
{
    const float* hidden  = (const float*)d_in[0];
    const float* bbox    = (const float*)d_in[1];
    const float* fc1_w   = (const float*)d_in[2];
    const float* fc1_b   = (const float*)d_in[3];
    const float* conv_w  = (const float*)d_in[4];
    const float* conv_b  = (const float*)d_in[5];
    const float* fc2_w   = (const float*)d_in[6];
    const float* fc2_b   = (const float*)d_in[7];
    const float* ln_ad_w = (const float*)d_in[8];
    const float* ln_ad_b = (const float*)d_in[9];
    const float* ln1_w   = (const float*)d_in[10];
    const float* q_w     = (const float*)d_in[11];
    const float* k_w     = (const float*)d_in[12];
    const float* v_w     = (const float*)d_in[13];
    const float* o_w     = (const float*)d_in[14];
    const float* rel_b   = (const float*)d_in[15];
    const float* ln2_w   = (const float*)d_in[16];
    const float* wi_w    = (const float*)d_in[17];
    const float* wo_w    = (const float*)d_in[18];
    float* out = (float*)d_out;

    float *h1, *cv, *hs, *hn, *q, *k, *v, *ctx, *hs2, *attn, *ff;
    int* bkt;
    cudaGetSymbolAddress((void**)&h1,  g_h1);
    cudaGetSymbolAddress((void**)&cv,  g_conv);
    cudaGetSymbolAddress((void**)&hs,  g_hs);
    cudaGetSymbolAddress((void**)&hn,  g_hn);
    cudaGetSymbolAddress((void**)&q,   g_q);
    cudaGetSymbolAddress((void**)&k,   g_k);
    cudaGetSymbolAddress((void**)&v,   g_v);
    cudaGetSymbolAddress((void**)&ctx, g_ctx);
    cudaGetSymbolAddress((void**)&hs2, g_hs2);
    cudaGetSymbolAddress((void**)&attn,g_attn);
    cudaGetSymbolAddress((void**)&ff,  g_ff);
    cudaGetSymbolAddress((void**)&bkt, g_bucket);

    cudaFuncSetAttribute(tgemm<1>, cudaFuncAttributeMaxDynamicSharedMemorySize, SMEM_BYTES);
    cudaFuncSetAttribute(tgemm<2>, cudaFuncAttributeMaxDynamicSharedMemorySize, SMEM_BYTES);
    cudaFuncSetAttribute(tgemm<3>, cudaFuncAttributeMaxDynamicSharedMemorySize, SMEM_BYTES);
    cudaFuncSetAttribute(qkv_tgemm, cudaFuncAttributeMaxDynamicSharedMemorySize, SMEM_BYTES);

    // rel-pos bucket table
    bucket_kernel<<<SEQ, SEQ>>>(bkt);

    // ---- adapter ----
    tgemm<1><<<dim3(1, 32), 256, SMEM_BYTES>>>(hidden, fc1_w, h1, ROWS, ADC, DMODEL, fc1_b);
    conv_kernel<<<ROWS, ADC>>>(h1, conv_w, conv_b, cv);
    tgemm<1><<<dim3(6, 32), 256, SMEM_BYTES>>>(cv, fc2_w, hn, ROWS, DMODEL, ADC, fc2_b);
    ln_res_kernel<<<ROWS, 256>>>(hn, ln_ad_w, ln_ad_b, hidden, hs);

    // ---- attention ----
    rms_kernel<<<ROWS, 256>>>(hs, ln1_w, hn);
    qkv_tgemm<<<dim3(6, 32, 3), 256, SMEM_BYTES>>>(hn, q_w, k_w, v_w, q, k, v,
                                                   ROWS, DMODEL, DMODEL);
    scores_kernel<<<dim3(BATCH, SEQ), 256>>>(q, k, bbox, rel_b, bkt, attn);
    ctx_kernel<<<dim3(BATCH*NHEADS, SEQ/64), 256>>>(attn, v, ctx);
    tgemm<3><<<dim3(6, 32), 256, SMEM_BYTES>>>(ctx, o_w, hs2, ROWS, DMODEL, DMODEL, hs);

    // ---- FFN ----
    rms_kernel<<<ROWS, 256>>>(hs2, ln2_w, hn);
    tgemm<2><<<dim3(24, 32), 256, SMEM_BYTES>>>(hn, wi_w, ff, ROWS, DFF, DMODEL, nullptr);
    tgemm<3><<<dim3(6, 32), 256, SMEM_BYTES>>>(ff, wo_w, out, ROWS, DMODEL, DFF, hs2);
}

// round 4
// speedup vs baseline: 1.9736x; 1.1199x over previous
#include <cuda_runtime.h>
#include <math.h>
#include <stdint.h>

// ---------------- problem constants ----------------
#define BATCH   16
#define NFRAMES 8
#define SEQ     256
#define DMODEL  768
#define NHEADS  12
#define DHEAD   64
#define DFF     3072
#define ADC     128
#define ROWS    (BATCH*SEQ) // 4096

// ---------------- scratch (device globals; no allocations) ----------------
__device__ float g_h1  [ROWS*ADC];
__device__ float g_conv[ROWS*ADC];
__device__ float g_hs  [ROWS*DMODEL];
__device__ float g_hn  [ROWS*DMODEL];
__device__ float g_hr  [ROWS*DMODEL];   // tf32-rounded copy of hidden
__device__ float g_q   [ROWS*DMODEL];
__device__ float g_k   [ROWS*DMODEL];
__device__ float g_v   [ROWS*DMODEL];
__device__ float g_ctx [ROWS*DMODEL];
__device__ float g_hs2 [ROWS*DMODEL];
__device__ float g_attn[BATCH*NHEADS*SEQ*SEQ];
__device__ float g_ff  [ROWS*DFF];
__device__ int   g_bucket[SEQ*SEQ];
// transposed + tf32-rounded weights [N][K]
__device__ float g_wt_q  [DMODEL*DMODEL];
__device__ float g_wt_k  [DMODEL*DMODEL];
__device__ float g_wt_v  [DMODEL*DMODEL];
__device__ float g_wt_o  [DMODEL*DMODEL];
__device__ float g_wt_wi [DMODEL*DFF];
__device__ float g_wt_wo [DFF*DMODEL];
__device__ float g_wt_fc1[DMODEL*ADC];
__device__ float g_wt_fc2[ADC*DMODEL];

// ================= helpers =================
__device__ __forceinline__ uint32_t smem_u32(const void* p) {
    uint32_t a;
    asm("{ .reg .u64 t; cvta.to.shared.u64 t, %1; cvt.u32.u64 %0, t; }" : "=r"(a) : "l"(p));
    return a;
}
__device__ __forceinline__ float tf32r(float x) {
    unsigned y;
    asm("cvt.rna.tf32.f32 %0, %1;" : "=r"(y) : "f"(x));
    return __uint_as_float(y);
}
__device__ __forceinline__ void cp16(uint32_t s, const void* g) {
    asm volatile("cp.async.cg.shared.global [%0], [%1], 16;" :: "r"(s), "l"(g));
}
#define CP_COMMIT() asm volatile("cp.async.commit_group;" ::: "memory")
#define CP_WAIT1()  asm volatile("cp.async.wait_group 1;" ::: "memory")

__device__ __forceinline__ void ldsm4(uint32_t& r0, uint32_t& r1, uint32_t& r2, uint32_t& r3,
                                      uint32_t a) {
    asm volatile("ldmatrix.sync.aligned.m8n8.x4.shared.b16 {%0,%1,%2,%3}, [%4];"
                 : "=r"(r0), "=r"(r1), "=r"(r2), "=r"(r3) : "r"(a));
}
__device__ __forceinline__ void mma_tf32(float c[4], const uint32_t a[4],
                                         uint32_t b0, uint32_t b1) {
    asm volatile(
        "mma.sync.aligned.m16n8k8.row.col.f32.tf32.tf32.f32 "
        "{%0,%1,%2,%3}, {%4,%5,%6,%7}, {%8,%9}, {%0,%1,%2,%3};\n"
        : "+f"(c[0]), "+f"(c[1]), "+f"(c[2]), "+f"(c[3])
        : "r"(a[0]), "r"(a[1]), "r"(a[2]), "r"(a[3]), "r"(b0), "r"(b1));
}

#define SWZ(o) ((o) ^ (((o) >> 3) & 0x70))

// ================= tf32 mma.sync GEMM =================
// tile 128x128x32, 3-stage cp.async pipeline, ldmatrix fragment loads.
// A [M][K] (values pre-rounded to tf32), BT [N][K] (pre-rounded), both row-major.
// EPI: 0=none, 1=+bias[col], 2=relu(+tf32 round), 3=+residual
#define BK 32
#define A_BYTES (128*128)
#define STAGE_BYTES (2*A_BYTES)
#define SMEMB (3*STAGE_BYTES)

template<int EPI>
__device__ __forceinline__ void mgemm_core(
    const float* __restrict__ A, const float* __restrict__ BT,
    float* __restrict__ C, int M, int N, int K, const float* __restrict__ aux)
{
    extern __shared__ __align__(16) char smc[];
    const uint32_t sbase = smem_u32(smc);
    const int tid  = threadIdx.x;
    const int lane = tid & 31;
    const int warp = tid >> 5;
    const int wm = (warp & 1) * 64;
    const int wn = (warp >> 1) * 32;
    const int g = lane >> 2;
    const int t = lane & 3;
    const size_t bm = (size_t)blockIdx.y * 128;
    const size_t bn = (size_t)blockIdx.x * 128;

    const float* Ab = A  + bm * K;
    const float* Bb = BT + bn * K;

    // staging chunk ids: id = tid + p*256 -> row=id>>3, chunk c=id&7 (16B)
    const int ktiles = K >> 5;

    // fragment ldmatrix address components
    const int lane7 = lane & 7;
    const int l8    = ((lane >> 3) & 1) << 3;
    const int hb    = lane >> 4;                 // 0 or 1
    uint32_t arow128[4]; int axr[4];
    uint32_t brow128[2]; int bxr[2];
    #pragma unroll
    for (int im = 0; im < 4; im++) {
        int r = wm + im*16 + lane7 + l8;
        arow128[im] = r * 128; axr[im] = r & 7;
    }
    #pragma unroll
    for (int in = 0; in < 2; in++) {
        int r = wn + in*16 + lane7 + l8;
        brow128[in] = r * 128; bxr[in] = r & 7;
    }

    float acc[4][4][4];
    #pragma unroll
    for (int i = 0; i < 4; i++)
        #pragma unroll
        for (int j = 0; j < 4; j++)
            #pragma unroll
            for (int r = 0; r < 4; r++) acc[i][j][r] = 0.f;

    // ---- prologue: stage 0,1 ----
    #pragma unroll
    for (int s = 0; s < 2; s++) {
        if (s < ktiles) {
            uint32_t sa = sbase + s * STAGE_BYTES;
            const float* Ag = Ab + s * BK;
            const float* Bg = Bb + s * BK;
            #pragma unroll
            for (int p = 0; p < 4; p++) {
                int id = tid + p * 256;
                int row = id >> 3, c = id & 7;
                uint32_t off = SWZ(row * 128 + c * 16);
                cp16(sa + off,           Ag + (size_t)row * K + c * 4);
                cp16(sa + A_BYTES + off, Bg + (size_t)row * K + c * 4);
            }
        }
        CP_COMMIT();
    }

    int cs = 0, is_ = 2;
    for (int kt = 0; kt < ktiles; kt++) {
        CP_WAIT1();
        __syncthreads();

        if (kt + 2 < ktiles) {
            uint32_t sa = sbase + is_ * STAGE_BYTES;
            const float* Ag = Ab + (kt + 2) * BK;
            const float* Bg = Bb + (kt + 2) * BK;
            #pragma unroll
            for (int p = 0; p < 4; p++) {
                int id = tid + p * 256;
                int row = id >> 3, c = id & 7;
                uint32_t off = SWZ(row * 128 + c * 16);
                cp16(sa + off,           Ag + (size_t)row * K + c * 4);
                cp16(sa + A_BYTES + off, Bg + (size_t)row * K + c * 4);
            }
        }
        CP_COMMIT();

        const uint32_t as = sbase + cs * STAGE_BYTES;
        const uint32_t bs = as + A_BYTES;
        #pragma unroll
        for (int ks = 0; ks < 4; ks++) {
            uint32_t af[4][4], bf[2][4];
            const int cc = 2 * ks + hb;
            #pragma unroll
            for (int im = 0; im < 4; im++)
                ldsm4(af[im][0], af[im][1], af[im][2], af[im][3],
                      as + arow128[im] + ((uint32_t)(cc ^ axr[im]) << 4));
            #pragma unroll
            for (int in = 0; in < 2; in++)
                ldsm4(bf[in][0], bf[in][1], bf[in][2], bf[in][3],
                      bs + brow128[in] + ((uint32_t)(cc ^ bxr[in]) << 4));
            #pragma unroll
            for (int im = 0; im < 4; im++) {
                #pragma unroll
                for (int j = 0; j < 4; j++)
                    mma_tf32(acc[im][j], af[im], bf[j >> 1][j & 1], bf[j >> 1][2 + (j & 1)]);
            }
        }
        cs = (cs == 2) ? 0 : cs + 1;
        is_ = (is_ == 2) ? 0 : is_ + 1;
        __syncthreads();
    }

    // ---- epilogue ----
    #pragma unroll
    for (int im = 0; im < 4; im++) {
        #pragma unroll
        for (int half = 0; half < 2; half++) {
            size_t row = bm + wm + im*16 + g + half*8;
            #pragma unroll
            for (int in = 0; in < 4; in++) {
                size_t col = bn + wn + in*8 + 2*t;
                float v0 = acc[im][in][half*2 + 0];
                float v1 = acc[im][in][half*2 + 1];
                if (EPI == 1) {
                    v0 += aux[col]; v1 += aux[col+1];
                } else if (EPI == 2) {
                    v0 = tf32r(fmaxf(v0, 0.f)); v1 = tf32r(fmaxf(v1, 0.f));
                } else if (EPI == 3) {
                    v0 += aux[row*N+col]; v1 += aux[row*N+col+1];
                }
                *(float2*)(C + row*N + col) = make_float2(v0, v1);
            }
        }
    }
}

template<int EPI>
__global__ __launch_bounds__(256, 2) void mgemm(
    const float* __restrict__ A, const float* __restrict__ BT, float* __restrict__ C,
    int M, int N, int K, const float* __restrict__ aux)
{
    mgemm_core<EPI>(A, BT, C, M, N, K, aux);
}

__global__ __launch_bounds__(256, 2) void mgemm_qkv(
    const float* __restrict__ A,
    const float* __restrict__ BT0, const float* __restrict__ BT1, const float* __restrict__ BT2,
    float* __restrict__ C0, float* __restrict__ C1, float* __restrict__ C2,
    int M, int N, int K)
{
    const float* BT = (blockIdx.z == 0) ? BT0 : ((blockIdx.z == 1) ? BT1 : BT2);
    float*       C  = (blockIdx.z == 0) ? C0  : ((blockIdx.z == 1) ? C1  : C2);
    mgemm_core<0>(A, BT, C, M, N, K, nullptr);
}

// ---------------- weight transpose + tf32 round: in[R][C] -> out[C][R] ----------------
__global__ __launch_bounds__(256) void transpose_kernel(
    const float* __restrict__ in, float* __restrict__ out, int R, int C)
{
    __shared__ float tsm[32][33];
    int cx = blockIdx.x * 32, ry = blockIdx.y * 32;
    int x = threadIdx.x, y = threadIdx.y;
    #pragma unroll
    for (int i = 0; i < 32; i += 8)
        tsm[y + i][x] = in[(size_t)(ry + y + i) * C + cx + x];
    __syncthreads();
    #pragma unroll
    for (int i = 0; i < 32; i += 8)
        out[(size_t)(cx + y + i) * R + ry + x] = tf32r(tsm[x][y + i]);
}

// ---------------- tf32 rounding copy ----------------
__global__ __launch_bounds__(256) void round_kernel(
    const float* __restrict__ in, float* __restrict__ out)
{
    size_t i = ((size_t)blockIdx.x * 256 + threadIdx.x) * 4;
    float4 v = *(const float4*)(in + i);
    v.x = tf32r(v.x); v.y = tf32r(v.y); v.z = tf32r(v.z); v.w = tf32r(v.w);
    *(float4*)(out + i) = v;
}

// ---------------- relative-position bucket ----------------
__global__ void bucket_kernel(int* __restrict__ bkt) {
    int i = blockIdx.x, j = threadIdx.x;
    int rel = j - i;
    int base = (rel > 0) ? 16 : 0;
    int arel = rel < 0 ? -rel : rel;
    int v;
    if (arel < 8) {
        v = arel;
    } else {
        float t = logf((float)arel / 8.0f) / 2.772588722239781f * 8.0f;
        v = 8 + (int)t;
        if (v > 15) v = 15;
    }
    bkt[i*SEQ + j] = base + v;
}

// ---------------- depthwise 3x3 conv (output tf32-rounded for fc2) ----------------
__global__ __launch_bounds__(128) void conv_kernel(
    const float* __restrict__ h1, const float* __restrict__ cw,
    const float* __restrict__ cb, float* __restrict__ out)
{
    int p  = blockIdx.x;
    int l  = p & 255;
    int bn = p >> 8;
    int ni = bn & 7;
    int bi = bn >> 3;
    int c  = threadIdx.x;

    float acc = cb[c];
    #pragma unroll
    for (int dn = -1; dn <= 1; dn++) {
        int nn = ni + dn;
        if (nn < 0 || nn >= NFRAMES) continue;
        #pragma unroll
        for (int dl = -1; dl <= 1; dl++) {
            int ll = l + dl;
            if (ll < 0 || ll >= SEQ) continue;
            float x = h1[(size_t)(((bi*NFRAMES + nn)*SEQ) + ll) * ADC + c];
            acc = fmaf(x, cw[c*9 + (dn+1)*3 + (dl+1)], acc);
        }
    }
    out[(size_t)p * ADC + c] = tf32r(acc);
}

// ---------------- block reductions / norms ----------------
__device__ __forceinline__ float blk_sum(float v, volatile float* red) {
    int tid = threadIdx.x;
    #pragma unroll
    for (int o = 16; o; o >>= 1) v += __shfl_xor_sync(0xffffffffu, v, o);
    if ((tid & 31) == 0) red[tid >> 5] = v;
    __syncthreads();
    if (tid == 0) {
        float s = 0.f;
        #pragma unroll
        for (int w = 0; w < 8; w++) s += red[w];
        red[8] = s;
    }
    __syncthreads();
    return red[8];
}

__global__ __launch_bounds__(256) void ln_res_kernel(
    const float* __restrict__ x, const float* __restrict__ w,
    const float* __restrict__ bvec, const float* __restrict__ res,
    float* __restrict__ out)
{
    __shared__ float red[9];
    size_t base = (size_t)blockIdx.x * DMODEL;
    int t = threadIdx.x;
    float v0 = x[base+t], v1 = x[base+t+256], v2 = x[base+t+512];
    float mu = blk_sum(v0+v1+v2, red) * (1.f/DMODEL);
    __syncthreads();
    float d0 = v0-mu, d1 = v1-mu, d2 = v2-mu;
    float var = blk_sum(d0*d0 + d1*d1 + d2*d2, red) * (1.f/DMODEL);
    float inv = rsqrtf(var + 1e-5f);
    out[base+t    ] = d0*inv*w[t]     + bvec[t]     + res[base+t];
    out[base+t+256] = d1*inv*w[t+256] + bvec[t+256] + res[base+t+256];
    out[base+t+512] = d2*inv*w[t+512] + bvec[t+512] + res[base+t+512];
}

// rms with tf32-rounded output (consumed only as GEMM A)
__global__ __launch_bounds__(256) void rms_kernel(
    const float* __restrict__ x, const float* __restrict__ w, float* __restrict__ out)
{
    __shared__ float red[9];
    size_t base = (size_t)blockIdx.x * DMODEL;
    int t = threadIdx.x;
    float v0 = x[base+t], v1 = x[base+t+256], v2 = x[base+t+512];
    float ms = blk_sum(v0*v0 + v1*v1 + v2*v2, red) * (1.f/DMODEL);
    float inv = rsqrtf(ms + 1e-6f);
    out[base+t    ] = tf32r(w[t]    *v0*inv);
    out[base+t+256] = tf32r(w[t+256]*v1*inv);
    out[base+t+512] = tf32r(w[t+512]*v2*inv);
}

// ---------------- fused scores (+bbox +relpos) + softmax ----------------
__global__ __launch_bounds__(256) void scores_kernel(
    const float* __restrict__ q, const float* __restrict__ k,
    const float* __restrict__ bbox, const float* __restrict__ rel_bias,
    const int* __restrict__ bkt, float* __restrict__ attn)
{
    int b = blockIdx.x;
    int i = blockIdx.y;
    __shared__ float qrow[DMODEL];
    __shared__ float sc[NHEADS][SEQ];
    int tid = threadIdx.x;

    for (int t = tid; t < DMODEL; t += 256)
        qrow[t] = q[((size_t)(b*SEQ) + i) * DMODEL + t];
    __syncthreads();

    int j = tid;
    const float* krow = k + ((size_t)(b*SEQ) + j) * DMODEL;
    const float* bb   = bbox + (((size_t)i*SEQ + j) * BATCH + b) * DHEAD;
    int bu = bkt[i*SEQ + j];

    float bbv[DHEAD];
    #pragma unroll
    for (int d = 0; d < DHEAD; d += 4)
        *(float4*)&bbv[d] = *(const float4*)&bb[d];

    for (int h = 0; h < NHEADS; h++) {
        const float* qh = &qrow[h*DHEAD];
        const float* kh = &krow[h*DHEAD];
        float s1 = 0.f, s2 = 0.f;
        #pragma unroll
        for (int d = 0; d < DHEAD; d += 4) {
            float4 kv = *(const float4*)&kh[d];
            s1 = fmaf(qh[d+0], kv.x, s1);
            s1 = fmaf(qh[d+1], kv.y, s1);
            s1 = fmaf(qh[d+2], kv.z, s1);
            s1 = fmaf(qh[d+3], kv.w, s1);
            s2 = fmaf(qh[d+0], bbv[d+0], s2);
            s2 = fmaf(qh[d+1], bbv[d+1], s2);
            s2 = fmaf(qh[d+2], bbv[d+2], s2);
            s2 = fmaf(qh[d+3], bbv[d+3], s2);
        }
        sc[h][j] = (s1 + s2 + rel_bias[bu*NHEADS + h]) * 0.125f;
    }
    __syncthreads();

    int warp = tid >> 5, lane = tid & 31;
    for (int h = warp; h < NHEADS; h += 8) {
        float m = -1e30f;
        for (int t = lane; t < SEQ; t += 32) m = fmaxf(m, sc[h][t]);
        #pragma unroll
        for (int o = 16; o; o >>= 1) m = fmaxf(m, __shfl_xor_sync(0xffffffffu, m, o));
        float sum = 0.f;
        for (int t = lane; t < SEQ; t += 32) {
            float e = expf(sc[h][t] - m);
            sc[h][t] = e;
            sum += e;
        }
        #pragma unroll
        for (int o = 16; o; o >>= 1) sum += __shfl_xor_sync(0xffffffffu, sum, o);
        float invs = 1.f / sum;
        float* out = attn + (((size_t)(b*NHEADS + h)*SEQ) + i) * SEQ;
        for (int t = lane; t < SEQ; t += 32) out[t] = sc[h][t] * invs;
    }
}

// ---------------- ctx = attn @ V -> (b, l, h, d), tf32-rounded ----------------
__global__ __launch_bounds__(256) void ctx_kernel(
    const float* __restrict__ attn, const float* __restrict__ v,
    float* __restrict__ ctx)
{
    int bh = blockIdx.x;
    int b = bh / NHEADS, h = bh % NHEADS;
    int i0 = blockIdx.y * 64;
    __shared__ float At[64][65];
    __shared__ float Vt[64][64];
    int tid = threadIdx.x;
    int tx = tid & 15, ty = tid >> 4;

    float acc[4][4] = {};
    const float* arow = attn + ((size_t)bh * SEQ + i0) * SEQ;

    for (int j0 = 0; j0 < SEQ; j0 += 64) {
        __syncthreads();
        for (int e = tid; e < 4096; e += 256) {
            int r = e >> 6, c = e & 63;
            At[c][r] = arow[(size_t)r * SEQ + j0 + c];
            Vt[r][c] = v[(size_t)(b*SEQ + j0 + r) * DMODEL + h*DHEAD + c];
        }
        __syncthreads();
        #pragma unroll 8
        for (int kk = 0; kk < 64; kk++) {
            float a[4], bb[4];
            #pragma unroll
            for (int ii = 0; ii < 4; ii++) a[ii] = At[kk][(ty<<2) + ii];
            *(float4*)bb = *(const float4*)&Vt[kk][tx<<2];
            #pragma unroll
            for (int ii = 0; ii < 4; ii++)
                #pragma unroll
                for (int jj = 0; jj < 4; jj++)
                    acc[ii][jj] = fmaf(a[ii], bb[jj], acc[ii][jj]);
        }
    }
    #pragma unroll
    for (int ii = 0; ii < 4; ii++)
        #pragma unroll
        for (int jj = 0; jj < 4; jj++)
            ctx[(((size_t)(b*SEQ + i0 + (ty<<2) + ii))*NHEADS + h)*DHEAD + (tx<<2) + jj]
                = tf32r(acc[ii][jj]);
}

// ---------------- launch ----------------
extern "C" void kernel_launch(void* const* d_in, const int* in_sizes, int n_in,
                              void* d_out, int out_size)
{
    const float* hidden  = (const float*)d_in[0];
    const float* bbox    = (const float*)d_in[1];
    const float* fc1_w   = (const float*)d_in[2];
    const float* fc1_b   = (const float*)d_in[3];
    const float* conv_w  = (const float*)d_in[4];
    const float* conv_b  = (const float*)d_in[5];
    const float* fc2_w   = (const float*)d_in[6];
    const float* fc2_b   = (const float*)d_in[7];
    const float* ln_ad_w = (const float*)d_in[8];
    const float* ln_ad_b = (const float*)d_in[9];
    const float* ln1_w   = (const float*)d_in[10];
    const float* q_w     = (const float*)d_in[11];
    const float* k_w     = (const float*)d_in[12];
    const float* v_w     = (const float*)d_in[13];
    const float* o_w     = (const float*)d_in[14];
    const float* rel_b   = (const float*)d_in[15];
    const float* ln2_w   = (const float*)d_in[16];
    const float* wi_w    = (const float*)d_in[17];
    const float* wo_w    = (const float*)d_in[18];
    float* out = (float*)d_out;

    float *h1, *cv, *hs, *hn, *hr, *q, *k, *v, *ctx, *hs2, *attn, *ff;
    float *wtq, *wtk, *wtv, *wto, *wtwi, *wtwo, *wtf1, *wtf2;
    int* bkt;
    cudaGetSymbolAddress((void**)&h1,  g_h1);
    cudaGetSymbolAddress((void**)&cv,  g_conv);
    cudaGetSymbolAddress((void**)&hs,  g_hs);
    cudaGetSymbolAddress((void**)&hn,  g_hn);
    cudaGetSymbolAddress((void**)&hr,  g_hr);
    cudaGetSymbolAddress((void**)&q,   g_q);
    cudaGetSymbolAddress((void**)&k,   g_k);
    cudaGetSymbolAddress((void**)&v,   g_v);
    cudaGetSymbolAddress((void**)&ctx, g_ctx);
    cudaGetSymbolAddress((void**)&hs2, g_hs2);
    cudaGetSymbolAddress((void**)&attn,g_attn);
    cudaGetSymbolAddress((void**)&ff,  g_ff);
    cudaGetSymbolAddress((void**)&bkt, g_bucket);
    cudaGetSymbolAddress((void**)&wtq, g_wt_q);
    cudaGetSymbolAddress((void**)&wtk, g_wt_k);
    cudaGetSymbolAddress((void**)&wtv, g_wt_v);
    cudaGetSymbolAddress((void**)&wto, g_wt_o);
    cudaGetSymbolAddress((void**)&wtwi, g_wt_wi);
    cudaGetSymbolAddress((void**)&wtwo, g_wt_wo);
    cudaGetSymbolAddress((void**)&wtf1, g_wt_fc1);
    cudaGetSymbolAddress((void**)&wtf2, g_wt_fc2);

    cudaFuncSetAttribute(mgemm<0>, cudaFuncAttributeMaxDynamicSharedMemorySize, SMEMB);
    cudaFuncSetAttribute(mgemm<1>, cudaFuncAttributeMaxDynamicSharedMemorySize, SMEMB);
    cudaFuncSetAttribute(mgemm<2>, cudaFuncAttributeMaxDynamicSharedMemorySize, SMEMB);
    cudaFuncSetAttribute(mgemm<3>, cudaFuncAttributeMaxDynamicSharedMemorySize, SMEMB);
    cudaFuncSetAttribute(mgemm_qkv, cudaFuncAttributeMaxDynamicSharedMemorySize, SMEMB);

    dim3 tb(32, 8);
    // weight transposes ([K][N] -> [N][K], tf32-rounded)
    transpose_kernel<<<dim3(ADC/32,    DMODEL/32), tb>>>(fc1_w, wtf1, DMODEL, ADC);
    transpose_kernel<<<dim3(DMODEL/32, ADC/32),    tb>>>(fc2_w, wtf2, ADC, DMODEL);
    transpose_kernel<<<dim3(DMODEL/32, DMODEL/32), tb>>>(q_w, wtq, DMODEL, DMODEL);
    transpose_kernel<<<dim3(DMODEL/32, DMODEL/32), tb>>>(k_w, wtk, DMODEL, DMODEL);
    transpose_kernel<<<dim3(DMODEL/32, DMODEL/32), tb>>>(v_w, wtv, DMODEL, DMODEL);
    transpose_kernel<<<dim3(DMODEL/32, DMODEL/32), tb>>>(o_w, wto, DMODEL, DMODEL);
    transpose_kernel<<<dim3(DFF/32,    DMODEL/32), tb>>>(wi_w, wtwi, DMODEL, DFF);
    transpose_kernel<<<dim3(DMODEL/32, DFF/32),    tb>>>(wo_w, wtwo, DFF, DMODEL);

    round_kernel<<<ROWS*DMODEL/1024, 256>>>(hidden, hr);
    bucket_kernel<<<SEQ, SEQ>>>(bkt);

    // ---- adapter ----
    mgemm<1><<<dim3(1, 32), 256, SMEMB>>>(hr, wtf1, h1, ROWS, ADC, DMODEL, fc1_b);
    conv_kernel<<<ROWS, ADC>>>(h1, conv_w, conv_b, cv);
    mgemm<1><<<dim3(6, 32), 256, SMEMB>>>(cv, wtf2, hn, ROWS, DMODEL, ADC, fc2_b);
    ln_res_kernel<<<ROWS, 256>>>(hn, ln_ad_w, ln_ad_b, hidden, hs);

    // ---- attention ----
    rms_kernel<<<ROWS, 256>>>(hs, ln1_w, hn);
    mgemm_qkv<<<dim3(6, 32, 3), 256, SMEMB>>>(hn, wtq, wtk, wtv, q, k, v,
                                              ROWS, DMODEL, DMODEL);
    scores_kernel<<<dim3(BATCH, SEQ), 256>>>(q, k, bbox, rel_b, bkt, attn);
    ctx_kernel<<<dim3(BATCH*NHEADS, SEQ/64), 256>>>(attn, v, ctx);
    mgemm<3><<<dim3(6, 32), 256, SMEMB>>>(ctx, wto, hs2, ROWS, DMODEL, DMODEL, hs);

    // ---- FFN ----
    rms_kernel<<<ROWS, 256>>>(hs2, ln2_w, hn);
    mgemm<2><<<dim3(24, 32), 256, SMEMB>>>(hn, wtwi, ff, ROWS, DFF, DMODEL, nullptr);
    mgemm<3><<<dim3(6, 32), 256, SMEMB>>>(ff, wtwo, out, ROWS, DMODEL, DFF, hs2);
}

// round 5
// speedup vs baseline: 3.8402x; 1.9457x over previous
#include <cuda_runtime.h>
#include <cuda_fp16.h>
#include <math.h>
#include <stdint.h>

// ---------------- problem constants ----------------
#define BATCH   16
#define NFRAMES 8
#define SEQ     256
#define DMODEL  768
#define NHEADS  12
#define DHEAD   64
#define DFF     3072
#define ADC     128
#define ROWS    (BATCH*SEQ) // 4096
#define QKVN    2304

// ---------------- scratch (device globals; no allocations) ----------------
__device__ __align__(16) __half g_h16 [ROWS*DMODEL];
__device__ __align__(16) float  g_h1  [ROWS*ADC];
__device__ __align__(16) __half g_cv16[ROWS*ADC];
__device__ __align__(16) float  g_ad  [ROWS*DMODEL];
__device__ __align__(16) float  g_hs  [ROWS*DMODEL];
__device__ __align__(16) __half g_hn16[ROWS*DMODEL];
__device__ __align__(16) float  g_qkv [ROWS*QKVN];
__device__ __align__(16) __half g_ctx16[ROWS*DMODEL];
__device__ __align__(16) float  g_hs2 [ROWS*DMODEL];
__device__ __align__(16) float  g_attn[BATCH*NHEADS*SEQ*SEQ];
__device__ __align__(16) __half g_ff16[ROWS*DFF];
__device__ int g_bucket[SEQ*SEQ];
// fp16 transposed weights [N][K]
__device__ __align__(16) __half g_wt_qkv[QKVN*DMODEL];
__device__ __align__(16) __half g_wt_o  [DMODEL*DMODEL];
__device__ __align__(16) __half g_wt_wi [DFF*DMODEL];
__device__ __align__(16) __half g_wt_wo [DMODEL*DFF];
__device__ __align__(16) __half g_wt_fc1[ADC*DMODEL];
__device__ __align__(16) __half g_wt_fc2[DMODEL*ADC];

// ================= helpers =================
__device__ __forceinline__ uint32_t smem_u32(const void* p) {
    uint32_t a;
    asm("{ .reg .u64 t; cvta.to.shared.u64 t, %1; cvt.u32.u64 %0, t; }" : "=r"(a) : "l"(p));
    return a;
}
__device__ __forceinline__ void cp16(uint32_t s, const void* g) {
    asm volatile("cp.async.cg.shared.global [%0], [%1], 16;" :: "r"(s), "l"(g));
}
#define CP_COMMIT() asm volatile("cp.async.commit_group;" ::: "memory")
#define CP_WAIT1()  asm volatile("cp.async.wait_group 1;" ::: "memory")

__device__ __forceinline__ void ldsm4(uint32_t* r, uint32_t a) {
    asm volatile("ldmatrix.sync.aligned.m8n8.x4.shared.b16 {%0,%1,%2,%3}, [%4];"
                 : "=r"(r[0]), "=r"(r[1]), "=r"(r[2]), "=r"(r[3]) : "r"(a));
}
__device__ __forceinline__ void mma_f16(float c[4], const uint32_t a[4],
                                        uint32_t b0, uint32_t b1) {
    asm volatile(
        "mma.sync.aligned.m16n8k16.row.col.f32.f16.f16.f32 "
        "{%0,%1,%2,%3}, {%4,%5,%6,%7}, {%8,%9}, {%0,%1,%2,%3};\n"
        : "+f"(c[0]), "+f"(c[1]), "+f"(c[2]), "+f"(c[3])
        : "r"(a[0]), "r"(a[1]), "r"(a[2]), "r"(a[3]), "r"(b0), "r"(b1));
}

// fast exp on FMA pipe (no MUFU): exp(x) = 2^(x*log2e), x <= 0
__device__ __forceinline__ float fast_exp(float x) {
    float t = x * 1.4426950408889634f;
    t = fmaxf(t, -126.0f);
    float r = t + 12582912.0f;
    float n = r - 12582912.0f;
    float f = t - n;
    float p = 1.33335581e-3f;
    p = fmaf(p, f, 9.61812910e-3f);
    p = fmaf(p, f, 5.55041087e-2f);
    p = fmaf(p, f, 2.40226507e-1f);
    p = fmaf(p, f, 6.93147182e-1f);
    p = fmaf(p, f, 1.0f);
    int ni = (int)n;
    return p * __int_as_float((ni + 127) << 23);
}

// ================= fp16 mma.sync GEMM =================
// tile 128x128x64 (fp16 tiles, 128B rows), 3-stage cp.async, 8 warps (2x4 -> 64x32)
// EPI: 0=none, 1=+bias[col], 2=relu->half, 3=+residual
#define BK 64
#define ABYT (128*128)
#define STG  (2*ABYT)
#define SMEMB (3*STG)

__device__ __forceinline__ void stage_tile(uint32_t sa, const __half* Ag,
                                           const __half* Bg, int K, int tid) {
    #pragma unroll
    for (int p = 0; p < 4; p++) {
        int id = tid + p * 256;
        int row = id >> 3, c = id & 7;
        uint32_t off = (uint32_t)(row * 128 + c * 16);
        off ^= ((off >> 3) & 0x70);
        cp16(sa + off,        Ag + (size_t)row * K + c * 8);
        cp16(sa + ABYT + off, Bg + (size_t)row * K + c * 8);
    }
}

template<int EPI>
__device__ __forceinline__ void hgemm_core(
    const __half* __restrict__ A, const __half* __restrict__ BT,
    void* __restrict__ Cv, int M, int N, int K, const float* __restrict__ aux)
{
    extern __shared__ __align__(16) char smc[];
    const uint32_t sbase = smem_u32(smc);
    const int tid  = threadIdx.x;
    const int lane = tid & 31;
    const int warp = tid >> 5;
    const int wm = (warp & 1) * 64;
    const int wn = (warp >> 1) * 32;
    const int g = lane >> 2;
    const int t = lane & 3;
    const size_t bm = (size_t)blockIdx.y * 128;
    const size_t bn = (size_t)blockIdx.x * 128;

    const __half* Ab = A  + bm * K;
    const __half* Bb = BT + bn * K;
    const int ktiles = K >> 6;

    // ldsm address components: row = base + (lane&15), kbyte += (lane>>4)*16
    const int l16 = lane & 15;
    const int khb = (lane >> 4) << 4;       // 0 or 16 bytes
    uint32_t arb[4], brb[2]; uint32_t arx[4], brx[2];
    #pragma unroll
    for (int im = 0; im < 4; im++) {
        int r = wm + im*16 + l16;
        arb[im] = r * 128; arx[im] = (r & 7) << 4;
    }
    #pragma unroll
    for (int p = 0; p < 2; p++) {
        int r = wn + p*16 + l16;
        brb[p] = r * 128; brx[p] = (r & 7) << 4;
    }

    float acc[4][4][4];
    #pragma unroll
    for (int i = 0; i < 4; i++)
        #pragma unroll
        for (int j = 0; j < 4; j++)
            #pragma unroll
            for (int r = 0; r < 4; r++) acc[i][j][r] = 0.f;

    #pragma unroll
    for (int s = 0; s < 2; s++) {
        if (s < ktiles)
            stage_tile(sbase + s * STG, Ab + s * BK, Bb + s * BK, K, tid);
        CP_COMMIT();
    }

    int cs = 0, is_ = 2;
    for (int kt = 0; kt < ktiles; kt++) {
        CP_WAIT1();
        __syncthreads();

        if (kt + 2 < ktiles)
            stage_tile(sbase + is_ * STG, Ab + (kt+2) * BK, Bb + (kt+2) * BK, K, tid);
        CP_COMMIT();

        const uint32_t as = sbase + cs * STG;
        const uint32_t bs = as + ABYT;
        #pragma unroll
        for (int kk = 0; kk < 4; kk++) {
            const uint32_t kb = kk * 32 + khb;
            uint32_t af[4][4], bf[2][4];
            #pragma unroll
            for (int im = 0; im < 4; im++)
                ldsm4(af[im], as + arb[im] + (kb ^ arx[im]));
            #pragma unroll
            for (int p = 0; p < 2; p++)
                ldsm4(bf[p], bs + brb[p] + (kb ^ brx[p]));
            #pragma unroll
            for (int im = 0; im < 4; im++)
                #pragma unroll
                for (int j = 0; j < 4; j++)
                    mma_f16(acc[im][j], af[im], bf[j>>1][j&1], bf[j>>1][2+(j&1)]);
        }
        cs = (cs == 2) ? 0 : cs + 1;
        is_ = (is_ == 2) ? 0 : is_ + 1;
        __syncthreads();
    }

    // epilogue
    #pragma unroll
    for (int im = 0; im < 4; im++) {
        #pragma unroll
        for (int half = 0; half < 2; half++) {
            size_t row = bm + wm + im*16 + g + half*8;
            #pragma unroll
            for (int in = 0; in < 4; in++) {
                size_t col = bn + wn + in*8 + 2*t;
                float v0 = acc[im][in][half*2 + 0];
                float v1 = acc[im][in][half*2 + 1];
                if (EPI == 2) {
                    v0 = fmaxf(v0, 0.f); v1 = fmaxf(v1, 0.f);
                    __half2* cp = (__half2*)((__half*)Cv + row*N + col);
                    *cp = __floats2half2_rn(v0, v1);
                } else {
                    if (EPI == 1) { v0 += aux[col]; v1 += aux[col+1]; }
                    else if (EPI == 3) { v0 += aux[row*N+col]; v1 += aux[row*N+col+1]; }
                    *(float2*)((float*)Cv + row*N + col) = make_float2(v0, v1);
                }
            }
        }
    }
}

template<int EPI>
__global__ __launch_bounds__(256, 2) void hgemm(
    const __half* __restrict__ A, const __half* __restrict__ BT, void* __restrict__ C,
    int M, int N, int K, const float* __restrict__ aux)
{
    hgemm_core<EPI>(A, BT, C, M, N, K, aux);
}

// ---------------- weight transpose + fp16: in[R][C] float -> out[C][R] half ----------------
__global__ __launch_bounds__(256) void transpose_kernel(
    const float* __restrict__ in, __half* __restrict__ out, int R, int C)
{
    __shared__ float tsm[32][33];
    int cx = blockIdx.x * 32, ry = blockIdx.y * 32;
    int x = threadIdx.x, y = threadIdx.y;
    #pragma unroll
    for (int i = 0; i < 32; i += 8)
        tsm[y + i][x] = in[(size_t)(ry + y + i) * C + cx + x];
    __syncthreads();
    #pragma unroll
    for (int i = 0; i < 32; i += 8)
        out[(size_t)(cx + y + i) * R + ry + x] = __float2half_rn(tsm[x][y + i]);
}

// ---------------- float -> half copy ----------------
__global__ __launch_bounds__(256) void round_kernel(
    const float* __restrict__ in, __half* __restrict__ out)
{
    size_t i = ((size_t)blockIdx.x * 256 + threadIdx.x) * 4;
    float4 v = *(const float4*)(in + i);
    __half2* o = (__half2*)(out + i);
    o[0] = __floats2half2_rn(v.x, v.y);
    o[1] = __floats2half2_rn(v.z, v.w);
}

// ---------------- relative-position bucket ----------------
__global__ void bucket_kernel(int* __restrict__ bkt) {
    int i = blockIdx.x, j = threadIdx.x;
    int rel = j - i;
    int base = (rel > 0) ? 16 : 0;
    int arel = rel < 0 ? -rel : rel;
    int v;
    if (arel < 8) {
        v = arel;
    } else {
        float t = logf((float)arel / 8.0f) / 2.772588722239781f * 8.0f;
        v = 8 + (int)t;
        if (v > 15) v = 15;
    }
    bkt[i*SEQ + j] = base + v;
}

// ---------------- depthwise 3x3 conv -> half ----------------
__global__ __launch_bounds__(128) void conv_kernel(
    const float* __restrict__ h1, const float* __restrict__ cw,
    const float* __restrict__ cb, __half* __restrict__ out)
{
    int p  = blockIdx.x;
    int l  = p & 255;
    int bn = p >> 8;
    int ni = bn & 7;
    int bi = bn >> 3;
    int c  = threadIdx.x;

    float acc = cb[c];
    #pragma unroll
    for (int dn = -1; dn <= 1; dn++) {
        int nn = ni + dn;
        if (nn < 0 || nn >= NFRAMES) continue;
        #pragma unroll
        for (int dl = -1; dl <= 1; dl++) {
            int ll = l + dl;
            if (ll < 0 || ll >= SEQ) continue;
            float x = h1[(size_t)(((bi*NFRAMES + nn)*SEQ) + ll) * ADC + c];
            acc = fmaf(x, cw[c*9 + (dn+1)*3 + (dl+1)], acc);
        }
    }
    out[(size_t)p * ADC + c] = __float2half_rn(acc);
}

// ---------------- norms ----------------
__device__ __forceinline__ float blk_sum(float v, volatile float* red) {
    int tid = threadIdx.x;
    #pragma unroll
    for (int o = 16; o; o >>= 1) v += __shfl_xor_sync(0xffffffffu, v, o);
    if ((tid & 31) == 0) red[tid >> 5] = v;
    __syncthreads();
    if (tid == 0) {
        float s = 0.f;
        #pragma unroll
        for (int w = 0; w < 8; w++) s += red[w];
        red[8] = s;
    }
    __syncthreads();
    return red[8];
}

__global__ __launch_bounds__(256) void ln_res_kernel(
    const float* __restrict__ x, const float* __restrict__ w,
    const float* __restrict__ bvec, const float* __restrict__ res,
    float* __restrict__ out)
{
    __shared__ float red[9];
    size_t base = (size_t)blockIdx.x * DMODEL;
    int t = threadIdx.x;
    float v0 = x[base+t], v1 = x[base+t+256], v2 = x[base+t+512];
    float mu = blk_sum(v0+v1+v2, red) * (1.f/DMODEL);
    __syncthreads();
    float d0 = v0-mu, d1 = v1-mu, d2 = v2-mu;
    float var = blk_sum(d0*d0 + d1*d1 + d2*d2, red) * (1.f/DMODEL);
    float inv = rsqrtf(var + 1e-5f);
    out[base+t    ] = d0*inv*w[t]     + bvec[t]     + res[base+t];
    out[base+t+256] = d1*inv*w[t+256] + bvec[t+256] + res[base+t+256];
    out[base+t+512] = d2*inv*w[t+512] + bvec[t+512] + res[base+t+512];
}

__global__ __launch_bounds__(256) void rms_kernel(
    const float* __restrict__ x, const float* __restrict__ w, __half* __restrict__ out)
{
    __shared__ float red[9];
    size_t base = (size_t)blockIdx.x * DMODEL;
    int t = threadIdx.x;
    float v0 = x[base+t], v1 = x[base+t+256], v2 = x[base+t+512];
    float ms = blk_sum(v0*v0 + v1*v1 + v2*v2, red) * (1.f/DMODEL);
    float inv = rsqrtf(ms + 1e-6f);
    out[base+t    ] = __float2half_rn(w[t]    *v0*inv);
    out[base+t+256] = __float2half_rn(w[t+256]*v1*inv);
    out[base+t+512] = __float2half_rn(w[t+512]*v2*inv);
}

// ---------------- fused scores (+bbox +relpos) + softmax, 4 query rows/block ----------------
#define SC_SMEM ((4*DMODEL + 48*SEQ + 384)*4)
__global__ __launch_bounds__(256) void scores_kernel(
    const float* __restrict__ qkv, const float* __restrict__ bbox,
    const float* __restrict__ rel_bias, const int* __restrict__ bkt,
    float* __restrict__ attn)
{
    const int b  = blockIdx.x;
    const int i0 = blockIdx.y * 4;
    extern __shared__ __align__(16) float dsm[];
    float* qs  = dsm;                 // [4][768]
    float* sc  = dsm + 4*DMODEL;      // [48][256]
    float* rbs = sc + 48*SEQ;         // [32][12]
    const int tid = threadIdx.x;

    for (int t = tid; t < 4*DMODEL; t += 256) {
        int r = t / DMODEL, d = t - r*DMODEL;
        qs[r*DMODEL + d] = qkv[((size_t)(b*SEQ) + i0 + r) * QKVN + d];
    }
    for (int t = tid; t < 384; t += 256) rbs[t] = rel_bias[t];
    __syncthreads();

    const int j = tid;
    const float* krow = qkv + ((size_t)(b*SEQ) + j) * QKVN + DMODEL;

    // QK phase: thread j, k row in registers chunk-wise, 4 query rows
    #pragma unroll 1
    for (int h = 0; h < NHEADS; h++) {
        const float4* k4 = (const float4*)(krow + h*DHEAD);
        float acc[4] = {0.f, 0.f, 0.f, 0.f};
        #pragma unroll
        for (int c = 0; c < 16; c++) {
            float4 kv = k4[c];
            #pragma unroll
            for (int i = 0; i < 4; i++) {
                float4 qv = *(const float4*)&qs[i*DMODEL + h*DHEAD + c*4];
                acc[i] = fmaf(qv.x, kv.x, acc[i]);
                acc[i] = fmaf(qv.y, kv.y, acc[i]);
                acc[i] = fmaf(qv.z, kv.z, acc[i]);
                acc[i] = fmaf(qv.w, kv.w, acc[i]);
            }
        }
        #pragma unroll
        for (int i = 0; i < 4; i++) sc[(h*4+i)*SEQ + j] = acc[i];
    }

    // bbox + rel bias + scale
    #pragma unroll 1
    for (int i = 0; i < 4; i++) {
        const float4* bb4 = (const float4*)(bbox + (((size_t)(i0+i)*SEQ + j)*BATCH + b)*DHEAD);
        float part[NHEADS];
        #pragma unroll
        for (int h = 0; h < NHEADS; h++) part[h] = 0.f;
        #pragma unroll
        for (int c = 0; c < 16; c++) {
            float4 bv = bb4[c];
            #pragma unroll
            for (int h = 0; h < NHEADS; h++) {
                float4 qv = *(const float4*)&qs[i*DMODEL + h*DHEAD + c*4];
                part[h] = fmaf(qv.x, bv.x, part[h]);
                part[h] = fmaf(qv.y, bv.y, part[h]);
                part[h] = fmaf(qv.z, bv.z, part[h]);
                part[h] = fmaf(qv.w, bv.w, part[h]);
            }
        }
        int bu = bkt[(i0+i)*SEQ + j];
        #pragma unroll
        for (int h = 0; h < NHEADS; h++) {
            float s = sc[(h*4+i)*SEQ + j] + part[h] + rbs[bu*NHEADS + h];
            sc[(h*4+i)*SEQ + j] = s * 0.125f;
        }
    }
    __syncthreads();

    // softmax: 48 (h,i) rows; warp w -> rows w*6 .. w*6+5
    const int warp = tid >> 5, lane = tid & 31;
    for (int rr = 0; rr < 6; rr++) {
        int row = warp*6 + rr;
        int h = row >> 2, i = row & 3;
        float* p = sc + row*SEQ;
        float m = -1e30f;
        #pragma unroll
        for (int u = 0; u < 8; u++) m = fmaxf(m, p[lane + u*32]);
        #pragma unroll
        for (int o = 16; o; o >>= 1) m = fmaxf(m, __shfl_xor_sync(0xffffffffu, m, o));
        float e[8], sum = 0.f;
        #pragma unroll
        for (int u = 0; u < 8; u++) { e[u] = fast_exp(p[lane + u*32] - m); sum += e[u]; }
        #pragma unroll
        for (int o = 16; o; o >>= 1) sum += __shfl_xor_sync(0xffffffffu, sum, o);
        float inv = 1.f / sum;
        float* o = attn + (((size_t)(b*NHEADS + h)*SEQ) + i0 + i)*SEQ;
        #pragma unroll
        for (int u = 0; u < 8; u++) o[lane + u*32] = e[u] * inv;
    }
}

// ---------------- ctx = attn @ V -> half (b, l, h, d) ----------------
__global__ __launch_bounds__(256) void ctx_kernel(
    const float* __restrict__ attn, const float* __restrict__ qkv,
    __half* __restrict__ ctx)
{
    int bh = blockIdx.x;
    int b = bh / NHEADS, h = bh % NHEADS;
    int i0 = blockIdx.y * 64;
    __shared__ float At[64][65];
    __shared__ float Vt[64][64];
    int tid = threadIdx.x;
    int tx = tid & 15, ty = tid >> 4;

    float acc[4][4] = {};
    const float* arow = attn + ((size_t)bh * SEQ + i0) * SEQ;

    for (int j0 = 0; j0 < SEQ; j0 += 64) {
        __syncthreads();
        for (int e = tid; e < 4096; e += 256) {
            int r = e >> 6, c = e & 63;
            At[c][r] = arow[(size_t)r * SEQ + j0 + c];
            Vt[r][c] = qkv[(size_t)(b*SEQ + j0 + r) * QKVN + 1536 + h*DHEAD + c];
        }
        __syncthreads();
        #pragma unroll 8
        for (int kk = 0; kk < 64; kk++) {
            float a[4], bb[4];
            #pragma unroll
            for (int ii = 0; ii < 4; ii++) a[ii] = At[kk][(ty<<2) + ii];
            *(float4*)bb = *(const float4*)&Vt[kk][tx<<2];
            #pragma unroll
            for (int ii = 0; ii < 4; ii++)
                #pragma unroll
                for (int jj = 0; jj < 4; jj++)
                    acc[ii][jj] = fmaf(a[ii], bb[jj], acc[ii][jj]);
        }
    }
    #pragma unroll
    for (int ii = 0; ii < 4; ii++)
        #pragma unroll
        for (int jj = 0; jj < 4; jj++)
            ctx[(((size_t)(b*SEQ + i0 + (ty<<2) + ii))*NHEADS + h)*DHEAD + (tx<<2) + jj]
                = __float2half_rn(acc[ii][jj]);
}

// ---------------- launch ----------------
extern "C" void kernel_launch(void* const* d_in, const int* in_sizes, int n_in,
                              void* d_out, int out_size)
{
    const float* hidden  = (const float*)d_in[0];
    const float* bbox    = (const float*)d_in[1];
    const float* fc1_w   = (const float*)d_in[2];
    const float* fc1_b   = (const float*)d_in[3];
    const float* conv_w  = (const float*)d_in[4];
    const float* conv_b  = (const float*)d_in[5];
    const float* fc2_w   = (const float*)d_in[6];
    const float* fc2_b   = (const float*)d_in[7];
    const float* ln_ad_w = (const float*)d_in[8];
    const float* ln_ad_b = (const float*)d_in[9];
    const float* ln1_w   = (const float*)d_in[10];
    const float* q_w     = (const float*)d_in[11];
    const float* k_w     = (const float*)d_in[12];
    const float* v_w     = (const float*)d_in[13];
    const float* o_w     = (const float*)d_in[14];
    const float* rel_b   = (const float*)d_in[15];
    const float* ln2_w   = (const float*)d_in[16];
    const float* wi_w    = (const float*)d_in[17];
    const float* wo_w    = (const float*)d_in[18];
    float* out = (float*)d_out;

    __half *h16, *cv16, *hn16, *ctx16, *ff16;
    __half *wtqkv, *wto, *wtwi, *wtwo, *wtf1, *wtf2;
    float *h1, *ad, *hs, *qkv, *hs2, *attn;
    int* bkt;
    cudaGetSymbolAddress((void**)&h16,  g_h16);
    cudaGetSymbolAddress((void**)&h1,   g_h1);
    cudaGetSymbolAddress((void**)&cv16, g_cv16);
    cudaGetSymbolAddress((void**)&ad,   g_ad);
    cudaGetSymbolAddress((void**)&hs,   g_hs);
    cudaGetSymbolAddress((void**)&hn16, g_hn16);
    cudaGetSymbolAddress((void**)&qkv,  g_qkv);
    cudaGetSymbolAddress((void**)&ctx16,g_ctx16);
    cudaGetSymbolAddress((void**)&hs2,  g_hs2);
    cudaGetSymbolAddress((void**)&attn, g_attn);
    cudaGetSymbolAddress((void**)&ff16, g_ff16);
    cudaGetSymbolAddress((void**)&bkt,  g_bucket);
    cudaGetSymbolAddress((void**)&wtqkv,g_wt_qkv);
    cudaGetSymbolAddress((void**)&wto,  g_wt_o);
    cudaGetSymbolAddress((void**)&wtwi, g_wt_wi);
    cudaGetSymbolAddress((void**)&wtwo, g_wt_wo);
    cudaGetSymbolAddress((void**)&wtf1, g_wt_fc1);
    cudaGetSymbolAddress((void**)&wtf2, g_wt_fc2);

    cudaFuncSetAttribute(hgemm<0>, cudaFuncAttributeMaxDynamicSharedMemorySize, SMEMB);
    cudaFuncSetAttribute(hgemm<1>, cudaFuncAttributeMaxDynamicSharedMemorySize, SMEMB);
    cudaFuncSetAttribute(hgemm<2>, cudaFuncAttributeMaxDynamicSharedMemorySize, SMEMB);
    cudaFuncSetAttribute(hgemm<3>, cudaFuncAttributeMaxDynamicSharedMemorySize, SMEMB);
    cudaFuncSetAttribute(scores_kernel, cudaFuncAttributeMaxDynamicSharedMemorySize, SC_SMEM);

    dim3 tb(32, 8);
    // 0-5: order so ncu (-s 5) captures the fc1 GEMM
    transpose_kernel<<<dim3(ADC/32,    DMODEL/32), tb>>>(fc1_w, wtf1, DMODEL, ADC);          // 0
    round_kernel<<<ROWS*DMODEL/1024, 256>>>(hidden, h16);                                    // 1
    bucket_kernel<<<SEQ, SEQ>>>(bkt);                                                        // 2
    transpose_kernel<<<dim3(DMODEL/32, ADC/32),    tb>>>(fc2_w, wtf2, ADC, DMODEL);          // 3
    transpose_kernel<<<dim3(DMODEL/32, DMODEL/32), tb>>>(q_w, wtqkv, DMODEL, DMODEL);        // 4
    hgemm<1><<<dim3(1, 32), 256, SMEMB>>>(h16, wtf1, h1, ROWS, ADC, DMODEL, fc1_b);          // 5 (profiled)
    conv_kernel<<<ROWS, ADC>>>(h1, conv_w, conv_b, cv16);                                    // 6
    hgemm<1><<<dim3(6, 32), 256, SMEMB>>>(cv16, wtf2, ad, ROWS, DMODEL, ADC, fc2_b);         // 7
    ln_res_kernel<<<ROWS, 256>>>(ad, ln_ad_w, ln_ad_b, hidden, hs);                          // 8
    rms_kernel<<<ROWS, 256>>>(hs, ln1_w, hn16);                                              // 9
    transpose_kernel<<<dim3(DMODEL/32, DMODEL/32), tb>>>(k_w, wtqkv + 768*768, DMODEL, DMODEL);
    transpose_kernel<<<dim3(DMODEL/32, DMODEL/32), tb>>>(v_w, wtqkv + 2*768*768, DMODEL, DMODEL);
    hgemm<0><<<dim3(QKVN/128, 32), 256, SMEMB>>>(hn16, wtqkv, qkv, ROWS, QKVN, DMODEL, nullptr);
    transpose_kernel<<<dim3(DMODEL/32, DMODEL/32), tb>>>(o_w, wto, DMODEL, DMODEL);
    scores_kernel<<<dim3(BATCH, SEQ/4), 256, SC_SMEM>>>(qkv, bbox, rel_b, bkt, attn);
    ctx_kernel<<<dim3(BATCH*NHEADS, SEQ/64), 256>>>(attn, qkv, ctx16);
    hgemm<3><<<dim3(6, 32), 256, SMEMB>>>(ctx16, wto, hs2, ROWS, DMODEL, DMODEL, hs);
    rms_kernel<<<ROWS, 256>>>(hs2, ln2_w, hn16);
    transpose_kernel<<<dim3(DFF/32,    DMODEL/32), tb>>>(wi_w, wtwi, DMODEL, DFF);
    hgemm<2><<<dim3(24, 32), 256, SMEMB>>>(hn16, wtwi, ff16, ROWS, DFF, DMODEL, nullptr);
    transpose_kernel<<<dim3(DMODEL/32, DFF/32),    tb>>>(wo_w, wtwo, DFF, DMODEL);
    hgemm<3><<<dim3(6, 32), 256, SMEMB>>>(ff16, wtwo, out, ROWS, DMODEL, DFF, hs2);
}

// round 6
// speedup vs baseline: 4.7130x; 1.2273x over previous
#include <cuda_runtime.h>
#include <cuda_fp16.h>
#include <math.h>
#include <stdint.h>

// ---------------- problem constants ----------------
#define BATCH   16
#define NFRAMES 8
#define SEQ     256
#define DMODEL  768
#define NHEADS  12
#define DHEAD   64
#define DFF     3072
#define ADC     128
#define ROWS    (BATCH*SEQ) // 4096
#define QKVN    2304

// ---------------- scratch (device globals; no allocations) ----------------
__device__ __align__(16) __half g_h16 [ROWS*DMODEL];
__device__ __align__(16) float  g_h1  [ROWS*ADC];
__device__ __align__(16) __half g_cv16[ROWS*ADC];
__device__ __align__(16) float  g_ad  [ROWS*DMODEL];
__device__ __align__(16) float  g_hs  [ROWS*DMODEL];
__device__ __align__(16) __half g_hn16[ROWS*DMODEL];
__device__ __align__(16) __half g_qkvh[ROWS*QKVN];
__device__ __align__(16) __half g_ctx16[ROWS*DMODEL];
__device__ __align__(16) float  g_hs2 [ROWS*DMODEL];
__device__ __align__(16) float  g_attn[BATCH*NHEADS*SEQ*SEQ];   // raw scores f32
__device__ __align__(16) __half g_attnh[BATCH*NHEADS*SEQ*SEQ];  // probs half
__device__ __align__(16) __half g_ff16[ROWS*DFF];
__device__ int g_bucket[SEQ*SEQ];
// fp16 transposed weights [N][K]
__device__ __align__(16) __half g_wt_qkv[QKVN*DMODEL];
__device__ __align__(16) __half g_wt_o  [DMODEL*DMODEL];
__device__ __align__(16) __half g_wt_wi [DFF*DMODEL];
__device__ __align__(16) __half g_wt_wo [DMODEL*DFF];
__device__ __align__(16) __half g_wt_fc1[ADC*DMODEL];
__device__ __align__(16) __half g_wt_fc2[DMODEL*ADC];

// ================= helpers =================
__device__ __forceinline__ uint32_t smem_u32(const void* p) {
    uint32_t a;
    asm("{ .reg .u64 t; cvta.to.shared.u64 t, %1; cvt.u32.u64 %0, t; }" : "=r"(a) : "l"(p));
    return a;
}
__device__ __forceinline__ void cp16(uint32_t s, const void* g) {
    asm volatile("cp.async.cg.shared.global [%0], [%1], 16;" :: "r"(s), "l"(g));
}
#define CP_COMMIT() asm volatile("cp.async.commit_group;" ::: "memory")
#define CP_WAIT1()  asm volatile("cp.async.wait_group 1;" ::: "memory")

__device__ __forceinline__ void ldsm4(uint32_t* r, uint32_t a) {
    asm volatile("ldmatrix.sync.aligned.m8n8.x4.shared.b16 {%0,%1,%2,%3}, [%4];"
                 : "=r"(r[0]), "=r"(r[1]), "=r"(r[2]), "=r"(r[3]) : "r"(a));
}
__device__ __forceinline__ void mma_f16(float c[4], const uint32_t a[4],
                                        uint32_t b0, uint32_t b1) {
    asm volatile(
        "mma.sync.aligned.m16n8k16.row.col.f32.f16.f16.f32 "
        "{%0,%1,%2,%3}, {%4,%5,%6,%7}, {%8,%9}, {%0,%1,%2,%3};\n"
        : "+f"(c[0]), "+f"(c[1]), "+f"(c[2]), "+f"(c[3])
        : "r"(a[0]), "r"(a[1]), "r"(a[2]), "r"(a[3]), "r"(b0), "r"(b1));
}

// fast exp on FMA pipe
__device__ __forceinline__ float fast_exp(float x) {
    float t = x * 1.4426950408889634f;
    t = fmaxf(t, -126.0f);
    float r = t + 12582912.0f;
    float n = r - 12582912.0f;
    float f = t - n;
    float p = 1.33335581e-3f;
    p = fmaf(p, f, 9.61812910e-3f);
    p = fmaf(p, f, 5.55041087e-2f);
    p = fmaf(p, f, 2.40226507e-1f);
    p = fmaf(p, f, 6.93147182e-1f);
    p = fmaf(p, f, 1.0f);
    int ni = (int)n;
    return p * __int_as_float((ni + 127) << 23);
}

// ================= fp16 mma.sync GEMM =================
// tile 128x128x64 (BK=64 halves=128B rows), 3-stage cp.async, frag double-buffer.
// EPI: 0=none f32, 1=+bias f32, 2=relu->half, 3=+residual f32, 4=plain->half
#define BK 64
#define ABYT (128*128)
#define STG  (2*ABYT)
#define SMEMB (3*STG)

__device__ __forceinline__ void stage_tile(uint32_t sa, const __half* Ag, int lda,
                                           const __half* Bg, int ldb, int tid) {
    #pragma unroll
    for (int p = 0; p < 4; p++) {
        int id = tid + p * 256;
        int row = id >> 3, c = id & 7;
        uint32_t off = (uint32_t)(row * 128 + c * 16);
        off ^= ((off >> 3) & 0x70);
        cp16(sa + off,        Ag + (size_t)row * lda + c * 8);
        cp16(sa + ABYT + off, Bg + (size_t)row * ldb + c * 8);
    }
}

template<int EPI>
__device__ __forceinline__ void hgemm_core(
    const __half* __restrict__ A, int lda,
    const __half* __restrict__ BT, int ldb,
    void* __restrict__ Cv, int ldc, int K, const float* __restrict__ aux)
{
    extern __shared__ __align__(16) char smc[];
    const uint32_t sbase = smem_u32(smc);
    const int tid  = threadIdx.x;
    const int lane = tid & 31;
    const int warp = tid >> 5;
    const int wm = (warp & 1) * 64;
    const int wn = (warp >> 1) * 32;
    const int g = lane >> 2;
    const int t = lane & 3;
    const size_t bm = (size_t)blockIdx.y * 128;
    const size_t bn = (size_t)blockIdx.x * 128;

    const __half* Ab = A  + bm * lda;
    const __half* Bb = BT + bn * ldb;
    const int ktiles = K >> 6;

    const int l16 = lane & 15;
    const uint32_t khb = (uint32_t)((lane >> 4) << 4);
    const uint32_t xr  = (uint32_t)((lane & 7) << 4);

    float acc[4][4][4];
    #pragma unroll
    for (int i = 0; i < 4; i++)
        #pragma unroll
        for (int j = 0; j < 4; j++)
            #pragma unroll
            for (int r = 0; r < 4; r++) acc[i][j][r] = 0.f;

    #pragma unroll
    for (int s = 0; s < 2; s++) {
        if (s < ktiles)
            stage_tile(sbase + s * STG, Ab + s * BK, lda, Bb + s * BK, ldb, tid);
        CP_COMMIT();
    }

    int cs = 0, is_ = 2;
    for (int kt = 0; kt < ktiles; kt++) {
        CP_WAIT1();
        __syncthreads();

        if (kt + 2 < ktiles)
            stage_tile(sbase + is_ * STG, Ab + (kt+2) * BK, lda,
                       Bb + (kt+2) * BK, ldb, tid);
        CP_COMMIT();

        const uint32_t as = sbase + cs * STG;
        const uint32_t abase = as + (uint32_t)((wm + l16) * 128);
        const uint32_t bbase = as + ABYT + (uint32_t)((wn + l16) * 128);

        uint32_t af[2][4][4], bf[2][2][4];
        {   // preload kk=0
            const uint32_t kb = khb;
            #pragma unroll
            for (int im = 0; im < 4; im++)
                ldsm4(af[0][im], abase + im*2048 + (kb ^ xr));
            #pragma unroll
            for (int p = 0; p < 2; p++)
                ldsm4(bf[0][p], bbase + p*2048 + (kb ^ xr));
        }
        #pragma unroll
        for (int kk = 0; kk < 4; kk++) {
            const int cur = kk & 1, nxt = cur ^ 1;
            if (kk < 3) {
                const uint32_t kb = (uint32_t)((kk+1) * 32) + khb;
                #pragma unroll
                for (int im = 0; im < 4; im++)
                    ldsm4(af[nxt][im], abase + im*2048 + (kb ^ xr));
                #pragma unroll
                for (int p = 0; p < 2; p++)
                    ldsm4(bf[nxt][p], bbase + p*2048 + (kb ^ xr));
            }
            #pragma unroll
            for (int im = 0; im < 4; im++)
                #pragma unroll
                for (int j = 0; j < 4; j++)
                    mma_f16(acc[im][j], af[cur][im],
                            bf[cur][j>>1][j&1], bf[cur][j>>1][2+(j&1)]);
        }
        cs = (cs == 2) ? 0 : cs + 1;
        is_ = (is_ == 2) ? 0 : is_ + 1;
        __syncthreads();
    }

    // epilogue
    #pragma unroll
    for (int im = 0; im < 4; im++) {
        #pragma unroll
        for (int half = 0; half < 2; half++) {
            size_t row = bm + wm + im*16 + g + half*8;
            #pragma unroll
            for (int in = 0; in < 4; in++) {
                size_t col = bn + wn + in*8 + 2*t;
                float v0 = acc[im][in][half*2 + 0];
                float v1 = acc[im][in][half*2 + 1];
                if (EPI == 2) {
                    v0 = fmaxf(v0, 0.f); v1 = fmaxf(v1, 0.f);
                    *(__half2*)((__half*)Cv + row*ldc + col) = __floats2half2_rn(v0, v1);
                } else if (EPI == 4) {
                    *(__half2*)((__half*)Cv + row*ldc + col) = __floats2half2_rn(v0, v1);
                } else {
                    if (EPI == 1) { v0 += aux[col]; v1 += aux[col+1]; }
                    else if (EPI == 3) { v0 += aux[row*ldc+col]; v1 += aux[row*ldc+col+1]; }
                    *(float2*)((float*)Cv + row*ldc + col) = make_float2(v0, v1);
                }
            }
        }
    }
}

template<int EPI>
__global__ __launch_bounds__(256, 2) void hgemm(
    const __half* __restrict__ A, const __half* __restrict__ BT, void* __restrict__ C,
    int N, int K, const float* __restrict__ aux)
{
    hgemm_core<EPI>(A, K, BT, K, C, N, K, aux);
}

// batched QK^T: per (b,h) 256x256x64, A/B rows stride QKVN
__global__ __launch_bounds__(256, 2) void qk_gemm(
    const __half* __restrict__ qkvh, float* __restrict__ attn)
{
    const int z = blockIdx.z;           // b*12+h
    const int b = z / NHEADS, h = z % NHEADS;
    const __half* A = qkvh + (size_t)(b*SEQ) * QKVN + h*DHEAD;
    const __half* B = A + DMODEL;
    float* C = attn + (size_t)z * SEQ * SEQ;
    hgemm_core<0>(A, QKVN, B, QKVN, C, SEQ, DHEAD, nullptr);
}

// ---------------- weight transpose + fp16 ----------------
__global__ __launch_bounds__(256) void transpose_kernel(
    const float* __restrict__ in, __half* __restrict__ out, int R, int C)
{
    __shared__ float tsm[32][33];
    int cx = blockIdx.x * 32, ry = blockIdx.y * 32;
    int x = threadIdx.x, y = threadIdx.y;
    #pragma unroll
    for (int i = 0; i < 32; i += 8)
        tsm[y + i][x] = in[(size_t)(ry + y + i) * C + cx + x];
    __syncthreads();
    #pragma unroll
    for (int i = 0; i < 32; i += 8)
        out[(size_t)(cx + y + i) * R + ry + x] = __float2half_rn(tsm[x][y + i]);
}

// ---------------- float -> half copy ----------------
__global__ __launch_bounds__(256) void round_kernel(
    const float* __restrict__ in, __half* __restrict__ out)
{
    size_t i = ((size_t)blockIdx.x * 256 + threadIdx.x) * 4;
    float4 v = *(const float4*)(in + i);
    __half2* o = (__half2*)(out + i);
    o[0] = __floats2half2_rn(v.x, v.y);
    o[1] = __floats2half2_rn(v.z, v.w);
}

// ---------------- relative-position bucket ----------------
__global__ void bucket_kernel(int* __restrict__ bkt) {
    int i = blockIdx.x, j = threadIdx.x;
    int rel = j - i;
    int base = (rel > 0) ? 16 : 0;
    int arel = rel < 0 ? -rel : rel;
    int v;
    if (arel < 8) {
        v = arel;
    } else {
        float t = logf((float)arel / 8.0f) / 2.772588722239781f * 8.0f;
        v = 8 + (int)t;
        if (v > 15) v = 15;
    }
    bkt[i*SEQ + j] = base + v;
}

// ---------------- depthwise 3x3 conv -> half ----------------
__global__ __launch_bounds__(128) void conv_kernel(
    const float* __restrict__ h1, const float* __restrict__ cw,
    const float* __restrict__ cb, __half* __restrict__ out)
{
    int p  = blockIdx.x;
    int l  = p & 255;
    int bn = p >> 8;
    int ni = bn & 7;
    int bi = bn >> 3;
    int c  = threadIdx.x;

    float acc = cb[c];
    #pragma unroll
    for (int dn = -1; dn <= 1; dn++) {
        int nn = ni + dn;
        if (nn < 0 || nn >= NFRAMES) continue;
        #pragma unroll
        for (int dl = -1; dl <= 1; dl++) {
            int ll = l + dl;
            if (ll < 0 || ll >= SEQ) continue;
            float x = h1[(size_t)(((bi*NFRAMES + nn)*SEQ) + ll) * ADC + c];
            acc = fmaf(x, cw[c*9 + (dn+1)*3 + (dl+1)], acc);
        }
    }
    out[(size_t)p * ADC + c] = __float2half_rn(acc);
}

// ---------------- norms ----------------
__device__ __forceinline__ float blk_sum(float v, volatile float* red) {
    int tid = threadIdx.x;
    #pragma unroll
    for (int o = 16; o; o >>= 1) v += __shfl_xor_sync(0xffffffffu, v, o);
    if ((tid & 31) == 0) red[tid >> 5] = v;
    __syncthreads();
    if (tid == 0) {
        float s = 0.f;
        #pragma unroll
        for (int w = 0; w < 8; w++) s += red[w];
        red[8] = s;
    }
    __syncthreads();
    return red[8];
}

__global__ __launch_bounds__(256) void ln_res_kernel(
    const float* __restrict__ x, const float* __restrict__ w,
    const float* __restrict__ bvec, const float* __restrict__ res,
    float* __restrict__ out)
{
    __shared__ float red[9];
    size_t base = (size_t)blockIdx.x * DMODEL;
    int t = threadIdx.x;
    float v0 = x[base+t], v1 = x[base+t+256], v2 = x[base+t+512];
    float mu = blk_sum(v0+v1+v2, red) * (1.f/DMODEL);
    __syncthreads();
    float d0 = v0-mu, d1 = v1-mu, d2 = v2-mu;
    float var = blk_sum(d0*d0 + d1*d1 + d2*d2, red) * (1.f/DMODEL);
    float inv = rsqrtf(var + 1e-5f);
    out[base+t    ] = d0*inv*w[t]     + bvec[t]     + res[base+t];
    out[base+t+256] = d1*inv*w[t+256] + bvec[t+256] + res[base+t+256];
    out[base+t+512] = d2*inv*w[t+512] + bvec[t+512] + res[base+t+512];
}

__global__ __launch_bounds__(256) void rms_kernel(
    const float* __restrict__ x, const float* __restrict__ w, __half* __restrict__ out)
{
    __shared__ float red[9];
    size_t base = (size_t)blockIdx.x * DMODEL;
    int t = threadIdx.x;
    float v0 = x[base+t], v1 = x[base+t+256], v2 = x[base+t+512];
    float ms = blk_sum(v0*v0 + v1*v1 + v2*v2, red) * (1.f/DMODEL);
    float inv = rsqrtf(ms + 1e-6f);
    out[base+t    ] = __float2half_rn(w[t]    *v0*inv);
    out[base+t+256] = __float2half_rn(w[t+256]*v1*inv);
    out[base+t+512] = __float2half_rn(w[t+512]*v2*inv);
}

// ---------------- bbox einsum + bias + softmax (QK already done) ----------------
#define BB_SMEM ((4*DMODEL + 48*SEQ + 384)*4)
__global__ __launch_bounds__(256) void bbox_softmax_kernel(
    const __half* __restrict__ qkvh, const float* __restrict__ bbox,
    const float* __restrict__ rel_bias, const int* __restrict__ bkt,
    const float* __restrict__ scores, __half* __restrict__ attnh)
{
    const int b  = blockIdx.x;
    const int i0 = blockIdx.y * 4;
    extern __shared__ __align__(16) float dsm[];
    float* qs  = dsm;                 // [4][768]
    float* sc  = dsm + 4*DMODEL;      // [48][256]
    float* rbs = sc + 48*SEQ;         // [32][12]
    const int tid = threadIdx.x;

    for (int t = tid; t < 4*DMODEL; t += 256) {
        int r = t / DMODEL, d = t - r*DMODEL;
        qs[t] = __half2float(qkvh[((size_t)(b*SEQ) + i0 + r) * QKVN + d]);
    }
    for (int t = tid; t < 384; t += 256) rbs[t] = rel_bias[t];
    __syncthreads();

    const int j = tid;
    #pragma unroll 1
    for (int i = 0; i < 4; i++) {
        const float4* bb4 = (const float4*)(bbox + (((size_t)(i0+i)*SEQ + j)*BATCH + b)*DHEAD);
        float part[NHEADS];
        #pragma unroll
        for (int h = 0; h < NHEADS; h++) part[h] = 0.f;
        #pragma unroll
        for (int c = 0; c < 16; c++) {
            float4 bv = bb4[c];
            #pragma unroll
            for (int h = 0; h < NHEADS; h++) {
                float4 qv = *(const float4*)&qs[i*DMODEL + h*DHEAD + c*4];
                part[h] = fmaf(qv.x, bv.x, part[h]);
                part[h] = fmaf(qv.y, bv.y, part[h]);
                part[h] = fmaf(qv.z, bv.z, part[h]);
                part[h] = fmaf(qv.w, bv.w, part[h]);
            }
        }
        int bu = bkt[(i0+i)*SEQ + j];
        #pragma unroll
        for (int h = 0; h < NHEADS; h++) {
            float s = scores[(((size_t)(b*NHEADS + h)*SEQ) + i0 + i)*SEQ + j]
                      + part[h] + rbs[bu*NHEADS + h];
            sc[(h*4+i)*SEQ + j] = s * 0.125f;
        }
    }
    __syncthreads();

    const int warp = tid >> 5, lane = tid & 31;
    for (int rr = 0; rr < 6; rr++) {
        int row = warp*6 + rr;
        int h = row >> 2, i = row & 3;
        float* p = sc + row*SEQ;
        float m = -1e30f;
        #pragma unroll
        for (int u = 0; u < 8; u++) m = fmaxf(m, p[lane + u*32]);
        #pragma unroll
        for (int o = 16; o; o >>= 1) m = fmaxf(m, __shfl_xor_sync(0xffffffffu, m, o));
        float e[8], sum = 0.f;
        #pragma unroll
        for (int u = 0; u < 8; u++) { e[u] = fast_exp(p[lane + u*32] - m); sum += e[u]; }
        #pragma unroll
        for (int o = 16; o; o >>= 1) sum += __shfl_xor_sync(0xffffffffu, sum, o);
        float inv = 1.f / sum;
        __half* o = attnh + (((size_t)(b*NHEADS + h)*SEQ) + i0 + i)*SEQ;
        #pragma unroll
        for (int u = 0; u < 8; u++) o[lane + u*32] = __float2half_rn(e[u] * inv);
    }
}

// ---------------- ctx = attn @ V -> half (b, l, h, d) ----------------
__global__ __launch_bounds__(256) void ctx_kernel(
    const __half* __restrict__ attnh, const __half* __restrict__ qkvh,
    __half* __restrict__ ctx)
{
    int bh = blockIdx.x;
    int b = bh / NHEADS, h = bh % NHEADS;
    int i0 = blockIdx.y * 64;
    __shared__ float At[64][65];
    __shared__ float Vt[64][64];
    int tid = threadIdx.x;
    int tx = tid & 15, ty = tid >> 4;

    float acc[4][4] = {};
    const __half* arow = attnh + ((size_t)bh * SEQ + i0) * SEQ;

    for (int j0 = 0; j0 < SEQ; j0 += 64) {
        __syncthreads();
        for (int e = tid; e < 4096; e += 256) {
            int r = e >> 6, c = e & 63;
            At[c][r] = __half2float(arow[(size_t)r * SEQ + j0 + c]);
            Vt[r][c] = __half2float(qkvh[(size_t)(b*SEQ + j0 + r) * QKVN + 1536 + h*DHEAD + c]);
        }
        __syncthreads();
        #pragma unroll 8
        for (int kk = 0; kk < 64; kk++) {
            float a[4], bb[4];
            #pragma unroll
            for (int ii = 0; ii < 4; ii++) a[ii] = At[kk][(ty<<2) + ii];
            *(float4*)bb = *(const float4*)&Vt[kk][tx<<2];
            #pragma unroll
            for (int ii = 0; ii < 4; ii++)
                #pragma unroll
                for (int jj = 0; jj < 4; jj++)
                    acc[ii][jj] = fmaf(a[ii], bb[jj], acc[ii][jj]);
        }
    }
    #pragma unroll
    for (int ii = 0; ii < 4; ii++)
        #pragma unroll
        for (int jj = 0; jj < 4; jj++)
            ctx[(((size_t)(b*SEQ + i0 + (ty<<2) + ii))*NHEADS + h)*DHEAD + (tx<<2) + jj]
                = __float2half_rn(acc[ii][jj]);
}

// ---------------- launch ----------------
extern "C" void kernel_launch(void* const* d_in, const int* in_sizes, int n_in,
                              void* d_out, int out_size)
{
    const float* hidden  = (const float*)d_in[0];
    const float* bbox    = (const float*)d_in[1];
    const float* fc1_w   = (const float*)d_in[2];
    const float* fc1_b   = (const float*)d_in[3];
    const float* conv_w  = (const float*)d_in[4];
    const float* conv_b  = (const float*)d_in[5];
    const float* fc2_w   = (const float*)d_in[6];
    const float* fc2_b   = (const float*)d_in[7];
    const float* ln_ad_w = (const float*)d_in[8];
    const float* ln_ad_b = (const float*)d_in[9];
    const float* ln1_w   = (const float*)d_in[10];
    const float* q_w     = (const float*)d_in[11];
    const float* k_w     = (const float*)d_in[12];
    const float* v_w     = (const float*)d_in[13];
    const float* o_w     = (const float*)d_in[14];
    const float* rel_b   = (const float*)d_in[15];
    const float* ln2_w   = (const float*)d_in[16];
    const float* wi_w    = (const float*)d_in[17];
    const float* wo_w    = (const float*)d_in[18];
    float* out = (float*)d_out;

    __half *h16, *cv16, *hn16, *qkvh, *ctx16, *ff16, *attnh;
    __half *wtqkv, *wto, *wtwi, *wtwo, *wtf1, *wtf2;
    float *h1, *ad, *hs, *hs2, *attn;
    int* bkt;
    cudaGetSymbolAddress((void**)&h16,  g_h16);
    cudaGetSymbolAddress((void**)&h1,   g_h1);
    cudaGetSymbolAddress((void**)&cv16, g_cv16);
    cudaGetSymbolAddress((void**)&ad,   g_ad);
    cudaGetSymbolAddress((void**)&hs,   g_hs);
    cudaGetSymbolAddress((void**)&hn16, g_hn16);
    cudaGetSymbolAddress((void**)&qkvh, g_qkvh);
    cudaGetSymbolAddress((void**)&ctx16,g_ctx16);
    cudaGetSymbolAddress((void**)&hs2,  g_hs2);
    cudaGetSymbolAddress((void**)&attn, g_attn);
    cudaGetSymbolAddress((void**)&attnh,g_attnh);
    cudaGetSymbolAddress((void**)&ff16, g_ff16);
    cudaGetSymbolAddress((void**)&bkt,  g_bucket);
    cudaGetSymbolAddress((void**)&wtqkv,g_wt_qkv);
    cudaGetSymbolAddress((void**)&wto,  g_wt_o);
    cudaGetSymbolAddress((void**)&wtwi, g_wt_wi);
    cudaGetSymbolAddress((void**)&wtwo, g_wt_wo);
    cudaGetSymbolAddress((void**)&wtf1, g_wt_fc1);
    cudaGetSymbolAddress((void**)&wtf2, g_wt_fc2);

    cudaFuncSetAttribute(hgemm<0>, cudaFuncAttributeMaxDynamicSharedMemorySize, SMEMB);
    cudaFuncSetAttribute(hgemm<1>, cudaFuncAttributeMaxDynamicSharedMemorySize, SMEMB);
    cudaFuncSetAttribute(hgemm<2>, cudaFuncAttributeMaxDynamicSharedMemorySize, SMEMB);
    cudaFuncSetAttribute(hgemm<3>, cudaFuncAttributeMaxDynamicSharedMemorySize, SMEMB);
    cudaFuncSetAttribute(hgemm<4>, cudaFuncAttributeMaxDynamicSharedMemorySize, SMEMB);
    cudaFuncSetAttribute(qk_gemm,  cudaFuncAttributeMaxDynamicSharedMemorySize, SMEMB);
    cudaFuncSetAttribute(bbox_softmax_kernel, cudaFuncAttributeMaxDynamicSharedMemorySize, BB_SMEM);

    dim3 tb(32, 8);
    // launches 0..3 arranged so the profiler window lands on an hgemm
    transpose_kernel<<<dim3(ADC/32, DMODEL/32), tb>>>(fc1_w, wtf1, DMODEL, ADC);         // 0
    round_kernel<<<ROWS*DMODEL/1024, 256>>>(hidden, h16);                                // 1
    hgemm<1><<<dim3(1, 32), 256, SMEMB>>>(h16, wtf1, h1, ADC, DMODEL, fc1_b);            // 2
    hgemm<1><<<dim3(1, 32), 256, SMEMB>>>(h16, wtf1, h1, ADC, DMODEL, fc1_b);            // 3 (dup for profiler)
    bucket_kernel<<<SEQ, SEQ>>>(bkt);                                                    // 4
    conv_kernel<<<ROWS, ADC>>>(h1, conv_w, conv_b, cv16);                                // 5
    transpose_kernel<<<dim3(DMODEL/32, ADC/32), tb>>>(fc2_w, wtf2, ADC, DMODEL);         // 6
    hgemm<1><<<dim3(6, 32), 256, SMEMB>>>(cv16, wtf2, ad, DMODEL, ADC, fc2_b);           // 7
    ln_res_kernel<<<ROWS, 256>>>(ad, ln_ad_w, ln_ad_b, hidden, hs);                      // 8
    rms_kernel<<<ROWS, 256>>>(hs, ln1_w, hn16);                                          // 9
    transpose_kernel<<<dim3(DMODEL/32, DMODEL/32), tb>>>(q_w, wtqkv, DMODEL, DMODEL);
    transpose_kernel<<<dim3(DMODEL/32, DMODEL/32), tb>>>(k_w, wtqkv + 768*768, DMODEL, DMODEL);
    transpose_kernel<<<dim3(DMODEL/32, DMODEL/32), tb>>>(v_w, wtqkv + 2*768*768, DMODEL, DMODEL);
    hgemm<4><<<dim3(QKVN/128, 32), 256, SMEMB>>>(hn16, wtqkv, qkvh, QKVN, DMODEL, nullptr);
    qk_gemm<<<dim3(2, 2, BATCH*NHEADS), 256, SMEMB>>>(qkvh, attn);
    transpose_kernel<<<dim3(DMODEL/32, DMODEL/32), tb>>>(o_w, wto, DMODEL, DMODEL);
    bbox_softmax_kernel<<<dim3(BATCH, SEQ/4), 256, BB_SMEM>>>(qkvh, bbox, rel_b, bkt, attn, attnh);
    ctx_kernel<<<dim3(BATCH*NHEADS, SEQ/64), 256>>>(attnh, qkvh, ctx16);
    hgemm<3><<<dim3(6, 32), 256, SMEMB>>>(ctx16, wto, hs2, DMODEL, DMODEL, hs);
    rms_kernel<<<ROWS, 256>>>(hs2, ln2_w, hn16);
    transpose_kernel<<<dim3(DFF/32, DMODEL/32), tb>>>(wi_w, wtwi, DMODEL, DFF);
    hgemm<2><<<dim3(24, 32), 256, SMEMB>>>(hn16, wtwi, ff16, DFF, DMODEL, nullptr);
    transpose_kernel<<<dim3(DMODEL/32, DFF/32), tb>>>(wo_w, wtwo, DFF, DMODEL);
    hgemm<3><<<dim3(6, 32), 256, SMEMB>>>(ff16, wtwo, out, DMODEL, DFF, hs2);
}

// round 7
// speedup vs baseline: 5.6155x; 1.1915x over previous
#include <cuda_runtime.h>
#include <cuda_fp16.h>
#include <math.h>
#include <stdint.h>

// ---------------- problem constants ----------------
#define BATCH   16
#define NFRAMES 8
#define SEQ     256
#define DMODEL  768
#define NHEADS  12
#define DHEAD   64
#define DFF     3072
#define ADC     128
#define ROWS    (BATCH*SEQ) // 4096
#define QKVN    2304

// ---------------- scratch (device globals; no allocations) ----------------
__device__ __align__(16) __half g_h16 [ROWS*DMODEL];
__device__ __align__(16) float  g_h1  [ROWS*ADC];
__device__ __align__(16) __half g_cv16[ROWS*ADC];
__device__ __align__(16) float  g_ad  [ROWS*DMODEL];
__device__ __align__(16) float  g_hs  [ROWS*DMODEL];
__device__ __align__(16) __half g_hn16[ROWS*DMODEL];
__device__ __align__(16) __half g_qkvh[ROWS*QKVN];
__device__ __align__(16) __half g_ctx16[ROWS*DMODEL];
__device__ __align__(16) float  g_hs2 [ROWS*DMODEL];
__device__ __align__(16) __half g_scoresh[BATCH*NHEADS*SEQ*SEQ]; // raw QK^T half
__device__ __align__(16) __half g_attnh [BATCH*NHEADS*SEQ*SEQ];  // probs half
__device__ __align__(16) __half g_ff16[ROWS*DFF];
__device__ int g_bucket[SEQ*SEQ];
// fp16 transposed weights [N][K]
__device__ __align__(16) __half g_wt_qkv[QKVN*DMODEL];
__device__ __align__(16) __half g_wt_o  [DMODEL*DMODEL];
__device__ __align__(16) __half g_wt_wi [DFF*DMODEL];
__device__ __align__(16) __half g_wt_wo [DMODEL*DFF];
__device__ __align__(16) __half g_wt_fc1[ADC*DMODEL];
__device__ __align__(16) __half g_wt_fc2[DMODEL*ADC];

// ================= helpers =================
__device__ __forceinline__ uint32_t smem_u32(const void* p) {
    uint32_t a;
    asm("{ .reg .u64 t; cvta.to.shared.u64 t, %1; cvt.u32.u64 %0, t; }" : "=r"(a) : "l"(p));
    return a;
}
__device__ __forceinline__ void cp16(uint32_t s, const void* g) {
    asm volatile("cp.async.cg.shared.global [%0], [%1], 16;" :: "r"(s), "l"(g));
}
#define CP_COMMIT() asm volatile("cp.async.commit_group;" ::: "memory")
#define CP_WAIT1()  asm volatile("cp.async.wait_group 1;" ::: "memory")

__device__ __forceinline__ void ldsm4(uint32_t* r, uint32_t a) {
    asm volatile("ldmatrix.sync.aligned.m8n8.x4.shared.b16 {%0,%1,%2,%3}, [%4];"
                 : "=r"(r[0]), "=r"(r[1]), "=r"(r[2]), "=r"(r[3]) : "r"(a));
}
__device__ __forceinline__ void ldsm4t(uint32_t* r, uint32_t a) {
    asm volatile("ldmatrix.sync.aligned.m8n8.x4.trans.shared.b16 {%0,%1,%2,%3}, [%4];"
                 : "=r"(r[0]), "=r"(r[1]), "=r"(r[2]), "=r"(r[3]) : "r"(a));
}
__device__ __forceinline__ void mma_f16(float c[4], const uint32_t a[4],
                                        uint32_t b0, uint32_t b1) {
    asm volatile(
        "mma.sync.aligned.m16n8k16.row.col.f32.f16.f16.f32 "
        "{%0,%1,%2,%3}, {%4,%5,%6,%7}, {%8,%9}, {%0,%1,%2,%3};\n"
        : "+f"(c[0]), "+f"(c[1]), "+f"(c[2]), "+f"(c[3])
        : "r"(a[0]), "r"(a[1]), "r"(a[2]), "r"(a[3]), "r"(b0), "r"(b1));
}

// fast exp on FMA pipe
__device__ __forceinline__ float fast_exp(float x) {
    float t = x * 1.4426950408889634f;
    t = fmaxf(t, -126.0f);
    float r = t + 12582912.0f;
    float n = r - 12582912.0f;
    float f = t - n;
    float p = 1.33335581e-3f;
    p = fmaf(p, f, 9.61812910e-3f);
    p = fmaf(p, f, 5.55041087e-2f);
    p = fmaf(p, f, 2.40226507e-1f);
    p = fmaf(p, f, 6.93147182e-1f);
    p = fmaf(p, f, 1.0f);
    int ni = (int)n;
    return p * __int_as_float((ni + 127) << 23);
}

// ================= fp16 mma.sync GEMM =================
// tile 128x128x64, 3-stage cp.async, frag double-buffer.
// EPI: 1=+bias f32, 2=relu->half, 3=+residual f32, 4=plain->half
#define BK 64
#define ABYT (128*128)
#define STG  (2*ABYT)
#define SMEMB (3*STG)

__device__ __forceinline__ void stage_tile(uint32_t sa, const __half* Ag, int lda,
                                           const __half* Bg, int ldb, int tid) {
    #pragma unroll
    for (int p = 0; p < 4; p++) {
        int id = tid + p * 256;
        int row = id >> 3, c = id & 7;
        uint32_t off = (uint32_t)(row * 128 + c * 16);
        off ^= ((off >> 3) & 0x70);
        cp16(sa + off,        Ag + (size_t)row * lda + c * 8);
        cp16(sa + ABYT + off, Bg + (size_t)row * ldb + c * 8);
    }
}

template<int EPI>
__device__ __forceinline__ void hgemm_core(
    const __half* __restrict__ A, int lda,
    const __half* __restrict__ BT, int ldb,
    void* __restrict__ Cv, int ldc, int K, const float* __restrict__ aux)
{
    extern __shared__ __align__(16) char smc[];
    const uint32_t sbase = smem_u32(smc);
    const int tid  = threadIdx.x;
    const int lane = tid & 31;
    const int warp = tid >> 5;
    const int wm = (warp & 1) * 64;
    const int wn = (warp >> 1) * 32;
    const int g = lane >> 2;
    const int t = lane & 3;
    const size_t bm = (size_t)blockIdx.y * 128;
    const size_t bn = (size_t)blockIdx.x * 128;

    const __half* Ab = A  + bm * lda;
    const __half* Bb = BT + bn * ldb;
    const int ktiles = K >> 6;

    const int l16 = lane & 15;
    const uint32_t khb = (uint32_t)((lane >> 4) << 4);
    const uint32_t xr  = (uint32_t)((lane & 7) << 4);

    float acc[4][4][4];
    #pragma unroll
    for (int i = 0; i < 4; i++)
        #pragma unroll
        for (int j = 0; j < 4; j++)
            #pragma unroll
            for (int r = 0; r < 4; r++) acc[i][j][r] = 0.f;

    #pragma unroll
    for (int s = 0; s < 2; s++) {
        if (s < ktiles)
            stage_tile(sbase + s * STG, Ab + s * BK, lda, Bb + s * BK, ldb, tid);
        CP_COMMIT();
    }

    int cs = 0, is_ = 2;
    for (int kt = 0; kt < ktiles; kt++) {
        CP_WAIT1();
        __syncthreads();

        if (kt + 2 < ktiles)
            stage_tile(sbase + is_ * STG, Ab + (kt+2) * BK, lda,
                       Bb + (kt+2) * BK, ldb, tid);
        CP_COMMIT();

        const uint32_t as = sbase + cs * STG;
        const uint32_t abase = as + (uint32_t)((wm + l16) * 128);
        const uint32_t bbase = as + ABYT + (uint32_t)((wn + l16) * 128);

        uint32_t af[2][4][4], bf[2][2][4];
        {
            const uint32_t kb = khb;
            #pragma unroll
            for (int im = 0; im < 4; im++)
                ldsm4(af[0][im], abase + im*2048 + (kb ^ xr));
            #pragma unroll
            for (int p = 0; p < 2; p++)
                ldsm4(bf[0][p], bbase + p*2048 + (kb ^ xr));
        }
        #pragma unroll
        for (int kk = 0; kk < 4; kk++) {
            const int cur = kk & 1, nxt = cur ^ 1;
            if (kk < 3) {
                const uint32_t kb = (uint32_t)((kk+1) * 32) + khb;
                #pragma unroll
                for (int im = 0; im < 4; im++)
                    ldsm4(af[nxt][im], abase + im*2048 + (kb ^ xr));
                #pragma unroll
                for (int p = 0; p < 2; p++)
                    ldsm4(bf[nxt][p], bbase + p*2048 + (kb ^ xr));
            }
            #pragma unroll
            for (int im = 0; im < 4; im++)
                #pragma unroll
                for (int j = 0; j < 4; j++)
                    mma_f16(acc[im][j], af[cur][im],
                            bf[cur][j>>1][j&1], bf[cur][j>>1][2+(j&1)]);
        }
        cs = (cs == 2) ? 0 : cs + 1;
        is_ = (is_ == 2) ? 0 : is_ + 1;
        __syncthreads();
    }

    #pragma unroll
    for (int im = 0; im < 4; im++) {
        #pragma unroll
        for (int half = 0; half < 2; half++) {
            size_t row = bm + wm + im*16 + g + half*8;
            #pragma unroll
            for (int in = 0; in < 4; in++) {
                size_t col = bn + wn + in*8 + 2*t;
                float v0 = acc[im][in][half*2 + 0];
                float v1 = acc[im][in][half*2 + 1];
                if (EPI == 2) {
                    v0 = fmaxf(v0, 0.f); v1 = fmaxf(v1, 0.f);
                    *(__half2*)((__half*)Cv + row*ldc + col) = __floats2half2_rn(v0, v1);
                } else if (EPI == 4) {
                    *(__half2*)((__half*)Cv + row*ldc + col) = __floats2half2_rn(v0, v1);
                } else {
                    if (EPI == 1) { v0 += aux[col]; v1 += aux[col+1]; }
                    else if (EPI == 3) { v0 += aux[row*ldc+col]; v1 += aux[row*ldc+col+1]; }
                    *(float2*)((float*)Cv + row*ldc + col) = make_float2(v0, v1);
                }
            }
        }
    }
}

template<int EPI>
__global__ __launch_bounds__(256, 2) void hgemm(
    const __half* __restrict__ A, const __half* __restrict__ BT, void* __restrict__ C,
    int N, int K, const float* __restrict__ aux)
{
    hgemm_core<EPI>(A, K, BT, K, C, N, K, aux);
}

// batched QK^T: per (b,h) 256x256x64 -> half scores
__global__ __launch_bounds__(256, 2) void qk_gemm(
    const __half* __restrict__ qkvh, __half* __restrict__ scoresh)
{
    const int z = blockIdx.z;
    const int b = z / NHEADS;
    const __half* A = qkvh + (size_t)(b*SEQ) * QKVN + (z % NHEADS)*DHEAD;
    const __half* B = A + DMODEL;
    __half* C = scoresh + (size_t)z * SEQ * SEQ;
    hgemm_core<4>(A, QKVN, B, QKVN, C, SEQ, DHEAD, nullptr);
}

// ================= AV tensor GEMM: ctx = probs @ V =================
// per (b,h): 128x64 tile, K=256 (4 kt of 64). A regular ldsm, V via ldsm.trans.
#define AV_A 16384
#define AVSTG 24576
#define AVSMEM (3*AVSTG)

__device__ __forceinline__ void av_stage(uint32_t sa, const __half* Ag,
                                         const __half* Vg, int tid) {
    #pragma unroll
    for (int p = 0; p < 4; p++) {
        int id = tid + p * 256;
        int row = id >> 3, c = id & 7;
        uint32_t off = (uint32_t)(row * 128 + c * 16);
        off ^= ((off >> 3) & 0x70);
        cp16(sa + off, Ag + (size_t)row * SEQ + c * 8);
    }
    #pragma unroll
    for (int p = 0; p < 2; p++) {
        int id = tid + p * 256;
        int row = id >> 3, c = id & 7;
        uint32_t off = (uint32_t)(row * 128 + c * 16);
        off ^= ((off >> 3) & 0x70);
        cp16(sa + AV_A + off, Vg + (size_t)row * QKVN + c * 8);
    }
}

__global__ __launch_bounds__(256, 2) void av_gemm(
    const __half* __restrict__ attnh, const __half* __restrict__ qkvh,
    __half* __restrict__ ctx)
{
    extern __shared__ __align__(16) char smc[];
    const uint32_t sbase = smem_u32(smc);
    const int tid  = threadIdx.x;
    const int lane = tid & 31;
    const int warp = tid >> 5;
    const int wm = (warp & 1) * 64;
    const int wn = (warp >> 1) * 16;
    const int z = blockIdx.y;
    const int b = z / NHEADS, h = z % NHEADS;
    const int bm = blockIdx.x * 128;

    const __half* Ab = attnh + ((size_t)z * SEQ + bm) * SEQ;
    const __half* Vb = qkvh + (size_t)(b*SEQ) * QKVN + 1536 + h*DHEAD;

    const int l16 = lane & 15;
    const uint32_t khb = (uint32_t)((lane >> 4) << 4);
    const uint32_t xr  = (uint32_t)((lane & 7) << 4);
    const int vrow = ((lane >> 3) & 1) * 8 + (lane & 7);
    const uint32_t vcolb = (uint32_t)(wn*2 + ((lane >> 4) << 4));

    float acc[4][2][4];
    #pragma unroll
    for (int i = 0; i < 4; i++)
        #pragma unroll
        for (int j = 0; j < 2; j++)
            #pragma unroll
            for (int r = 0; r < 4; r++) acc[i][j][r] = 0.f;

    #pragma unroll
    for (int s = 0; s < 2; s++) {
        av_stage(sbase + s * AVSTG, Ab + s * 64, Vb + (size_t)s * 64 * QKVN, tid);
        CP_COMMIT();
    }

    int cs = 0, is_ = 2;
    for (int kt = 0; kt < 4; kt++) {
        CP_WAIT1();
        __syncthreads();
        if (kt + 2 < 4)
            av_stage(sbase + is_ * AVSTG, Ab + (kt+2) * 64,
                     Vb + (size_t)(kt+2) * 64 * QKVN, tid);
        CP_COMMIT();

        const uint32_t as = sbase + cs * AVSTG;
        const uint32_t vs = as + AV_A;
        const uint32_t abase = as + (uint32_t)((wm + l16) * 128);
        #pragma unroll
        for (int kk = 0; kk < 4; kk++) {
            const uint32_t kb = (uint32_t)(kk * 32) + khb;
            uint32_t af[4][4], bv[4];
            #pragma unroll
            for (int im = 0; im < 4; im++)
                ldsm4(af[im], abase + im*2048 + (kb ^ xr));
            ldsm4t(bv, vs + (uint32_t)((kk*16 + vrow) * 128) + (vcolb ^ xr));
            #pragma unroll
            for (int im = 0; im < 4; im++) {
                mma_f16(acc[im][0], af[im], bv[0], bv[1]);
                mma_f16(acc[im][1], af[im], bv[2], bv[3]);
            }
        }
        cs = (cs == 2) ? 0 : cs + 1;
        is_ = (is_ == 2) ? 0 : is_ + 1;
        __syncthreads();
    }

    const int g = lane >> 2, t = lane & 3;
    #pragma unroll
    for (int im = 0; im < 4; im++) {
        #pragma unroll
        for (int half = 0; half < 2; half++) {
            int row = bm + wm + im*16 + g + half*8;
            #pragma unroll
            for (int jn = 0; jn < 2; jn++) {
                int col = wn + jn*8 + 2*t;
                *(__half2*)(ctx + ((size_t)(b*SEQ + row))*DMODEL + h*DHEAD + col)
                    = __floats2half2_rn(acc[im][jn][half*2], acc[im][jn][half*2+1]);
            }
        }
    }
}

// ---------------- weight transposes ----------------
__global__ __launch_bounds__(256) void transpose_kernel(
    const float* __restrict__ in, __half* __restrict__ out, int R, int C)
{
    __shared__ float tsm[32][33];
    int cx = blockIdx.x * 32, ry = blockIdx.y * 32;
    int x = threadIdx.x, y = threadIdx.y;
    #pragma unroll
    for (int i = 0; i < 32; i += 8)
        tsm[y + i][x] = in[(size_t)(ry + y + i) * C + cx + x];
    __syncthreads();
    #pragma unroll
    for (int i = 0; i < 32; i += 8)
        out[(size_t)(cx + y + i) * R + ry + x] = __float2half_rn(tsm[x][y + i]);
}

__global__ __launch_bounds__(256) void transpose3_kernel(
    const float* __restrict__ in0, const float* __restrict__ in1,
    const float* __restrict__ in2, __half* __restrict__ out)
{
    const float* in = (blockIdx.z == 0) ? in0 : ((blockIdx.z == 1) ? in1 : in2);
    __half* o = out + (size_t)blockIdx.z * DMODEL * DMODEL;
    __shared__ float tsm[32][33];
    int cx = blockIdx.x * 32, ry = blockIdx.y * 32;
    int x = threadIdx.x, y = threadIdx.y;
    #pragma unroll
    for (int i = 0; i < 32; i += 8)
        tsm[y + i][x] = in[(size_t)(ry + y + i) * DMODEL + cx + x];
    __syncthreads();
    #pragma unroll
    for (int i = 0; i < 32; i += 8)
        o[(size_t)(cx + y + i) * DMODEL + ry + x] = __float2half_rn(tsm[x][y + i]);
}

// ---------------- float -> half copy ----------------
__global__ __launch_bounds__(256) void round_kernel(
    const float* __restrict__ in, __half* __restrict__ out)
{
    size_t i = ((size_t)blockIdx.x * 256 + threadIdx.x) * 4;
    float4 v = *(const float4*)(in + i);
    __half2* o = (__half2*)(out + i);
    o[0] = __floats2half2_rn(v.x, v.y);
    o[1] = __floats2half2_rn(v.z, v.w);
}

// ---------------- relative-position bucket ----------------
__global__ void bucket_kernel(int* __restrict__ bkt) {
    int i = blockIdx.x, j = threadIdx.x;
    int rel = j - i;
    int base = (rel > 0) ? 16 : 0;
    int arel = rel < 0 ? -rel : rel;
    int v;
    if (arel < 8) {
        v = arel;
    } else {
        float t = logf((float)arel / 8.0f) / 2.772588722239781f * 8.0f;
        v = 8 + (int)t;
        if (v > 15) v = 15;
    }
    bkt[i*SEQ + j] = base + v;
}

// ---------------- depthwise 3x3 conv -> half ----------------
__global__ __launch_bounds__(128) void conv_kernel(
    const float* __restrict__ h1, const float* __restrict__ cw,
    const float* __restrict__ cb, __half* __restrict__ out)
{
    int p  = blockIdx.x;
    int l  = p & 255;
    int bn = p >> 8;
    int ni = bn & 7;
    int bi = bn >> 3;
    int c  = threadIdx.x;

    float acc = cb[c];
    #pragma unroll
    for (int dn = -1; dn <= 1; dn++) {
        int nn = ni + dn;
        if (nn < 0 || nn >= NFRAMES) continue;
        #pragma unroll
        for (int dl = -1; dl <= 1; dl++) {
            int ll = l + dl;
            if (ll < 0 || ll >= SEQ) continue;
            float x = h1[(size_t)(((bi*NFRAMES + nn)*SEQ) + ll) * ADC + c];
            acc = fmaf(x, cw[c*9 + (dn+1)*3 + (dl+1)], acc);
        }
    }
    out[(size_t)p * ADC + c] = __float2half_rn(acc);
}

// ---------------- norms ----------------
__device__ __forceinline__ float blk_sum(float v, volatile float* red) {
    int tid = threadIdx.x;
    #pragma unroll
    for (int o = 16; o; o >>= 1) v += __shfl_xor_sync(0xffffffffu, v, o);
    if ((tid & 31) == 0) red[tid >> 5] = v;
    __syncthreads();
    if (tid == 0) {
        float s = 0.f;
        #pragma unroll
        for (int w = 0; w < 8; w++) s += red[w];
        red[8] = s;
    }
    __syncthreads();
    return red[8];
}

// fused adapter LayerNorm (+bias +residual) -> hs, then RMSNorm -> hn16
__global__ __launch_bounds__(256) void ln_res_rms_kernel(
    const float* __restrict__ x, const float* __restrict__ w,
    const float* __restrict__ bvec, const float* __restrict__ res,
    const float* __restrict__ w1,
    float* __restrict__ hs, __half* __restrict__ hn16)
{
    __shared__ float red[9];
    size_t base = (size_t)blockIdx.x * DMODEL;
    int t = threadIdx.x;
    float v0 = x[base+t], v1 = x[base+t+256], v2 = x[base+t+512];
    float mu = blk_sum(v0+v1+v2, red) * (1.f/DMODEL);
    __syncthreads();
    float d0 = v0-mu, d1 = v1-mu, d2 = v2-mu;
    float var = blk_sum(d0*d0 + d1*d1 + d2*d2, red) * (1.f/DMODEL);
    float inv = rsqrtf(var + 1e-5f);
    float o0 = d0*inv*w[t]     + bvec[t]     + res[base+t];
    float o1 = d1*inv*w[t+256] + bvec[t+256] + res[base+t+256];
    float o2 = d2*inv*w[t+512] + bvec[t+512] + res[base+t+512];
    hs[base+t    ] = o0;
    hs[base+t+256] = o1;
    hs[base+t+512] = o2;
    __syncthreads();
    float ms = blk_sum(o0*o0 + o1*o1 + o2*o2, red) * (1.f/DMODEL);
    float rinv = rsqrtf(ms + 1e-6f);
    hn16[base+t    ] = __float2half_rn(w1[t]    *o0*rinv);
    hn16[base+t+256] = __float2half_rn(w1[t+256]*o1*rinv);
    hn16[base+t+512] = __float2half_rn(w1[t+512]*o2*rinv);
}

__global__ __launch_bounds__(256) void rms_kernel(
    const float* __restrict__ x, const float* __restrict__ w, __half* __restrict__ out)
{
    __shared__ float red[9];
    size_t base = (size_t)blockIdx.x * DMODEL;
    int t = threadIdx.x;
    float v0 = x[base+t], v1 = x[base+t+256], v2 = x[base+t+512];
    float ms = blk_sum(v0*v0 + v1*v1 + v2*v2, red) * (1.f/DMODEL);
    float inv = rsqrtf(ms + 1e-6f);
    out[base+t    ] = __float2half_rn(w[t]    *v0*inv);
    out[base+t+256] = __float2half_rn(w[t+256]*v1*inv);
    out[base+t+512] = __float2half_rn(w[t+512]*v2*inv);
}

// ---------------- bbox einsum + bias + softmax ----------------
#define BB_SMEM ((4*DMODEL + 48*SEQ + 384)*4)
__global__ __launch_bounds__(256) void bbox_softmax_kernel(
    const __half* __restrict__ qkvh, const float* __restrict__ bbox,
    const float* __restrict__ rel_bias, const int* __restrict__ bkt,
    const __half* __restrict__ scoresh, __half* __restrict__ attnh)
{
    const int b  = blockIdx.x;
    const int i0 = blockIdx.y * 4;
    extern __shared__ __align__(16) float dsm[];
    float* qs  = dsm;
    float* sc  = dsm + 4*DMODEL;
    float* rbs = sc + 48*SEQ;
    const int tid = threadIdx.x;

    for (int t = tid; t < 4*DMODEL; t += 256) {
        int r = t / DMODEL, d = t - r*DMODEL;
        qs[t] = __half2float(qkvh[((size_t)(b*SEQ) + i0 + r) * QKVN + d]);
    }
    for (int t = tid; t < 384; t += 256) rbs[t] = rel_bias[t];
    __syncthreads();

    const int j = tid;
    #pragma unroll 1
    for (int i = 0; i < 4; i++) {
        const float4* bb4 = (const float4*)(bbox + (((size_t)(i0+i)*SEQ + j)*BATCH + b)*DHEAD);
        float part[NHEADS];
        #pragma unroll
        for (int h = 0; h < NHEADS; h++) part[h] = 0.f;
        #pragma unroll
        for (int c = 0; c < 16; c++) {
            float4 bv = bb4[c];
            #pragma unroll
            for (int h = 0; h < NHEADS; h++) {
                float4 qv = *(const float4*)&qs[i*DMODEL + h*DHEAD + c*4];
                part[h] = fmaf(qv.x, bv.x, part[h]);
                part[h] = fmaf(qv.y, bv.y, part[h]);
                part[h] = fmaf(qv.z, bv.z, part[h]);
                part[h] = fmaf(qv.w, bv.w, part[h]);
            }
        }
        int bu = bkt[(i0+i)*SEQ + j];
        #pragma unroll
        for (int h = 0; h < NHEADS; h++) {
            float s = __half2float(scoresh[(((size_t)(b*NHEADS + h)*SEQ) + i0 + i)*SEQ + j])
                      + part[h] + rbs[bu*NHEADS + h];
            sc[(h*4+i)*SEQ + j] = s * 0.125f;
        }
    }
    __syncthreads();

    const int warp = tid >> 5, lane = tid & 31;
    for (int rr = 0; rr < 6; rr++) {
        int row = warp*6 + rr;
        int h = row >> 2, i = row & 3;
        float* p = sc + row*SEQ;
        float m = -1e30f;
        #pragma unroll
        for (int u = 0; u < 8; u++) m = fmaxf(m, p[lane + u*32]);
        #pragma unroll
        for (int o = 16; o; o >>= 1) m = fmaxf(m, __shfl_xor_sync(0xffffffffu, m, o));
        float e[8], sum = 0.f;
        #pragma unroll
        for (int u = 0; u < 8; u++) { e[u] = fast_exp(p[lane + u*32] - m); sum += e[u]; }
        #pragma unroll
        for (int o = 16; o; o >>= 1) sum += __shfl_xor_sync(0xffffffffu, sum, o);
        float inv = 1.f / sum;
        __half* o = attnh + (((size_t)(b*NHEADS + h)*SEQ) + i0 + i)*SEQ;
        #pragma unroll
        for (int u = 0; u < 8; u++) o[lane + u*32] = __float2half_rn(e[u] * inv);
    }
}

// ---------------- launch ----------------
extern "C" void kernel_launch(void* const* d_in, const int* in_sizes, int n_in,
                              void* d_out, int out_size)
{
    const float* hidden  = (const float*)d_in[0];
    const float* bbox    = (const float*)d_in[1];
    const float* fc1_w   = (const float*)d_in[2];
    const float* fc1_b   = (const float*)d_in[3];
    const float* conv_w  = (const float*)d_in[4];
    const float* conv_b  = (const float*)d_in[5];
    const float* fc2_w   = (const float*)d_in[6];
    const float* fc2_b   = (const float*)d_in[7];
    const float* ln_ad_w = (const float*)d_in[8];
    const float* ln_ad_b = (const float*)d_in[9];
    const float* ln1_w   = (const float*)d_in[10];
    const float* q_w     = (const float*)d_in[11];
    const float* k_w     = (const float*)d_in[12];
    const float* v_w     = (const float*)d_in[13];
    const float* o_w     = (const float*)d_in[14];
    const float* rel_b   = (const float*)d_in[15];
    const float* ln2_w   = (const float*)d_in[16];
    const float* wi_w    = (const float*)d_in[17];
    const float* wo_w    = (const float*)d_in[18];
    float* out = (float*)d_out;

    __half *h16, *cv16, *hn16, *qkvh, *ctx16, *ff16, *attnh, *scoresh;
    __half *wtqkv, *wto, *wtwi, *wtwo, *wtf1, *wtf2;
    float *h1, *ad, *hs, *hs2;
    int* bkt;
    cudaGetSymbolAddress((void**)&h16,  g_h16);
    cudaGetSymbolAddress((void**)&h1,   g_h1);
    cudaGetSymbolAddress((void**)&cv16, g_cv16);
    cudaGetSymbolAddress((void**)&ad,   g_ad);
    cudaGetSymbolAddress((void**)&hs,   g_hs);
    cudaGetSymbolAddress((void**)&hn16, g_hn16);
    cudaGetSymbolAddress((void**)&qkvh, g_qkvh);
    cudaGetSymbolAddress((void**)&ctx16,g_ctx16);
    cudaGetSymbolAddress((void**)&hs2,  g_hs2);
    cudaGetSymbolAddress((void**)&scoresh, g_scoresh);
    cudaGetSymbolAddress((void**)&attnh,g_attnh);
    cudaGetSymbolAddress((void**)&ff16, g_ff16);
    cudaGetSymbolAddress((void**)&bkt,  g_bucket);
    cudaGetSymbolAddress((void**)&wtqkv,g_wt_qkv);
    cudaGetSymbolAddress((void**)&wto,  g_wt_o);
    cudaGetSymbolAddress((void**)&wtwi, g_wt_wi);
    cudaGetSymbolAddress((void**)&wtwo, g_wt_wo);
    cudaGetSymbolAddress((void**)&wtf1, g_wt_fc1);
    cudaGetSymbolAddress((void**)&wtf2, g_wt_fc2);

    cudaFuncSetAttribute(hgemm<1>, cudaFuncAttributeMaxDynamicSharedMemorySize, SMEMB);
    cudaFuncSetAttribute(hgemm<2>, cudaFuncAttributeMaxDynamicSharedMemorySize, SMEMB);
    cudaFuncSetAttribute(hgemm<3>, cudaFuncAttributeMaxDynamicSharedMemorySize, SMEMB);
    cudaFuncSetAttribute(hgemm<4>, cudaFuncAttributeMaxDynamicSharedMemorySize, SMEMB);
    cudaFuncSetAttribute(qk_gemm,  cudaFuncAttributeMaxDynamicSharedMemorySize, SMEMB);
    cudaFuncSetAttribute(av_gemm,  cudaFuncAttributeMaxDynamicSharedMemorySize, AVSMEM);
    cudaFuncSetAttribute(bbox_softmax_kernel, cudaFuncAttributeMaxDynamicSharedMemorySize, BB_SMEM);

    dim3 tb(32, 8);
    transpose_kernel<<<dim3(ADC/32, DMODEL/32), tb>>>(fc1_w, wtf1, DMODEL, ADC);       // 0
    round_kernel<<<ROWS*DMODEL/1024, 256>>>(hidden, h16);                              // 1
    hgemm<1><<<dim3(1, 32), 256, SMEMB>>>(h16, wtf1, h1, ADC, DMODEL, fc1_b);          // 2
    conv_kernel<<<ROWS, ADC>>>(h1, conv_w, conv_b, cv16);                              // 3
    transpose_kernel<<<dim3(DMODEL/32, ADC/32), tb>>>(fc2_w, wtf2, ADC, DMODEL);       // 4
    hgemm<1><<<dim3(6, 32), 256, SMEMB>>>(cv16, wtf2, ad, DMODEL, ADC, fc2_b);         // 5 (profiled)
    bucket_kernel<<<SEQ, SEQ>>>(bkt);                                                  // 6
    ln_res_rms_kernel<<<ROWS, 256>>>(ad, ln_ad_w, ln_ad_b, hidden, ln1_w, hs, hn16);   // 7
    transpose3_kernel<<<dim3(DMODEL/32, DMODEL/32, 3), tb>>>(q_w, k_w, v_w, wtqkv);    // 8
    hgemm<4><<<dim3(QKVN/128, 32), 256, SMEMB>>>(hn16, wtqkv, qkvh, QKVN, DMODEL, nullptr);
    qk_gemm<<<dim3(2, 2, BATCH*NHEADS), 256, SMEMB>>>(qkvh, scoresh);
    transpose_kernel<<<dim3(DMODEL/32, DMODEL/32), tb>>>(o_w, wto, DMODEL, DMODEL);
    bbox_softmax_kernel<<<dim3(BATCH, SEQ/4), 256, BB_SMEM>>>(qkvh, bbox, rel_b, bkt, scoresh, attnh);
    av_gemm<<<dim3(2, BATCH*NHEADS), 256, AVSMEM>>>(attnh, qkvh, ctx16);
    hgemm<3><<<dim3(6, 32), 256, SMEMB>>>(ctx16, wto, hs2, DMODEL, DMODEL, hs);
    rms_kernel<<<ROWS, 256>>>(hs2, ln2_w, hn16);
    transpose_kernel<<<dim3(DFF/32, DMODEL/32), tb>>>(wi_w, wtwi, DMODEL, DFF);
    hgemm<2><<<dim3(24, 32), 256, SMEMB>>>(hn16, wtwi, ff16, DFF, DMODEL, nullptr);
    transpose_kernel<<<dim3(DMODEL/32, DFF/32), tb>>>(wo_w, wtwo, DFF, DMODEL);
    hgemm<3><<<dim3(6, 32), 256, SMEMB>>>(ff16, wtwo, out, DMODEL, DFF, hs2);
}

// round 8
// speedup vs baseline: 6.3481x; 1.1305x over previous
#include <cuda_runtime.h>
#include <cuda_fp16.h>
#include <math.h>
#include <stdint.h>

// ---------------- problem constants ----------------
#define BATCH   16
#define NFRAMES 8
#define SEQ     256
#define DMODEL  768
#define NHEADS  12
#define DHEAD   64
#define DFF     3072
#define ADC     128
#define ROWS    (BATCH*SEQ) // 4096
#define QKVN    2304

// ---------------- scratch (device globals; no allocations) ----------------
__device__ __align__(16) __half g_h16 [ROWS*DMODEL];
__device__ __align__(16) float  g_h1  [ROWS*ADC];
__device__ __align__(16) __half g_cv16[ROWS*ADC];
__device__ __align__(16) float  g_ad  [ROWS*DMODEL];
__device__ __align__(16) float  g_hs  [ROWS*DMODEL];
__device__ __align__(16) __half g_hn16[ROWS*DMODEL];
__device__ __align__(16) __half g_qkvh[ROWS*QKVN];
__device__ __align__(16) __half g_ctx16[ROWS*DMODEL];
__device__ __align__(16) float  g_hs2 [ROWS*DMODEL];
__device__ __align__(16) __half g_scoresh[BATCH*NHEADS*SEQ*SEQ]; // raw QK^T half
__device__ __align__(16) __half g_attnh [BATCH*NHEADS*SEQ*SEQ];  // probs half
__device__ __align__(16) __half g_ff16[ROWS*DFF];
__device__ int g_bucket[SEQ*SEQ];
// fp16 transposed weights [N][K]
__device__ __align__(16) __half g_wt_qkv[QKVN*DMODEL];
__device__ __align__(16) __half g_wt_o  [DMODEL*DMODEL];
__device__ __align__(16) __half g_wt_wi [DFF*DMODEL];
__device__ __align__(16) __half g_wt_wo [DMODEL*DFF];
__device__ __align__(16) __half g_wt_fc1[ADC*DMODEL];
__device__ __align__(16) __half g_wt_fc2[DMODEL*ADC];

// ================= helpers =================
__device__ __forceinline__ uint32_t smem_u32(const void* p) {
    uint32_t a;
    asm("{ .reg .u64 t; cvta.to.shared.u64 t, %1; cvt.u32.u64 %0, t; }" : "=r"(a) : "l"(p));
    return a;
}
__device__ __forceinline__ void cp16(uint32_t s, const void* g) {
    asm volatile("cp.async.cg.shared.global [%0], [%1], 16;" :: "r"(s), "l"(g));
}
#define CP_COMMIT() asm volatile("cp.async.commit_group;" ::: "memory")
#define CP_WAIT1()  asm volatile("cp.async.wait_group 1;" ::: "memory")

__device__ __forceinline__ void ldsm4(uint32_t* r, uint32_t a) {
    asm volatile("ldmatrix.sync.aligned.m8n8.x4.shared.b16 {%0,%1,%2,%3}, [%4];"
                 : "=r"(r[0]), "=r"(r[1]), "=r"(r[2]), "=r"(r[3]) : "r"(a));
}
__device__ __forceinline__ void ldsm4t(uint32_t* r, uint32_t a) {
    asm volatile("ldmatrix.sync.aligned.m8n8.x4.trans.shared.b16 {%0,%1,%2,%3}, [%4];"
                 : "=r"(r[0]), "=r"(r[1]), "=r"(r[2]), "=r"(r[3]) : "r"(a));
}
__device__ __forceinline__ void mma_f16(float c[4], const uint32_t a[4],
                                        uint32_t b0, uint32_t b1) {
    asm volatile(
        "mma.sync.aligned.m16n8k16.row.col.f32.f16.f16.f32 "
        "{%0,%1,%2,%3}, {%4,%5,%6,%7}, {%8,%9}, {%0,%1,%2,%3};\n"
        : "+f"(c[0]), "+f"(c[1]), "+f"(c[2]), "+f"(c[3])
        : "r"(a[0]), "r"(a[1]), "r"(a[2]), "r"(a[3]), "r"(b0), "r"(b1));
}

// fast exp on FMA pipe
__device__ __forceinline__ float fast_exp(float x) {
    float t = x * 1.4426950408889634f;
    t = fmaxf(t, -126.0f);
    float r = t + 12582912.0f;
    float n = r - 12582912.0f;
    float f = t - n;
    float p = 1.33335581e-3f;
    p = fmaf(p, f, 9.61812910e-3f);
    p = fmaf(p, f, 5.55041087e-2f);
    p = fmaf(p, f, 2.40226507e-1f);
    p = fmaf(p, f, 6.93147182e-1f);
    p = fmaf(p, f, 1.0f);
    int ni = (int)n;
    return p * __int_as_float((ni + 127) << 23);
}

// ================= fp16 mma.sync GEMM =================
// tile 128x128x64, 3-stage cp.async, frag double-buffer, ONE barrier per k-tile.
// EPI: 1=+bias f32, 2=relu->half, 3=+residual f32, 4=plain->half
#define BK 64
#define ABYT (128*128)
#define STG  (2*ABYT)
#define SMEMB (3*STG)

__device__ __forceinline__ void stage_tile(uint32_t sa, const __half* Ag, int lda,
                                           const __half* Bg, int ldb, int tid) {
    #pragma unroll
    for (int p = 0; p < 4; p++) {
        int id = tid + p * 256;
        int row = id >> 3, c = id & 7;
        uint32_t off = (uint32_t)(row * 128 + c * 16);
        off ^= ((off >> 3) & 0x70);
        cp16(sa + off,        Ag + (size_t)row * lda + c * 8);
        cp16(sa + ABYT + off, Bg + (size_t)row * ldb + c * 8);
    }
}

template<int EPI>
__device__ __forceinline__ void hgemm_core(
    const __half* __restrict__ A, int lda,
    const __half* __restrict__ BT, int ldb,
    void* __restrict__ Cv, int ldc, int K, const float* __restrict__ aux)
{
    extern __shared__ __align__(16) char smc[];
    const uint32_t sbase = smem_u32(smc);
    const int tid  = threadIdx.x;
    const int lane = tid & 31;
    const int warp = tid >> 5;
    const int wm = (warp & 1) * 64;
    const int wn = (warp >> 1) * 32;
    const int g = lane >> 2;
    const int t = lane & 3;
    const size_t bm = (size_t)blockIdx.y * 128;
    const size_t bn = (size_t)blockIdx.x * 128;

    const __half* Ab = A  + bm * lda;
    const __half* Bb = BT + bn * ldb;
    const int ktiles = K >> 6;

    const int l16 = lane & 15;
    const uint32_t khb = (uint32_t)((lane >> 4) << 4);
    const uint32_t xr  = (uint32_t)((lane & 7) << 4);

    float acc[4][4][4];
    #pragma unroll
    for (int i = 0; i < 4; i++)
        #pragma unroll
        for (int j = 0; j < 4; j++)
            #pragma unroll
            for (int r = 0; r < 4; r++) acc[i][j][r] = 0.f;

    #pragma unroll
    for (int s = 0; s < 2; s++) {
        if (s < ktiles)
            stage_tile(sbase + s * STG, Ab + s * BK, lda, Bb + s * BK, ldb, tid);
        CP_COMMIT();
    }

    int cs = 0, is_ = 2;
    for (int kt = 0; kt < ktiles; kt++) {
        CP_WAIT1();
        __syncthreads();   // single barrier per k-tile: fences prior reads + new data

        if (kt + 2 < ktiles)
            stage_tile(sbase + is_ * STG, Ab + (kt+2) * BK, lda,
                       Bb + (kt+2) * BK, ldb, tid);
        CP_COMMIT();

        const uint32_t as = sbase + cs * STG;
        const uint32_t abase = as + (uint32_t)((wm + l16) * 128);
        const uint32_t bbase = as + ABYT + (uint32_t)((wn + l16) * 128);

        uint32_t af[2][4][4], bf[2][2][4];
        {
            const uint32_t kb = khb;
            #pragma unroll
            for (int im = 0; im < 4; im++)
                ldsm4(af[0][im], abase + im*2048 + (kb ^ xr));
            #pragma unroll
            for (int p = 0; p < 2; p++)
                ldsm4(bf[0][p], bbase + p*2048 + (kb ^ xr));
        }
        #pragma unroll
        for (int kk = 0; kk < 4; kk++) {
            const int cur = kk & 1, nxt = cur ^ 1;
            if (kk < 3) {
                const uint32_t kb = (uint32_t)((kk+1) * 32) + khb;
                #pragma unroll
                for (int im = 0; im < 4; im++)
                    ldsm4(af[nxt][im], abase + im*2048 + (kb ^ xr));
                #pragma unroll
                for (int p = 0; p < 2; p++)
                    ldsm4(bf[nxt][p], bbase + p*2048 + (kb ^ xr));
            }
            #pragma unroll
            for (int im = 0; im < 4; im++)
                #pragma unroll
                for (int j = 0; j < 4; j++)
                    mma_f16(acc[im][j], af[cur][im],
                            bf[cur][j>>1][j&1], bf[cur][j>>1][2+(j&1)]);
        }
        cs = (cs == 2) ? 0 : cs + 1;
        is_ = (is_ == 2) ? 0 : is_ + 1;
    }

    #pragma unroll
    for (int im = 0; im < 4; im++) {
        #pragma unroll
        for (int half = 0; half < 2; half++) {
            size_t row = bm + wm + im*16 + g + half*8;
            #pragma unroll
            for (int in = 0; in < 4; in++) {
                size_t col = bn + wn + in*8 + 2*t;
                float v0 = acc[im][in][half*2 + 0];
                float v1 = acc[im][in][half*2 + 1];
                if (EPI == 2) {
                    v0 = fmaxf(v0, 0.f); v1 = fmaxf(v1, 0.f);
                    *(__half2*)((__half*)Cv + row*ldc + col) = __floats2half2_rn(v0, v1);
                } else if (EPI == 4) {
                    *(__half2*)((__half*)Cv + row*ldc + col) = __floats2half2_rn(v0, v1);
                } else {
                    if (EPI == 1) { v0 += aux[col]; v1 += aux[col+1]; }
                    else if (EPI == 3) { v0 += aux[row*ldc+col]; v1 += aux[row*ldc+col+1]; }
                    *(float2*)((float*)Cv + row*ldc + col) = make_float2(v0, v1);
                }
            }
        }
    }
}

template<int EPI>
__global__ __launch_bounds__(256, 2) void hgemm(
    const __half* __restrict__ A, const __half* __restrict__ BT, void* __restrict__ C,
    int N, int K, const float* __restrict__ aux)
{
    hgemm_core<EPI>(A, K, BT, K, C, N, K, aux);
}

// batched QK^T: per (b,h) 256x256x64 -> half scores (unscaled)
__global__ __launch_bounds__(256, 2) void qk_gemm(
    const __half* __restrict__ qkvh, __half* __restrict__ scoresh)
{
    const int z = blockIdx.z;
    const int b = z / NHEADS;
    const __half* A = qkvh + (size_t)(b*SEQ) * QKVN + (z % NHEADS)*DHEAD;
    const __half* B = A + DMODEL;
    __half* C = scoresh + (size_t)z * SEQ * SEQ;
    hgemm_core<4>(A, QKVN, B, QKVN, C, SEQ, DHEAD, nullptr);
}

// ================= AV tensor GEMM: ctx = probs @ V =================
#define AV_A 16384
#define AVSTG 24576
#define AVSMEM (3*AVSTG)

__device__ __forceinline__ void av_stage(uint32_t sa, const __half* Ag,
                                         const __half* Vg, int tid) {
    #pragma unroll
    for (int p = 0; p < 4; p++) {
        int id = tid + p * 256;
        int row = id >> 3, c = id & 7;
        uint32_t off = (uint32_t)(row * 128 + c * 16);
        off ^= ((off >> 3) & 0x70);
        cp16(sa + off, Ag + (size_t)row * SEQ + c * 8);
    }
    #pragma unroll
    for (int p = 0; p < 2; p++) {
        int id = tid + p * 256;
        int row = id >> 3, c = id & 7;
        uint32_t off = (uint32_t)(row * 128 + c * 16);
        off ^= ((off >> 3) & 0x70);
        cp16(sa + AV_A + off, Vg + (size_t)row * QKVN + c * 8);
    }
}

__global__ __launch_bounds__(256, 2) void av_gemm(
    const __half* __restrict__ attnh, const __half* __restrict__ qkvh,
    __half* __restrict__ ctx)
{
    extern __shared__ __align__(16) char smc[];
    const uint32_t sbase = smem_u32(smc);
    const int tid  = threadIdx.x;
    const int lane = tid & 31;
    const int warp = tid >> 5;
    const int wm = (warp & 1) * 64;
    const int wn = (warp >> 1) * 16;
    const int z = blockIdx.y;
    const int b = z / NHEADS, h = z % NHEADS;
    const int bm = blockIdx.x * 128;

    const __half* Ab = attnh + ((size_t)z * SEQ + bm) * SEQ;
    const __half* Vb = qkvh + (size_t)(b*SEQ) * QKVN + 1536 + h*DHEAD;

    const int l16 = lane & 15;
    const uint32_t khb = (uint32_t)((lane >> 4) << 4);
    const uint32_t xr  = (uint32_t)((lane & 7) << 4);
    const int vrow = ((lane >> 3) & 1) * 8 + (lane & 7);
    const uint32_t vcolb = (uint32_t)(wn*2 + ((lane >> 4) << 4));

    float acc[4][2][4];
    #pragma unroll
    for (int i = 0; i < 4; i++)
        #pragma unroll
        for (int j = 0; j < 2; j++)
            #pragma unroll
            for (int r = 0; r < 4; r++) acc[i][j][r] = 0.f;

    #pragma unroll
    for (int s = 0; s < 2; s++) {
        av_stage(sbase + s * AVSTG, Ab + s * 64, Vb + (size_t)s * 64 * QKVN, tid);
        CP_COMMIT();
    }

    int cs = 0, is_ = 2;
    for (int kt = 0; kt < 4; kt++) {
        CP_WAIT1();
        __syncthreads();
        if (kt + 2 < 4)
            av_stage(sbase + is_ * AVSTG, Ab + (kt+2) * 64,
                     Vb + (size_t)(kt+2) * 64 * QKVN, tid);
        CP_COMMIT();

        const uint32_t as = sbase + cs * AVSTG;
        const uint32_t vs = as + AV_A;
        const uint32_t abase = as + (uint32_t)((wm + l16) * 128);
        #pragma unroll
        for (int kk = 0; kk < 4; kk++) {
            const uint32_t kb = (uint32_t)(kk * 32) + khb;
            uint32_t af[4][4], bv[4];
            #pragma unroll
            for (int im = 0; im < 4; im++)
                ldsm4(af[im], abase + im*2048 + (kb ^ xr));
            ldsm4t(bv, vs + (uint32_t)((kk*16 + vrow) * 128) + (vcolb ^ xr));
            #pragma unroll
            for (int im = 0; im < 4; im++) {
                mma_f16(acc[im][0], af[im], bv[0], bv[1]);
                mma_f16(acc[im][1], af[im], bv[2], bv[3]);
            }
        }
        cs = (cs == 2) ? 0 : cs + 1;
        is_ = (is_ == 2) ? 0 : is_ + 1;
    }

    const int g = lane >> 2, t = lane & 3;
    #pragma unroll
    for (int im = 0; im < 4; im++) {
        #pragma unroll
        for (int half = 0; half < 2; half++) {
            int row = bm + wm + im*16 + g + half*8;
            #pragma unroll
            for (int jn = 0; jn < 2; jn++) {
                int col = wn + jn*8 + 2*t;
                *(__half2*)(ctx + ((size_t)(b*SEQ + row))*DMODEL + h*DHEAD + col)
                    = __floats2half2_rn(acc[im][jn][half*2], acc[im][jn][half*2+1]);
            }
        }
    }
}

// ================= bbox einsum (tensor cores) + bias + softmax =================
// block = (b, 8 query rows). A = Q[h,d] padded 16x64 per i; B = bbox[j,d] 256x64.
#define BB2_A   16384            // 8 x 16 x 128B
#define BB2_B   32768            // 256 x 128B
#define BB2_SC  (12*256*4)       // 12KB fp32 scores
#define BB2_RB  1536             // rel bias copy
#define BB2_SMEM (BB2_A + BB2_B + BB2_SC + BB2_RB)

__global__ __launch_bounds__(256) void bbox_softmax2(
    const __half* __restrict__ qkvh, const float* __restrict__ bbox,
    const float* __restrict__ rel_bias, const int* __restrict__ bkt,
    const __half* __restrict__ scoresh, __half* __restrict__ attnh)
{
    const int b  = blockIdx.x;
    const int i0 = blockIdx.y * 8;
    extern __shared__ __align__(16) char smc[];
    const uint32_t sA = smem_u32(smc);
    const uint32_t sB = sA + BB2_A;
    float* sc  = (float*)(smc + BB2_A + BB2_B);
    float* rbs = sc + 12*256;
    const int tid = threadIdx.x, lane = tid & 31, warp = tid >> 5;

    for (int t = tid; t < 384; t += 256) rbs[t] = rel_bias[t];

    // build 8 A tiles: rows = heads (12 valid + 4 zero), 64 halfs, swizzled
    #pragma unroll
    for (int p = 0; p < 4; p++) {
        int id = tid + p*256;           // 0..1023
        int c  = id & 7;
        int hr = (id >> 3) & 15;
        int i  = id >> 7;
        uint4 v = make_uint4(0u, 0u, 0u, 0u);
        if (hr < 12)
            v = *(const uint4*)(qkvh + ((size_t)(b*SEQ) + i0 + i) * QKVN + hr*DHEAD + c*8);
        uint32_t off = (uint32_t)(i*2048 + hr*128 + c*16);
        off ^= ((off >> 3) & 0x70);
        *(uint4*)(smc + off) = v;
    }

    const int l16 = lane & 15;
    const uint32_t khb = (uint32_t)((lane >> 4) << 4);
    const uint32_t xr  = (uint32_t)((l16 & 7) << 4);
    const int r0 = warp*32 + l16, r1 = r0 + 16;
    const uint32_t brow0 = (uint32_t)(r0*128), brx0 = (uint32_t)((r0 & 7) << 4);
    const uint32_t brow1 = (uint32_t)(r1*128), brx1 = (uint32_t)((r1 & 7) << 4);
    const int g = lane >> 2, t4 = lane & 3;

    for (int i = 0; i < 8; i++) {
        __syncthreads();   // protects B tile + sc from previous iteration readers
        // stage bbox slice (i0+i): 256 rows x 64 fp32 -> half, swizzled
        const float* bb = bbox + (((size_t)(i0 + i) * SEQ) * BATCH + b) * DHEAD;
        #pragma unroll
        for (int p = 0; p < 8; p++) {
            int id = tid + p*256;       // 0..2047
            int row = id >> 3, c = id & 7;
            const float4* s4 = (const float4*)(bb + (size_t)row * (BATCH*DHEAD) + c*8);
            float4 v0 = s4[0], v1 = s4[1];
            uint32_t off = (uint32_t)(row*128 + c*16);
            off ^= ((off >> 3) & 0x70);
            __half2* d = (__half2*)(smc + BB2_A + off);
            d[0] = __floats2half2_rn(v0.x, v0.y);
            d[1] = __floats2half2_rn(v0.z, v0.w);
            d[2] = __floats2half2_rn(v1.x, v1.y);
            d[3] = __floats2half2_rn(v1.z, v1.w);
        }
        __syncthreads();

        // mma: [16x64] @ [64x256] -> 12 valid rows; warp owns 32 cols
        float acc[4][4];
        #pragma unroll
        for (int j = 0; j < 4; j++)
            #pragma unroll
            for (int r = 0; r < 4; r++) acc[j][r] = 0.f;

        const uint32_t abase = sA + (uint32_t)(i*2048) + (uint32_t)(l16*128);
        #pragma unroll
        for (int kk = 0; kk < 4; kk++) {
            const uint32_t kb = (uint32_t)(kk*32) + khb;
            uint32_t af[4], bf[2][4];
            ldsm4(af, abase + (kb ^ xr));
            ldsm4(bf[0], sB + brow0 + (kb ^ brx0));
            ldsm4(bf[1], sB + brow1 + (kb ^ brx1));
            #pragma unroll
            for (int j = 0; j < 4; j++)
                mma_f16(acc[j], af, bf[j>>1][j&1], bf[j>>1][2+(j&1)]);
        }
        #pragma unroll
        for (int j = 0; j < 4; j++) {
            int col = warp*32 + j*8 + 2*t4;
            sc[g*256 + col]     = acc[j][0];
            sc[g*256 + col + 1] = acc[j][1];
            if (g < 4) {
                sc[(g+8)*256 + col]     = acc[j][2];
                sc[(g+8)*256 + col + 1] = acc[j][3];
            }
        }
        __syncthreads();

        // softmax rows: warp w -> head w, and head w+8 if w<4
        const int* bkrow = bkt + (i0 + i) * SEQ;
        #pragma unroll
        for (int rr = 0; rr < 2; rr++) {
            int h = warp + rr*8;
            if (h >= 12) break;
            const __half* qrow = scoresh + ((size_t)(b*NHEADS + h)*SEQ + i0 + i) * SEQ;
            float e[8], m = -1e30f;
            #pragma unroll
            for (int u = 0; u < 8; u++) {
                int col = lane + u*32;
                float s = sc[h*256 + col] + __half2float(qrow[col])
                          + rbs[bkrow[col]*NHEADS + h];
                s *= 0.125f;
                e[u] = s;
                m = fmaxf(m, s);
            }
            #pragma unroll
            for (int o = 16; o; o >>= 1) m = fmaxf(m, __shfl_xor_sync(0xffffffffu, m, o));
            float sum = 0.f;
            #pragma unroll
            for (int u = 0; u < 8; u++) { e[u] = fast_exp(e[u] - m); sum += e[u]; }
            #pragma unroll
            for (int o = 16; o; o >>= 1) sum += __shfl_xor_sync(0xffffffffu, sum, o);
            float inv = 1.f / sum;
            __half* op = attnh + ((size_t)(b*NHEADS + h)*SEQ + i0 + i) * SEQ;
            #pragma unroll
            for (int u = 0; u < 8; u++) op[lane + u*32] = __float2half_rn(e[u] * inv);
        }
    }
}

// ---------------- weight transposes ----------------
__global__ __launch_bounds__(256) void transpose_kernel(
    const float* __restrict__ in, __half* __restrict__ out, int R, int C)
{
    __shared__ float tsm[32][33];
    int cx = blockIdx.x * 32, ry = blockIdx.y * 32;
    int x = threadIdx.x, y = threadIdx.y;
    #pragma unroll
    for (int i = 0; i < 32; i += 8)
        tsm[y + i][x] = in[(size_t)(ry + y + i) * C + cx + x];
    __syncthreads();
    #pragma unroll
    for (int i = 0; i < 32; i += 8)
        out[(size_t)(cx + y + i) * R + ry + x] = __float2half_rn(tsm[x][y + i]);
}

__global__ __launch_bounds__(256) void transpose3_kernel(
    const float* __restrict__ in0, const float* __restrict__ in1,
    const float* __restrict__ in2, __half* __restrict__ out)
{
    const float* in = (blockIdx.z == 0) ? in0 : ((blockIdx.z == 1) ? in1 : in2);
    __half* o = out + (size_t)blockIdx.z * DMODEL * DMODEL;
    __shared__ float tsm[32][33];
    int cx = blockIdx.x * 32, ry = blockIdx.y * 32;
    int x = threadIdx.x, y = threadIdx.y;
    #pragma unroll
    for (int i = 0; i < 32; i += 8)
        tsm[y + i][x] = in[(size_t)(ry + y + i) * DMODEL + cx + x];
    __syncthreads();
    #pragma unroll
    for (int i = 0; i < 32; i += 8)
        o[(size_t)(cx + y + i) * DMODEL + ry + x] = __float2half_rn(tsm[x][y + i]);
}

// ---------------- float -> half copy ----------------
__global__ __launch_bounds__(256) void round_kernel(
    const float* __restrict__ in, __half* __restrict__ out)
{
    size_t i = ((size_t)blockIdx.x * 256 + threadIdx.x) * 4;
    float4 v = *(const float4*)(in + i);
    __half2* o = (__half2*)(out + i);
    o[0] = __floats2half2_rn(v.x, v.y);
    o[1] = __floats2half2_rn(v.z, v.w);
}

// ---------------- relative-position bucket ----------------
__global__ void bucket_kernel(int* __restrict__ bkt) {
    int i = blockIdx.x, j = threadIdx.x;
    int rel = j - i;
    int base = (rel > 0) ? 16 : 0;
    int arel = rel < 0 ? -rel : rel;
    int v;
    if (arel < 8) {
        v = arel;
    } else {
        float t = logf((float)arel / 8.0f) / 2.772588722239781f * 8.0f;
        v = 8 + (int)t;
        if (v > 15) v = 15;
    }
    bkt[i*SEQ + j] = base + v;
}

// ---------------- depthwise 3x3 conv -> half ----------------
__global__ __launch_bounds__(128) void conv_kernel(
    const float* __restrict__ h1, const float* __restrict__ cw,
    const float* __restrict__ cb, __half* __restrict__ out)
{
    int p  = blockIdx.x;
    int l  = p & 255;
    int bn = p >> 8;
    int ni = bn & 7;
    int bi = bn >> 3;
    int c  = threadIdx.x;

    float acc = cb[c];
    #pragma unroll
    for (int dn = -1; dn <= 1; dn++) {
        int nn = ni + dn;
        if (nn < 0 || nn >= NFRAMES) continue;
        #pragma unroll
        for (int dl = -1; dl <= 1; dl++) {
            int ll = l + dl;
            if (ll < 0 || ll >= SEQ) continue;
            float x = h1[(size_t)(((bi*NFRAMES + nn)*SEQ) + ll) * ADC + c];
            acc = fmaf(x, cw[c*9 + (dn+1)*3 + (dl+1)], acc);
        }
    }
    out[(size_t)p * ADC + c] = __float2half_rn(acc);
}

// ---------------- norms ----------------
__device__ __forceinline__ float blk_sum(float v, volatile float* red) {
    int tid = threadIdx.x;
    #pragma unroll
    for (int o = 16; o; o >>= 1) v += __shfl_xor_sync(0xffffffffu, v, o);
    if ((tid & 31) == 0) red[tid >> 5] = v;
    __syncthreads();
    if (tid == 0) {
        float s = 0.f;
        #pragma unroll
        for (int w = 0; w < 8; w++) s += red[w];
        red[8] = s;
    }
    __syncthreads();
    return red[8];
}

__global__ __launch_bounds__(256) void ln_res_rms_kernel(
    const float* __restrict__ x, const float* __restrict__ w,
    const float* __restrict__ bvec, const float* __restrict__ res,
    const float* __restrict__ w1,
    float* __restrict__ hs, __half* __restrict__ hn16)
{
    __shared__ float red[9];
    size_t base = (size_t)blockIdx.x * DMODEL;
    int t = threadIdx.x;
    float v0 = x[base+t], v1 = x[base+t+256], v2 = x[base+t+512];
    float mu = blk_sum(v0+v1+v2, red) * (1.f/DMODEL);
    __syncthreads();
    float d0 = v0-mu, d1 = v1-mu, d2 = v2-mu;
    float var = blk_sum(d0*d0 + d1*d1 + d2*d2, red) * (1.f/DMODEL);
    float inv = rsqrtf(var + 1e-5f);
    float o0 = d0*inv*w[t]     + bvec[t]     + res[base+t];
    float o1 = d1*inv*w[t+256] + bvec[t+256] + res[base+t+256];
    float o2 = d2*inv*w[t+512] + bvec[t+512] + res[base+t+512];
    hs[base+t    ] = o0;
    hs[base+t+256] = o1;
    hs[base+t+512] = o2;
    __syncthreads();
    float ms = blk_sum(o0*o0 + o1*o1 + o2*o2, red) * (1.f/DMODEL);
    float rinv = rsqrtf(ms + 1e-6f);
    hn16[base+t    ] = __float2half_rn(w1[t]    *o0*rinv);
    hn16[base+t+256] = __float2half_rn(w1[t+256]*o1*rinv);
    hn16[base+t+512] = __float2half_rn(w1[t+512]*o2*rinv);
}

__global__ __launch_bounds__(256) void rms_kernel(
    const float* __restrict__ x, const float* __restrict__ w, __half* __restrict__ out)
{
    __shared__ float red[9];
    size_t base = (size_t)blockIdx.x * DMODEL;
    int t = threadIdx.x;
    float v0 = x[base+t], v1 = x[base+t+256], v2 = x[base+t+512];
    float ms = blk_sum(v0*v0 + v1*v1 + v2*v2, red) * (1.f/DMODEL);
    float inv = rsqrtf(ms + 1e-6f);
    out[base+t    ] = __float2half_rn(w[t]    *v0*inv);
    out[base+t+256] = __float2half_rn(w[t+256]*v1*inv);
    out[base+t+512] = __float2half_rn(w[t+512]*v2*inv);
}

// ---------------- launch ----------------
extern "C" void kernel_launch(void* const* d_in, const int* in_sizes, int n_in,
                              void* d_out, int out_size)
{
    const float* hidden  = (const float*)d_in[0];
    const float* bbox    = (const float*)d_in[1];
    const float* fc1_w   = (const float*)d_in[2];
    const float* fc1_b   = (const float*)d_in[3];
    const float* conv_w  = (const float*)d_in[4];
    const float* conv_b  = (const float*)d_in[5];
    const float* fc2_w   = (const float*)d_in[6];
    const float* fc2_b   = (const float*)d_in[7];
    const float* ln_ad_w = (const float*)d_in[8];
    const float* ln_ad_b = (const float*)d_in[9];
    const float* ln1_w   = (const float*)d_in[10];
    const float* q_w     = (const float*)d_in[11];
    const float* k_w     = (const float*)d_in[12];
    const float* v_w     = (const float*)d_in[13];
    const float* o_w     = (const float*)d_in[14];
    const float* rel_b   = (const float*)d_in[15];
    const float* ln2_w   = (const float*)d_in[16];
    const float* wi_w    = (const float*)d_in[17];
    const float* wo_w    = (const float*)d_in[18];
    float* out = (float*)d_out;

    __half *h16, *cv16, *hn16, *qkvh, *ctx16, *ff16, *attnh, *scoresh;
    __half *wtqkv, *wto, *wtwi, *wtwo, *wtf1, *wtf2;
    float *h1, *ad, *hs, *hs2;
    int* bkt;
    cudaGetSymbolAddress((void**)&h16,  g_h16);
    cudaGetSymbolAddress((void**)&h1,   g_h1);
    cudaGetSymbolAddress((void**)&cv16, g_cv16);
    cudaGetSymbolAddress((void**)&ad,   g_ad);
    cudaGetSymbolAddress((void**)&hs,   g_hs);
    cudaGetSymbolAddress((void**)&hn16, g_hn16);
    cudaGetSymbolAddress((void**)&qkvh, g_qkvh);
    cudaGetSymbolAddress((void**)&ctx16,g_ctx16);
    cudaGetSymbolAddress((void**)&hs2,  g_hs2);
    cudaGetSymbolAddress((void**)&scoresh, g_scoresh);
    cudaGetSymbolAddress((void**)&attnh,g_attnh);
    cudaGetSymbolAddress((void**)&ff16, g_ff16);
    cudaGetSymbolAddress((void**)&bkt,  g_bucket);
    cudaGetSymbolAddress((void**)&wtqkv,g_wt_qkv);
    cudaGetSymbolAddress((void**)&wto,  g_wt_o);
    cudaGetSymbolAddress((void**)&wtwi, g_wt_wi);
    cudaGetSymbolAddress((void**)&wtwo, g_wt_wo);
    cudaGetSymbolAddress((void**)&wtf1, g_wt_fc1);
    cudaGetSymbolAddress((void**)&wtf2, g_wt_fc2);

    cudaFuncSetAttribute(hgemm<1>, cudaFuncAttributeMaxDynamicSharedMemorySize, SMEMB);
    cudaFuncSetAttribute(hgemm<2>, cudaFuncAttributeMaxDynamicSharedMemorySize, SMEMB);
    cudaFuncSetAttribute(hgemm<3>, cudaFuncAttributeMaxDynamicSharedMemorySize, SMEMB);
    cudaFuncSetAttribute(hgemm<4>, cudaFuncAttributeMaxDynamicSharedMemorySize, SMEMB);
    cudaFuncSetAttribute(qk_gemm,  cudaFuncAttributeMaxDynamicSharedMemorySize, SMEMB);
    cudaFuncSetAttribute(av_gemm,  cudaFuncAttributeMaxDynamicSharedMemorySize, AVSMEM);
    cudaFuncSetAttribute(bbox_softmax2, cudaFuncAttributeMaxDynamicSharedMemorySize, BB2_SMEM);

    dim3 tb(32, 8);
    transpose_kernel<<<dim3(ADC/32, DMODEL/32), tb>>>(fc1_w, wtf1, DMODEL, ADC);       // 0
    round_kernel<<<ROWS*DMODEL/1024, 256>>>(hidden, h16);                              // 1
    hgemm<1><<<dim3(1, 32), 256, SMEMB>>>(h16, wtf1, h1, ADC, DMODEL, fc1_b);          // 2
    conv_kernel<<<ROWS, ADC>>>(h1, conv_w, conv_b, cv16);                              // 3
    transpose_kernel<<<dim3(DMODEL/32, ADC/32), tb>>>(fc2_w, wtf2, ADC, DMODEL);       // 4
    hgemm<1><<<dim3(6, 32), 256, SMEMB>>>(cv16, wtf2, ad, DMODEL, ADC, fc2_b);         // 5
    bucket_kernel<<<SEQ, SEQ>>>(bkt);                                                  // 6
    ln_res_rms_kernel<<<ROWS, 256>>>(ad, ln_ad_w, ln_ad_b, hidden, ln1_w, hs, hn16);   // 7
    transpose3_kernel<<<dim3(DMODEL/32, DMODEL/32, 3), tb>>>(q_w, k_w, v_w, wtqkv);    // 8
    hgemm<4><<<dim3(QKVN/128, 32), 256, SMEMB>>>(hn16, wtqkv, qkvh, QKVN, DMODEL, nullptr);
    qk_gemm<<<dim3(2, 2, BATCH*NHEADS), 256, SMEMB>>>(qkvh, scoresh);
    transpose_kernel<<<dim3(DMODEL/32, DMODEL/32), tb>>>(o_w, wto, DMODEL, DMODEL);
    bbox_softmax2<<<dim3(BATCH, SEQ/8), 256, BB2_SMEM>>>(qkvh, bbox, rel_b, bkt, scoresh, attnh);
    av_gemm<<<dim3(2, BATCH*NHEADS), 256, AVSMEM>>>(attnh, qkvh, ctx16);
    hgemm<3><<<dim3(6, 32), 256, SMEMB>>>(ctx16, wto, hs2, DMODEL, DMODEL, hs);
    rms_kernel<<<ROWS, 256>>>(hs2, ln2_w, hn16);
    transpose_kernel<<<dim3(DFF/32, DMODEL/32), tb>>>(wi_w, wtwi, DMODEL, DFF);
    hgemm<2><<<dim3(24, 32), 256, SMEMB>>>(hn16, wtwi, ff16, DFF, DMODEL, nullptr);
    transpose_kernel<<<dim3(DMODEL/32, DFF/32), tb>>>(wo_w, wtwo, DFF, DMODEL);
    hgemm<3><<<dim3(6, 32), 256, SMEMB>>>(ff16, wtwo, out, DMODEL, DFF, hs2);
}

// round 9
// speedup vs baseline: 6.4569x; 1.0171x over previous
#include <cuda_runtime.h>
#include <cuda_fp16.h>
#include <math.h>
#include <stdint.h>

// ---------------- problem constants ----------------
#define BATCH   16
#define NFRAMES 8
#define SEQ     256
#define DMODEL  768
#define NHEADS  12
#define DHEAD   64
#define DFF     3072
#define ADC     128
#define ROWS    (BATCH*SEQ) // 4096
#define QKVN    2304

// ---------------- scratch (device globals; no allocations) ----------------
__device__ __align__(16) __half g_h16 [ROWS*DMODEL];
__device__ __align__(16) __half g_h1h [ROWS*ADC];
__device__ __align__(16) __half g_cv16[ROWS*ADC];
__device__ __align__(16) float  g_ad  [ROWS*DMODEL];
__device__ __align__(16) float  g_hs  [ROWS*DMODEL];
__device__ __align__(16) __half g_hn16[ROWS*DMODEL];
__device__ __align__(16) __half g_qkvh[ROWS*QKVN];
__device__ __align__(16) __half g_ctx16[ROWS*DMODEL];
__device__ __align__(16) float  g_hs2 [ROWS*DMODEL];
__device__ __align__(16) __half g_scoresh[BATCH*NHEADS*SEQ*SEQ]; // raw QK^T half
__device__ __align__(16) __half g_attnh [BATCH*NHEADS*SEQ*SEQ];  // probs half
__device__ __align__(16) __half g_ff16[ROWS*DFF];
__device__ int g_bucket[SEQ*SEQ];
// fp16 transposed weights [N][K]
__device__ __align__(16) __half g_wt_qkv[QKVN*DMODEL];
__device__ __align__(16) __half g_wt_o  [DMODEL*DMODEL];
__device__ __align__(16) __half g_wt_wi [DFF*DMODEL];
__device__ __align__(16) __half g_wt_wo [DMODEL*DFF];
__device__ __align__(16) __half g_wt_fc1[ADC*DMODEL];
__device__ __align__(16) __half g_wt_fc2[DMODEL*ADC];

// ================= helpers =================
__device__ __forceinline__ uint32_t smem_u32(const void* p) {
    uint32_t a;
    asm("{ .reg .u64 t; cvta.to.shared.u64 t, %1; cvt.u32.u64 %0, t; }" : "=r"(a) : "l"(p));
    return a;
}
__device__ __forceinline__ void cp16(uint32_t s, const void* g) {
    asm volatile("cp.async.cg.shared.global [%0], [%1], 16;" :: "r"(s), "l"(g));
}
#define CP_COMMIT() asm volatile("cp.async.commit_group;" ::: "memory")
#define CP_WAIT1()  asm volatile("cp.async.wait_group 1;" ::: "memory")

__device__ __forceinline__ void ldsm4(uint32_t* r, uint32_t a) {
    asm volatile("ldmatrix.sync.aligned.m8n8.x4.shared.b16 {%0,%1,%2,%3}, [%4];"
                 : "=r"(r[0]), "=r"(r[1]), "=r"(r[2]), "=r"(r[3]) : "r"(a));
}
__device__ __forceinline__ void ldsm4t(uint32_t* r, uint32_t a) {
    asm volatile("ldmatrix.sync.aligned.m8n8.x4.trans.shared.b16 {%0,%1,%2,%3}, [%4];"
                 : "=r"(r[0]), "=r"(r[1]), "=r"(r[2]), "=r"(r[3]) : "r"(a));
}
__device__ __forceinline__ void mma_f16(float c[4], const uint32_t a[4],
                                        uint32_t b0, uint32_t b1) {
    asm volatile(
        "mma.sync.aligned.m16n8k16.row.col.f32.f16.f16.f32 "
        "{%0,%1,%2,%3}, {%4,%5,%6,%7}, {%8,%9}, {%0,%1,%2,%3};\n"
        : "+f"(c[0]), "+f"(c[1]), "+f"(c[2]), "+f"(c[3])
        : "r"(a[0]), "r"(a[1]), "r"(a[2]), "r"(a[3]), "r"(b0), "r"(b1));
}

// fast exp on FMA pipe
__device__ __forceinline__ float fast_exp(float x) {
    float t = x * 1.4426950408889634f;
    t = fmaxf(t, -126.0f);
    float r = t + 12582912.0f;
    float n = r - 12582912.0f;
    float f = t - n;
    float p = 1.33335581e-3f;
    p = fmaf(p, f, 9.61812910e-3f);
    p = fmaf(p, f, 5.55041087e-2f);
    p = fmaf(p, f, 2.40226507e-1f);
    p = fmaf(p, f, 6.93147182e-1f);
    p = fmaf(p, f, 1.0f);
    int ni = (int)n;
    return p * __int_as_float((ni + 127) << 23);
}

// ================= fp16 mma.sync GEMM =================
// tile 128x128x64, 3-stage cp.async, frag double-buffer, one barrier per k-tile.
// EPI: 1=+bias f32, 2=relu->half, 3=+residual f32, 4=plain->half, 5=+bias->half
#define BK 64
#define ABYT (128*128)
#define STG  (2*ABYT)
#define SMEMB (3*STG)

__device__ __forceinline__ void stage_tile(uint32_t sa, const __half* Ag, int lda,
                                           const __half* Bg, int ldb, int tid) {
    #pragma unroll
    for (int p = 0; p < 4; p++) {
        int id = tid + p * 256;
        int row = id >> 3, c = id & 7;
        uint32_t off = (uint32_t)(row * 128 + c * 16);
        off ^= ((off >> 3) & 0x70);
        cp16(sa + off,        Ag + (size_t)row * lda + c * 8);
        cp16(sa + ABYT + off, Bg + (size_t)row * ldb + c * 8);
    }
}

template<int EPI>
__device__ __forceinline__ void hgemm_core(
    const __half* __restrict__ A, int lda,
    const __half* __restrict__ BT, int ldb,
    void* __restrict__ Cv, int ldc, int K, const float* __restrict__ aux)
{
    extern __shared__ __align__(16) char smc[];
    const uint32_t sbase = smem_u32(smc);
    const int tid  = threadIdx.x;
    const int lane = tid & 31;
    const int warp = tid >> 5;
    const int wm = (warp & 1) * 64;
    const int wn = (warp >> 1) * 32;
    const int g = lane >> 2;
    const int t = lane & 3;
    const size_t bm = (size_t)blockIdx.y * 128;
    const size_t bn = (size_t)blockIdx.x * 128;

    const __half* Ab = A  + bm * lda;
    const __half* Bb = BT + bn * ldb;
    const int ktiles = K >> 6;

    const int l16 = lane & 15;
    const uint32_t khb = (uint32_t)((lane >> 4) << 4);
    const uint32_t xr  = (uint32_t)((lane & 7) << 4);

    float acc[4][4][4];
    #pragma unroll
    for (int i = 0; i < 4; i++)
        #pragma unroll
        for (int j = 0; j < 4; j++)
            #pragma unroll
            for (int r = 0; r < 4; r++) acc[i][j][r] = 0.f;

    #pragma unroll
    for (int s = 0; s < 2; s++) {
        if (s < ktiles)
            stage_tile(sbase + s * STG, Ab + s * BK, lda, Bb + s * BK, ldb, tid);
        CP_COMMIT();
    }

    int cs = 0, is_ = 2;
    for (int kt = 0; kt < ktiles; kt++) {
        CP_WAIT1();
        __syncthreads();

        if (kt + 2 < ktiles)
            stage_tile(sbase + is_ * STG, Ab + (kt+2) * BK, lda,
                       Bb + (kt+2) * BK, ldb, tid);
        CP_COMMIT();

        const uint32_t as = sbase + cs * STG;
        const uint32_t abase = as + (uint32_t)((wm + l16) * 128);
        const uint32_t bbase = as + ABYT + (uint32_t)((wn + l16) * 128);

        uint32_t af[2][4][4], bf[2][2][4];
        {
            const uint32_t kb = khb;
            #pragma unroll
            for (int im = 0; im < 4; im++)
                ldsm4(af[0][im], abase + im*2048 + (kb ^ xr));
            #pragma unroll
            for (int p = 0; p < 2; p++)
                ldsm4(bf[0][p], bbase + p*2048 + (kb ^ xr));
        }
        #pragma unroll
        for (int kk = 0; kk < 4; kk++) {
            const int cur = kk & 1, nxt = cur ^ 1;
            if (kk < 3) {
                const uint32_t kb = (uint32_t)((kk+1) * 32) + khb;
                #pragma unroll
                for (int im = 0; im < 4; im++)
                    ldsm4(af[nxt][im], abase + im*2048 + (kb ^ xr));
                #pragma unroll
                for (int p = 0; p < 2; p++)
                    ldsm4(bf[nxt][p], bbase + p*2048 + (kb ^ xr));
            }
            #pragma unroll
            for (int im = 0; im < 4; im++)
                #pragma unroll
                for (int j = 0; j < 4; j++)
                    mma_f16(acc[im][j], af[cur][im],
                            bf[cur][j>>1][j&1], bf[cur][j>>1][2+(j&1)]);
        }
        cs = (cs == 2) ? 0 : cs + 1;
        is_ = (is_ == 2) ? 0 : is_ + 1;
    }

    #pragma unroll
    for (int im = 0; im < 4; im++) {
        #pragma unroll
        for (int half = 0; half < 2; half++) {
            size_t row = bm + wm + im*16 + g + half*8;
            #pragma unroll
            for (int in = 0; in < 4; in++) {
                size_t col = bn + wn + in*8 + 2*t;
                float v0 = acc[im][in][half*2 + 0];
                float v1 = acc[im][in][half*2 + 1];
                if (EPI == 2) {
                    v0 = fmaxf(v0, 0.f); v1 = fmaxf(v1, 0.f);
                    *(__half2*)((__half*)Cv + row*ldc + col) = __floats2half2_rn(v0, v1);
                } else if (EPI == 4) {
                    *(__half2*)((__half*)Cv + row*ldc + col) = __floats2half2_rn(v0, v1);
                } else if (EPI == 5) {
                    v0 += aux[col]; v1 += aux[col+1];
                    *(__half2*)((__half*)Cv + row*ldc + col) = __floats2half2_rn(v0, v1);
                } else {
                    if (EPI == 1) { v0 += aux[col]; v1 += aux[col+1]; }
                    else if (EPI == 3) { v0 += aux[row*ldc+col]; v1 += aux[row*ldc+col+1]; }
                    *(float2*)((float*)Cv + row*ldc + col) = make_float2(v0, v1);
                }
            }
        }
    }
}

template<int EPI>
__global__ __launch_bounds__(256, 2) void hgemm(
    const __half* __restrict__ A, const __half* __restrict__ BT, void* __restrict__ C,
    int N, int K, const float* __restrict__ aux)
{
    hgemm_core<EPI>(A, K, BT, K, C, N, K, aux);
}

// batched QK^T: per (b,h) 256x256x64 -> half scores (unscaled)
__global__ __launch_bounds__(256, 2) void qk_gemm(
    const __half* __restrict__ qkvh, __half* __restrict__ scoresh)
{
    const int z = blockIdx.z;
    const int b = z / NHEADS;
    const __half* A = qkvh + (size_t)(b*SEQ) * QKVN + (z % NHEADS)*DHEAD;
    const __half* B = A + DMODEL;
    __half* C = scoresh + (size_t)z * SEQ * SEQ;
    hgemm_core<4>(A, QKVN, B, QKVN, C, SEQ, DHEAD, nullptr);
}

// ================= AV tensor GEMM: ctx = probs @ V =================
#define AV_A 16384
#define AVSTG 24576
#define AVSMEM (3*AVSTG)

__device__ __forceinline__ void av_stage(uint32_t sa, const __half* Ag,
                                         const __half* Vg, int tid) {
    #pragma unroll
    for (int p = 0; p < 4; p++) {
        int id = tid + p * 256;
        int row = id >> 3, c = id & 7;
        uint32_t off = (uint32_t)(row * 128 + c * 16);
        off ^= ((off >> 3) & 0x70);
        cp16(sa + off, Ag + (size_t)row * SEQ + c * 8);
    }
    #pragma unroll
    for (int p = 0; p < 2; p++) {
        int id = tid + p * 256;
        int row = id >> 3, c = id & 7;
        uint32_t off = (uint32_t)(row * 128 + c * 16);
        off ^= ((off >> 3) & 0x70);
        cp16(sa + AV_A + off, Vg + (size_t)row * QKVN + c * 8);
    }
}

__global__ __launch_bounds__(256, 2) void av_gemm(
    const __half* __restrict__ attnh, const __half* __restrict__ qkvh,
    __half* __restrict__ ctx)
{
    extern __shared__ __align__(16) char smc[];
    const uint32_t sbase = smem_u32(smc);
    const int tid  = threadIdx.x;
    const int lane = tid & 31;
    const int warp = tid >> 5;
    const int wm = (warp & 1) * 64;
    const int wn = (warp >> 1) * 16;
    const int z = blockIdx.y;
    const int b = z / NHEADS, h = z % NHEADS;
    const int bm = blockIdx.x * 128;

    const __half* Ab = attnh + ((size_t)z * SEQ + bm) * SEQ;
    const __half* Vb = qkvh + (size_t)(b*SEQ) * QKVN + 1536 + h*DHEAD;

    const int l16 = lane & 15;
    const uint32_t khb = (uint32_t)((lane >> 4) << 4);
    const uint32_t xr  = (uint32_t)((lane & 7) << 4);
    const int vrow = ((lane >> 3) & 1) * 8 + (lane & 7);
    const uint32_t vcolb = (uint32_t)(wn*2 + ((lane >> 4) << 4));

    float acc[4][2][4];
    #pragma unroll
    for (int i = 0; i < 4; i++)
        #pragma unroll
        for (int j = 0; j < 2; j++)
            #pragma unroll
            for (int r = 0; r < 4; r++) acc[i][j][r] = 0.f;

    #pragma unroll
    for (int s = 0; s < 2; s++) {
        av_stage(sbase + s * AVSTG, Ab + s * 64, Vb + (size_t)s * 64 * QKVN, tid);
        CP_COMMIT();
    }

    int cs = 0, is_ = 2;
    for (int kt = 0; kt < 4; kt++) {
        CP_WAIT1();
        __syncthreads();
        if (kt + 2 < 4)
            av_stage(sbase + is_ * AVSTG, Ab + (kt+2) * 64,
                     Vb + (size_t)(kt+2) * 64 * QKVN, tid);
        CP_COMMIT();

        const uint32_t as = sbase + cs * AVSTG;
        const uint32_t vs = as + AV_A;
        const uint32_t abase = as + (uint32_t)((wm + l16) * 128);
        #pragma unroll
        for (int kk = 0; kk < 4; kk++) {
            const uint32_t kb = (uint32_t)(kk * 32) + khb;
            uint32_t af[4][4], bv[4];
            #pragma unroll
            for (int im = 0; im < 4; im++)
                ldsm4(af[im], abase + im*2048 + (kb ^ xr));
            ldsm4t(bv, vs + (uint32_t)((kk*16 + vrow) * 128) + (vcolb ^ xr));
            #pragma unroll
            for (int im = 0; im < 4; im++) {
                mma_f16(acc[im][0], af[im], bv[0], bv[1]);
                mma_f16(acc[im][1], af[im], bv[2], bv[3]);
            }
        }
        cs = (cs == 2) ? 0 : cs + 1;
        is_ = (is_ == 2) ? 0 : is_ + 1;
    }

    const int g = lane >> 2, t = lane & 3;
    #pragma unroll
    for (int im = 0; im < 4; im++) {
        #pragma unroll
        for (int half = 0; half < 2; half++) {
            int row = bm + wm + im*16 + g + half*8;
            #pragma unroll
            for (int jn = 0; jn < 2; jn++) {
                int col = wn + jn*8 + 2*t;
                *(__half2*)(ctx + ((size_t)(b*SEQ + row))*DMODEL + h*DHEAD + col)
                    = __floats2half2_rn(acc[im][jn][half*2], acc[im][jn][half*2+1]);
            }
        }
    }
}

// ================= bbox einsum (tensor cores) + bias + softmax =================
#define BB2_A   16384
#define BB2_B   32768
#define BB2_SC  (12*256*4)
#define BB2_RB  1536
#define BB2_SMEM (BB2_A + BB2_B + BB2_SC + BB2_RB)

__global__ __launch_bounds__(256) void bbox_softmax2(
    const __half* __restrict__ qkvh, const float* __restrict__ bbox,
    const float* __restrict__ rel_bias, const int* __restrict__ bkt,
    const __half* __restrict__ scoresh, __half* __restrict__ attnh)
{
    const int b  = blockIdx.x;
    const int i0 = blockIdx.y * 8;
    extern __shared__ __align__(16) char smc[];
    const uint32_t sA = smem_u32(smc);
    const uint32_t sB = sA + BB2_A;
    float* sc  = (float*)(smc + BB2_A + BB2_B);
    float* rbs = sc + 12*256;
    const int tid = threadIdx.x, lane = tid & 31, warp = tid >> 5;

    for (int t = tid; t < 384; t += 256) rbs[t] = rel_bias[t];

    #pragma unroll
    for (int p = 0; p < 4; p++) {
        int id = tid + p*256;
        int c  = id & 7;
        int hr = (id >> 3) & 15;
        int i  = id >> 7;
        uint4 v = make_uint4(0u, 0u, 0u, 0u);
        if (hr < 12)
            v = *(const uint4*)(qkvh + ((size_t)(b*SEQ) + i0 + i) * QKVN + hr*DHEAD + c*8);
        uint32_t off = (uint32_t)(i*2048 + hr*128 + c*16);
        off ^= ((off >> 3) & 0x70);
        *(uint4*)(smc + off) = v;
    }

    const int l16 = lane & 15;
    const uint32_t khb = (uint32_t)((lane >> 4) << 4);
    const uint32_t xr  = (uint32_t)((l16 & 7) << 4);
    const int r0 = warp*32 + l16, r1 = r0 + 16;
    const uint32_t brow0 = (uint32_t)(r0*128), brx0 = (uint32_t)((r0 & 7) << 4);
    const uint32_t brow1 = (uint32_t)(r1*128), brx1 = (uint32_t)((r1 & 7) << 4);
    const int g = lane >> 2, t4 = lane & 3;

    for (int i = 0; i < 8; i++) {
        __syncthreads();
        const float* bb = bbox + (((size_t)(i0 + i) * SEQ) * BATCH + b) * DHEAD;
        #pragma unroll
        for (int p = 0; p < 8; p++) {
            int id = tid + p*256;
            int row = id >> 3, c = id & 7;
            const float4* s4 = (const float4*)(bb + (size_t)row * (BATCH*DHEAD) + c*8);
            float4 v0 = s4[0], v1 = s4[1];
            uint32_t off = (uint32_t)(row*128 + c*16);
            off ^= ((off >> 3) & 0x70);
            __half2* d = (__half2*)(smc + BB2_A + off);
            d[0] = __floats2half2_rn(v0.x, v0.y);
            d[1] = __floats2half2_rn(v0.z, v0.w);
            d[2] = __floats2half2_rn(v1.x, v1.y);
            d[3] = __floats2half2_rn(v1.z, v1.w);
        }
        __syncthreads();

        float acc[4][4];
        #pragma unroll
        for (int j = 0; j < 4; j++)
            #pragma unroll
            for (int r = 0; r < 4; r++) acc[j][r] = 0.f;

        const uint32_t abase = sA + (uint32_t)(i*2048) + (uint32_t)(l16*128);
        #pragma unroll
        for (int kk = 0; kk < 4; kk++) {
            const uint32_t kb = (uint32_t)(kk*32) + khb;
            uint32_t af[4], bf[2][4];
            ldsm4(af, abase + (kb ^ xr));
            ldsm4(bf[0], sB + brow0 + (kb ^ brx0));
            ldsm4(bf[1], sB + brow1 + (kb ^ brx1));
            #pragma unroll
            for (int j = 0; j < 4; j++)
                mma_f16(acc[j], af, bf[j>>1][j&1], bf[j>>1][2+(j&1)]);
        }
        #pragma unroll
        for (int j = 0; j < 4; j++) {
            int col = warp*32 + j*8 + 2*t4;
            sc[g*256 + col]     = acc[j][0];
            sc[g*256 + col + 1] = acc[j][1];
            if (g < 4) {
                sc[(g+8)*256 + col]     = acc[j][2];
                sc[(g+8)*256 + col + 1] = acc[j][3];
            }
        }
        __syncthreads();

        const int* bkrow = bkt + (i0 + i) * SEQ;
        #pragma unroll
        for (int rr = 0; rr < 2; rr++) {
            int h = warp + rr*8;
            if (h >= 12) break;
            const __half* qrow = scoresh + ((size_t)(b*NHEADS + h)*SEQ + i0 + i) * SEQ;
            float e[8], m = -1e30f;
            #pragma unroll
            for (int u = 0; u < 8; u++) {
                int col = lane + u*32;
                float s = sc[h*256 + col] + __half2float(qrow[col])
                          + rbs[bkrow[col]*NHEADS + h];
                s *= 0.125f;
                e[u] = s;
                m = fmaxf(m, s);
            }
            #pragma unroll
            for (int o = 16; o; o >>= 1) m = fmaxf(m, __shfl_xor_sync(0xffffffffu, m, o));
            float sum = 0.f;
            #pragma unroll
            for (int u = 0; u < 8; u++) { e[u] = fast_exp(e[u] - m); sum += e[u]; }
            #pragma unroll
            for (int o = 16; o; o >>= 1) sum += __shfl_xor_sync(0xffffffffu, sum, o);
            float inv = 1.f / sum;
            __half* op = attnh + ((size_t)(b*NHEADS + h)*SEQ + i0 + i) * SEQ;
            #pragma unroll
            for (int u = 0; u < 8; u++) op[lane + u*32] = __float2half_rn(e[u] * inv);
        }
    }
}

// ---------------- mega transpose: all weights in one launch ----------------
#define NJOBS 8
struct TJobs {
    const float* src[NJOBS];
    __half* dst[NJOBS];
    int R[NJOBS], C[NJOBS], start[NJOBS + 1];
};

__global__ __launch_bounds__(256) void mega_transpose(TJobs jobs)
{
    __shared__ float tsm[32][33];
    int bid = blockIdx.x;
    int j = 0;
    #pragma unroll
    for (int k = 1; k < NJOBS; k++)
        if (bid >= jobs.start[k]) j = k;
    int local = bid - jobs.start[j];
    int R = jobs.R[j], C = jobs.C[j];
    int tiles_x = C >> 5;
    int cx = (local % tiles_x) << 5;
    int ry = (local / tiles_x) << 5;
    const float* in = jobs.src[j];
    __half* out = jobs.dst[j];
    int x = threadIdx.x, y = threadIdx.y;
    #pragma unroll
    for (int i = 0; i < 32; i += 8)
        tsm[y + i][x] = in[(size_t)(ry + y + i) * C + cx + x];
    __syncthreads();
    #pragma unroll
    for (int i = 0; i < 32; i += 8)
        out[(size_t)(cx + y + i) * R + ry + x] = __float2half_rn(tsm[x][y + i]);
}

// ---------------- float -> half copy ----------------
__global__ __launch_bounds__(256) void round_kernel(
    const float* __restrict__ in, __half* __restrict__ out)
{
    size_t i = ((size_t)blockIdx.x * 256 + threadIdx.x) * 4;
    float4 v = *(const float4*)(in + i);
    __half2* o = (__half2*)(out + i);
    o[0] = __floats2half2_rn(v.x, v.y);
    o[1] = __floats2half2_rn(v.z, v.w);
}

// ---------------- relative-position bucket ----------------
__global__ void bucket_kernel(int* __restrict__ bkt) {
    int i = blockIdx.x, j = threadIdx.x;
    int rel = j - i;
    int base = (rel > 0) ? 16 : 0;
    int arel = rel < 0 ? -rel : rel;
    int v;
    if (arel < 8) {
        v = arel;
    } else {
        float t = logf((float)arel / 8.0f) / 2.772588722239781f * 8.0f;
        v = 8 + (int)t;
        if (v > 15) v = 15;
    }
    bkt[i*SEQ + j] = base + v;
}

// ---------------- depthwise 3x3 conv (half in) -> half ----------------
__global__ __launch_bounds__(128) void conv_kernel(
    const __half* __restrict__ h1, const float* __restrict__ cw,
    const float* __restrict__ cb, __half* __restrict__ out)
{
    int p  = blockIdx.x;
    int l  = p & 255;
    int bn = p >> 8;
    int ni = bn & 7;
    int bi = bn >> 3;
    int c  = threadIdx.x;

    float acc = cb[c];
    #pragma unroll
    for (int dn = -1; dn <= 1; dn++) {
        int nn = ni + dn;
        if (nn < 0 || nn >= NFRAMES) continue;
        #pragma unroll
        for (int dl = -1; dl <= 1; dl++) {
            int ll = l + dl;
            if (ll < 0 || ll >= SEQ) continue;
            float x = __half2float(h1[(size_t)(((bi*NFRAMES + nn)*SEQ) + ll) * ADC + c]);
            acc = fmaf(x, cw[c*9 + (dn+1)*3 + (dl+1)], acc);
        }
    }
    out[(size_t)p * ADC + c] = __float2half_rn(acc);
}

// ---------------- norms ----------------
__device__ __forceinline__ float blk_sum(float v, volatile float* red) {
    int tid = threadIdx.x;
    #pragma unroll
    for (int o = 16; o; o >>= 1) v += __shfl_xor_sync(0xffffffffu, v, o);
    if ((tid & 31) == 0) red[tid >> 5] = v;
    __syncthreads();
    if (tid == 0) {
        float s = 0.f;
        #pragma unroll
        for (int w = 0; w < 8; w++) s += red[w];
        red[8] = s;
    }
    __syncthreads();
    return red[8];
}

__global__ __launch_bounds__(256) void ln_res_rms_kernel(
    const float* __restrict__ x, const float* __restrict__ w,
    const float* __restrict__ bvec, const float* __restrict__ res,
    const float* __restrict__ w1,
    float* __restrict__ hs, __half* __restrict__ hn16)
{
    __shared__ float red[9];
    size_t base = (size_t)blockIdx.x * DMODEL;
    int t = threadIdx.x;
    float v0 = x[base+t], v1 = x[base+t+256], v2 = x[base+t+512];
    float mu = blk_sum(v0+v1+v2, red) * (1.f/DMODEL);
    __syncthreads();
    float d0 = v0-mu, d1 = v1-mu, d2 = v2-mu;
    float var = blk_sum(d0*d0 + d1*d1 + d2*d2, red) * (1.f/DMODEL);
    float inv = rsqrtf(var + 1e-5f);
    float o0 = d0*inv*w[t]     + bvec[t]     + res[base+t];
    float o1 = d1*inv*w[t+256] + bvec[t+256] + res[base+t+256];
    float o2 = d2*inv*w[t+512] + bvec[t+512] + res[base+t+512];
    hs[base+t    ] = o0;
    hs[base+t+256] = o1;
    hs[base+t+512] = o2;
    __syncthreads();
    float ms = blk_sum(o0*o0 + o1*o1 + o2*o2, red) * (1.f/DMODEL);
    float rinv = rsqrtf(ms + 1e-6f);
    hn16[base+t    ] = __float2half_rn(w1[t]    *o0*rinv);
    hn16[base+t+256] = __float2half_rn(w1[t+256]*o1*rinv);
    hn16[base+t+512] = __float2half_rn(w1[t+512]*o2*rinv);
}

__global__ __launch_bounds__(256) void rms_kernel(
    const float* __restrict__ x, const float* __restrict__ w, __half* __restrict__ out)
{
    __shared__ float red[9];
    size_t base = (size_t)blockIdx.x * DMODEL;
    int t = threadIdx.x;
    float v0 = x[base+t], v1 = x[base+t+256], v2 = x[base+t+512];
    float ms = blk_sum(v0*v0 + v1*v1 + v2*v2, red) * (1.f/DMODEL);
    float inv = rsqrtf(ms + 1e-6f);
    out[base+t    ] = __float2half_rn(w[t]    *v0*inv);
    out[base+t+256] = __float2half_rn(w[t+256]*v1*inv);
    out[base+t+512] = __float2half_rn(w[t+512]*v2*inv);
}

// ---------------- launch ----------------
extern "C" void kernel_launch(void* const* d_in, const int* in_sizes, int n_in,
                              void* d_out, int out_size)
{
    const float* hidden  = (const float*)d_in[0];
    const float* bbox    = (const float*)d_in[1];
    const float* fc1_w   = (const float*)d_in[2];
    const float* fc1_b   = (const float*)d_in[3];
    const float* conv_w  = (const float*)d_in[4];
    const float* conv_b  = (const float*)d_in[5];
    const float* fc2_w   = (const float*)d_in[6];
    const float* fc2_b   = (const float*)d_in[7];
    const float* ln_ad_w = (const float*)d_in[8];
    const float* ln_ad_b = (const float*)d_in[9];
    const float* ln1_w   = (const float*)d_in[10];
    const float* q_w     = (const float*)d_in[11];
    const float* k_w     = (const float*)d_in[12];
    const float* v_w     = (const float*)d_in[13];
    const float* o_w     = (const float*)d_in[14];
    const float* rel_b   = (const float*)d_in[15];
    const float* ln2_w   = (const float*)d_in[16];
    const float* wi_w    = (const float*)d_in[17];
    const float* wo_w    = (const float*)d_in[18];
    float* out = (float*)d_out;

    __half *h16, *h1h, *cv16, *hn16, *qkvh, *ctx16, *ff16, *attnh, *scoresh;
    __half *wtqkv, *wto, *wtwi, *wtwo, *wtf1, *wtf2;
    float *ad, *hs, *hs2;
    int* bkt;
    cudaGetSymbolAddress((void**)&h16,  g_h16);
    cudaGetSymbolAddress((void**)&h1h,  g_h1h);
    cudaGetSymbolAddress((void**)&cv16, g_cv16);
    cudaGetSymbolAddress((void**)&ad,   g_ad);
    cudaGetSymbolAddress((void**)&hs,   g_hs);
    cudaGetSymbolAddress((void**)&hn16, g_hn16);
    cudaGetSymbolAddress((void**)&qkvh, g_qkvh);
    cudaGetSymbolAddress((void**)&ctx16,g_ctx16);
    cudaGetSymbolAddress((void**)&hs2,  g_hs2);
    cudaGetSymbolAddress((void**)&scoresh, g_scoresh);
    cudaGetSymbolAddress((void**)&attnh,g_attnh);
    cudaGetSymbolAddress((void**)&ff16, g_ff16);
    cudaGetSymbolAddress((void**)&bkt,  g_bucket);
    cudaGetSymbolAddress((void**)&wtqkv,g_wt_qkv);
    cudaGetSymbolAddress((void**)&wto,  g_wt_o);
    cudaGetSymbolAddress((void**)&wtwi, g_wt_wi);
    cudaGetSymbolAddress((void**)&wtwo, g_wt_wo);
    cudaGetSymbolAddress((void**)&wtf1, g_wt_fc1);
    cudaGetSymbolAddress((void**)&wtf2, g_wt_fc2);

    cudaFuncSetAttribute(hgemm<1>, cudaFuncAttributeMaxDynamicSharedMemorySize, SMEMB);
    cudaFuncSetAttribute(hgemm<2>, cudaFuncAttributeMaxDynamicSharedMemorySize, SMEMB);
    cudaFuncSetAttribute(hgemm<3>, cudaFuncAttributeMaxDynamicSharedMemorySize, SMEMB);
    cudaFuncSetAttribute(hgemm<4>, cudaFuncAttributeMaxDynamicSharedMemorySize, SMEMB);
    cudaFuncSetAttribute(hgemm<5>, cudaFuncAttributeMaxDynamicSharedMemorySize, SMEMB);
    cudaFuncSetAttribute(qk_gemm,  cudaFuncAttributeMaxDynamicSharedMemorySize, SMEMB);
    cudaFuncSetAttribute(av_gemm,  cudaFuncAttributeMaxDynamicSharedMemorySize, AVSMEM);
    cudaFuncSetAttribute(bbox_softmax2, cudaFuncAttributeMaxDynamicSharedMemorySize, BB2_SMEM);

    // build job table: {src, dst, R, C}; tiles = (R/32)*(C/32)
    TJobs J;
    const float* srcs[NJOBS] = {fc1_w, fc2_w, q_w, k_w, v_w, o_w, wi_w, wo_w};
    __half* dsts[NJOBS] = {wtf1, wtf2, wtqkv, wtqkv + DMODEL*DMODEL,
                           wtqkv + 2*DMODEL*DMODEL, wto, wtwi, wtwo};
    int Rs[NJOBS] = {DMODEL, ADC, DMODEL, DMODEL, DMODEL, DMODEL, DMODEL, DFF};
    int Cs[NJOBS] = {ADC, DMODEL, DMODEL, DMODEL, DMODEL, DMODEL, DFF, DMODEL};
    int acc = 0;
    for (int j = 0; j < NJOBS; j++) {
        J.src[j] = srcs[j]; J.dst[j] = dsts[j];
        J.R[j] = Rs[j]; J.C[j] = Cs[j];
        J.start[j] = acc;
        acc += (Rs[j] >> 5) * (Cs[j] >> 5);
    }
    J.start[NJOBS] = acc;

    dim3 tb(32, 8);
    mega_transpose<<<acc, tb>>>(J);                                                   // 0
    round_kernel<<<ROWS*DMODEL/1024, 256>>>(hidden, h16);                             // 1
    bucket_kernel<<<SEQ, SEQ>>>(bkt);                                                 // 2
    hgemm<5><<<dim3(1, 32), 256, SMEMB>>>(h16, wtf1, h1h, ADC, DMODEL, fc1_b);        // 3
    conv_kernel<<<ROWS, ADC>>>(h1h, conv_w, conv_b, cv16);                            // 4
    hgemm<1><<<dim3(6, 32), 256, SMEMB>>>(cv16, wtf2, ad, DMODEL, ADC, fc2_b);        // 5
    ln_res_rms_kernel<<<ROWS, 256>>>(ad, ln_ad_w, ln_ad_b, hidden, ln1_w, hs, hn16);  // 6
    hgemm<4><<<dim3(QKVN/128, 32), 256, SMEMB>>>(hn16, wtqkv, qkvh, QKVN, DMODEL, nullptr);
    qk_gemm<<<dim3(2, 2, BATCH*NHEADS), 256, SMEMB>>>(qkvh, scoresh);
    bbox_softmax2<<<dim3(BATCH, SEQ/8), 256, BB2_SMEM>>>(qkvh, bbox, rel_b, bkt, scoresh, attnh);
    av_gemm<<<dim3(2, BATCH*NHEADS), 256, AVSMEM>>>(attnh, qkvh, ctx16);
    hgemm<3><<<dim3(6, 32), 256, SMEMB>>>(ctx16, wto, hs2, DMODEL, DMODEL, hs);
    rms_kernel<<<ROWS, 256>>>(hs2, ln2_w, hn16);
    hgemm<2><<<dim3(24, 32), 256, SMEMB>>>(hn16, wtwi, ff16, DFF, DMODEL, nullptr);
    hgemm<3><<<dim3(6, 32), 256, SMEMB>>>(ff16, wtwo, out, DMODEL, DFF, hs2);
}